// round 3
// baseline (speedup 1.0000x reference)
#include <cuda_runtime.h>
#include <math.h>

#define BNUM 32
#define NTOK 4096
#define FDIN 768
#define DD 256
#define NS 8
#define MROWS (BNUM * NTOK)   // 131072
#define ITERS 3

// ---------------- scratch (static __device__ — no allocation) ----------------
__device__ float g_mean[MROWS];
__device__ float g_rstd[MROWS];
__device__ float g_h1[(size_t)MROWS * FDIN];
__device__ float g_h2[(size_t)MROWS * DD];
__device__ float g_feats[(size_t)MROWS * DD];
__device__ float g_kv[(size_t)MROWS * 2 * DD];   // [row][512]: keys | vals
__device__ float g_w1p[FDIN * FDIN];             // g ∘ w1
__device__ float g_gB[FDIN];                     // g^T w1
__device__ float g_bBp[FDIN];                    // b^T w1 + b1
__device__ float g_wkvT[DD * 2 * DD];            // [256][512] = [wk^T | wv^T]
__device__ float g_wqT[DD * DD];
__device__ float g_wihT[DD * 3 * DD];
__device__ float g_whhT[DD * 3 * DD];
__device__ float g_slots[BNUM * NS * DD];
__device__ float g_q[BNUM * NS * DD];
__device__ float g_U[BNUM * NS * DD];
__device__ float g_rowsum[BNUM * NS];

// ---------------- small utility kernels ----------------
__global__ void transpose_kernel(const float* __restrict__ in,
                                 float* __restrict__ out, int R, int C) {
    int idx = blockIdx.x * 256 + threadIdx.x;
    if (idx < R * C) {
        int r = idx / C, c = idx % C;
        out[c * R + r] = in[idx];
    }
}

__global__ void wkv_kernel(const float* __restrict__ wk, const float* __restrict__ wv) {
    int i = blockIdx.x * 256 + threadIdx.x;   // over DD*DD
    int n = i / DD, d = i % DD;
    g_wkvT[d * 512 + n]       = wk[i];
    g_wkvT[d * 512 + 256 + n] = wv[i];
}

__global__ void prep_scale_kernel(const float* __restrict__ w1,
                                  const float* __restrict__ g) {
    int i = blockIdx.x * 256 + threadIdx.x;   // over FDIN*FDIN
    int k = i / FDIN;
    g_w1p[i] = g[k] * w1[i];
}

__global__ void prep_sums_kernel(const float* __restrict__ w1,
                                 const float* __restrict__ g,
                                 const float* __restrict__ b,
                                 const float* __restrict__ b1) {
    __shared__ float r1[8], r2[8];
    int n = blockIdx.x, t = threadIdx.x;
    float s1 = 0.f, s2 = 0.f;
    for (int k = t; k < FDIN; k += 256) {
        float w = w1[(size_t)k * FDIN + n];
        s1 += g[k] * w;
        s2 += b[k] * w;
    }
    #pragma unroll
    for (int o = 16; o; o >>= 1) {
        s1 += __shfl_xor_sync(0xffffffffu, s1, o);
        s2 += __shfl_xor_sync(0xffffffffu, s2, o);
    }
    int w = t >> 5, lane = t & 31;
    if (lane == 0) { r1[w] = s1; r2[w] = s2; }
    __syncthreads();
    if (t == 0) {
        float a = 0.f, c = 0.f;
        #pragma unroll
        for (int i = 0; i < 8; i++) { a += r1[i]; c += r2[i]; }
        g_gB[n] = a;
        g_bBp[n] = c + b1[n];
    }
}

__global__ void slots_init_kernel(const float* __restrict__ si) {
    int i = blockIdx.x * 256 + threadIdx.x;
    g_slots[i] = si[i & (NS * DD - 1)];
}

__global__ void zero_ur_kernel() {
    int i = blockIdx.x * 256 + threadIdx.x;
    g_U[i] = 0.f;
    if (i < BNUM * NS) g_rowsum[i] = 0.f;
}

__global__ void copy_out_kernel(float* __restrict__ out) {
    int i = blockIdx.x * 256 + threadIdx.x;
    out[i] = g_slots[i];
}

// ---------------- LN stats for inputs (warp per row of 768) ----------------
__global__ void ln_stats_kernel(const float* __restrict__ x) {
    int row = blockIdx.x * 8 + (threadIdx.x >> 5);
    int lane = threadIdx.x & 31;
    const float* p = x + (size_t)row * FDIN;
    float s = 0.f, ss = 0.f;
    #pragma unroll
    for (int j = lane; j < FDIN; j += 32) { float v = p[j]; s += v; ss += v * v; }
    #pragma unroll
    for (int o = 16; o; o >>= 1) {
        s  += __shfl_xor_sync(0xffffffffu, s, o);
        ss += __shfl_xor_sync(0xffffffffu, ss, o);
    }
    float m = s * (1.f / FDIN);
    float var = ss * (1.f / FDIN) - m * m;
    if (lane == 0) { g_mean[row] = m; g_rstd[row] = rsqrtf(var + 1e-5f); }
}

// ---------------- tf32 MMA helper ----------------
__device__ __forceinline__ void mma_tf32(float* c, const unsigned* a, const unsigned* b) {
    asm volatile(
        "mma.sync.aligned.m16n8k8.row.col.f32.tf32.tf32.f32 "
        "{%0,%1,%2,%3}, {%4,%5,%6,%7}, {%8,%9}, {%0,%1,%2,%3};"
        : "+f"(c[0]), "+f"(c[1]), "+f"(c[2]), "+f"(c[3])
        : "r"(a[0]), "r"(a[1]), "r"(a[2]), "r"(a[3]), "r"(b[0]), "r"(b[1]));
}

#define CP_ASYNC16(dst, src) \
    asm volatile("cp.async.cg.shared.global [%0], [%1], 16;\n" :: "r"(dst), "l"(src))
#define CP_COMMIT() asm volatile("cp.async.commit_group;\n" ::: "memory")
#define CP_WAIT2()  asm volatile("cp.async.wait_group 2;\n" ::: "memory")

// ---------------- TF32 GEMM: 128x128 block, BK=16, 4-stage cp.async ----------
// C[M,N] = A[M,K] @ B[K,N]; EPI1: C = relu(r*acc - m*r*gB[n] + bBp[n]) (LN fold)
static const int G_ASZ = 128 * 20;        // A stage: [128][16+4pad]
static const int G_BSZ = 16 * 136;        // B stage: [16][128+8pad]
static const int G_STRIDE = G_ASZ + G_BSZ; // 4736 floats
static const int G_STAGES = 4;
static const int G_SMEM_BYTES = G_STAGES * G_STRIDE * 4; // 75776

template<bool EPI1, bool BIAS, bool RELU>
__global__ void __launch_bounds__(256)
tf32_gemm_kernel(const float* __restrict__ A, const float* __restrict__ Bw,
                 const float* __restrict__ bias, float* __restrict__ C,
                 int M, int Nn, int K) {
    extern __shared__ float sm[];
    unsigned sm_u32 = (unsigned)__cvta_generic_to_shared(sm);

    int tid = threadIdx.x;
    int lane = tid & 31;
    int warp = tid >> 5;
    int grp = lane >> 2;       // 0..7
    int tig = lane & 3;        // 0..3
    int wm = (warp & 3) * 32;  // warp M base
    int wn = (warp >> 2) * 64; // warp N base

    int bm = blockIdx.y * 128;
    int bn = blockIdx.x * 128;

    // loaders
    int aRow = tid >> 1;             // 0..127
    int aK0 = (tid & 1) * 8;         // 0 or 8
    int bRow = tid >> 4;             // 0..15
    int bCol = (tid & 15) * 8;       // 0..120

    const float* Abase = A + (size_t)(bm + aRow) * K + aK0;
    const float* Bbase = Bw + (size_t)bRow * Nn + bn + bCol;
    unsigned aDst0 = sm_u32 + (aRow * 20 + aK0) * 4;
    unsigned bDst0 = sm_u32 + (G_ASZ + bRow * 136 + bCol) * 4;

    float acc[2][8][4];
    #pragma unroll
    for (int mt = 0; mt < 2; mt++)
        #pragma unroll
        for (int nt = 0; nt < 8; nt++)
            #pragma unroll
            for (int i = 0; i < 4; i++) acc[mt][nt][i] = 0.f;

    int nsteps = K / 16;

    // prologue: stages 0..2
    #pragma unroll
    for (int s = 0; s < 3; s++) {
        const float* asrc = Abase + s * 16;
        const float* bsrc = Bbase + (size_t)(s * 16) * Nn;
        unsigned ad = aDst0 + s * G_STRIDE * 4;
        unsigned bd = bDst0 + s * G_STRIDE * 4;
        CP_ASYNC16(ad, asrc);
        CP_ASYNC16(ad + 16, asrc + 4);
        CP_ASYNC16(bd, bsrc);
        CP_ASYNC16(bd + 16, bsrc + 4);
        CP_COMMIT();
    }

    for (int s = 0; s < nsteps; s++) {
        CP_WAIT2();
        __syncthreads();

        // issue stage s+3
        if (s + 3 < nsteps) {
            int buf = (s + 3) & 3;
            const float* asrc = Abase + (s + 3) * 16;
            const float* bsrc = Bbase + (size_t)((s + 3) * 16) * Nn;
            unsigned ad = aDst0 + buf * G_STRIDE * 4;
            unsigned bd = bDst0 + buf * G_STRIDE * 4;
            CP_ASYNC16(ad, asrc);
            CP_ASYNC16(ad + 16, asrc + 4);
            CP_ASYNC16(bd, bsrc);
            CP_ASYNC16(bd + 16, bsrc + 4);
        }
        CP_COMMIT();   // commit even when empty to keep group accounting uniform

        // compute stage s
        const unsigned* asu = (const unsigned*)(sm + (s & 3) * G_STRIDE);
        const unsigned* bsu = (const unsigned*)(sm + (s & 3) * G_STRIDE + G_ASZ);
        #pragma unroll
        for (int kc = 0; kc < 16; kc += 8) {
            unsigned afr[2][4], bfr[8][2];
            #pragma unroll
            for (int mt = 0; mt < 2; mt++) {
                int m0 = wm + mt * 16 + grp;
                afr[mt][0] = asu[m0 * 20 + kc + tig];
                afr[mt][1] = asu[(m0 + 8) * 20 + kc + tig];
                afr[mt][2] = asu[m0 * 20 + kc + 4 + tig];
                afr[mt][3] = asu[(m0 + 8) * 20 + kc + 4 + tig];
            }
            #pragma unroll
            for (int nt = 0; nt < 8; nt++) {
                int n0 = wn + nt * 8 + grp;
                bfr[nt][0] = bsu[(kc + tig) * 136 + n0];
                bfr[nt][1] = bsu[(kc + 4 + tig) * 136 + n0];
            }
            #pragma unroll
            for (int mt = 0; mt < 2; mt++)
                #pragma unroll
                for (int nt = 0; nt < 8; nt++)
                    mma_tf32(acc[mt][nt], afr[mt], bfr[nt]);
        }
        __syncthreads();
    }

    // epilogue
    float mm[2][2], rr[2][2];
    if (EPI1) {
        #pragma unroll
        for (int mt = 0; mt < 2; mt++) {
            int r0 = bm + wm + mt * 16 + grp;
            mm[mt][0] = g_mean[r0];      rr[mt][0] = g_rstd[r0];
            mm[mt][1] = g_mean[r0 + 8];  rr[mt][1] = g_rstd[r0 + 8];
        }
    }
    #pragma unroll
    for (int mt = 0; mt < 2; mt++) {
        int row = bm + wm + mt * 16 + grp;
        #pragma unroll
        for (int nt = 0; nt < 8; nt++) {
            int col = bn + wn + nt * 8 + tig * 2;
            float c0 = acc[mt][nt][0], c1 = acc[mt][nt][1];
            float c2 = acc[mt][nt][2], c3 = acc[mt][nt][3];
            if (EPI1) {
                float gb0 = g_gB[col], gb1 = g_gB[col + 1];
                float bb0 = g_bBp[col], bb1 = g_bBp[col + 1];
                c0 = c0 * rr[mt][0] - mm[mt][0] * rr[mt][0] * gb0 + bb0;
                c1 = c1 * rr[mt][0] - mm[mt][0] * rr[mt][0] * gb1 + bb1;
                c2 = c2 * rr[mt][1] - mm[mt][1] * rr[mt][1] * gb0 + bb0;
                c3 = c3 * rr[mt][1] - mm[mt][1] * rr[mt][1] * gb1 + bb1;
            }
            if (BIAS) {
                float b0 = bias[col], b1 = bias[col + 1];
                c0 += b0; c1 += b1; c2 += b0; c3 += b1;
            }
            if (RELU) {
                c0 = fmaxf(c0, 0.f); c1 = fmaxf(c1, 0.f);
                c2 = fmaxf(c2, 0.f); c3 = fmaxf(c3, 0.f);
            }
            *(float2*)(C + (size_t)row * Nn + col)       = make_float2(c0, c1);
            *(float2*)(C + (size_t)(row + 8) * Nn + col) = make_float2(c2, c3);
        }
    }
}

// ---------------- block mean/var helper for 256-wide rows --------------------
__device__ __forceinline__ float2 block_meanvar_256(float v, float* r1, float* r2) {
    float s = v, q = v * v;
    #pragma unroll
    for (int o = 16; o; o >>= 1) {
        s += __shfl_xor_sync(0xffffffffu, s, o);
        q += __shfl_xor_sync(0xffffffffu, q, o);
    }
    int w = threadIdx.x >> 5, lane = threadIdx.x & 31;
    if (lane == 0) { r1[w] = s; r2[w] = q; }
    __syncthreads();
    float sum = 0.f, sq = 0.f;
    #pragma unroll
    for (int i = 0; i < 8; i++) { sum += r1[i]; sq += r2[i]; }
    __syncthreads();
    float m = sum * (1.f / 256.f);
    float var = sq * (1.f / 256.f) - m * m;
    return make_float2(m, rsqrtf(var + 1e-5f));
}

__global__ void ln256_kernel(const float* __restrict__ x, float* __restrict__ y,
                             const float* __restrict__ g, const float* __restrict__ b) {
    __shared__ float r1[8], r2[8];
    size_t row = blockIdx.x;
    int tid = threadIdx.x;
    float v = x[row * DD + tid];
    float2 mv = block_meanvar_256(v, r1, r2);
    y[row * DD + tid] = (v - mv.x) * mv.y * g[tid] + b[tid];
}

// ---------------- q = LN(slots) @ wq^T ----------------
__global__ void qproj_kernel(const float* __restrict__ ng, const float* __restrict__ nb) {
    __shared__ float sln[DD];
    __shared__ float r1[8], r2[8];
    int row = blockIdx.x, tid = threadIdx.x;
    float v = g_slots[row * DD + tid];
    float2 mv = block_meanvar_256(v, r1, r2);
    sln[tid] = (v - mv.x) * mv.y * ng[tid] + nb[tid];
    __syncthreads();
    float acc = 0.f;
    #pragma unroll 8
    for (int d = 0; d < DD; d++) acc += sln[d] * g_wqT[d * DD + tid];
    g_q[row * DD + tid] = acc;
}

// ---------------- attention over interleaved g_kv ----------------
__global__ void __launch_bounds__(256)
attn_kernel() {
    int b = blockIdx.x, ch = blockIdx.y;
    int warp = threadIdx.x >> 5, lane = threadIdx.x & 31;
    __shared__ float qs[NS * DD];
    __shared__ float dots[8][NS];
    for (int i = threadIdx.x; i < NS * DD; i += 256) qs[i] = g_q[b * NS * DD + i];
    __syncthreads();
    float qreg[8];
    #pragma unroll
    for (int j = 0; j < 8; j++) qreg[j] = qs[warp * DD + lane + 32 * j];
    float uacc[8];
    #pragma unroll
    for (int j = 0; j < 8; j++) uacc[j] = 0.f;
    float rsum = 0.f;
    const float scale = 0.0625f;
    int t0 = ch * 512;
    const float* kvb = g_kv + ((size_t)b * NTOK + t0) * 512;

    for (int tt = 0; tt < 512; tt += 8) {
        #pragma unroll
        for (int u = 0; u < 8; u++) {
            const float* kp = kvb + (size_t)(tt + u) * 512;
            float d = 0.f;
            #pragma unroll
            for (int j = 0; j < 8; j++) d += qreg[j] * kp[lane + 32 * j];
            #pragma unroll
            for (int o = 16; o; o >>= 1) d += __shfl_xor_sync(0xffffffffu, d, o);
            if (lane == 0) dots[u][warp] = d * scale;
        }
        __syncthreads();
        #pragma unroll
        for (int u = 0; u < 8; u++) {
            float mx = -1e30f;
            #pragma unroll
            for (int s2 = 0; s2 < NS; s2++) mx = fmaxf(mx, dots[u][s2]);
            float sume = 0.f;
            #pragma unroll
            for (int s2 = 0; s2 < NS; s2++) sume += expf(dots[u][s2] - mx);
            float a = expf(dots[u][warp] - mx) / sume + 1e-8f;
            const float* vp = kvb + (size_t)(tt + u) * 512 + 256;
            #pragma unroll
            for (int j = 0; j < 8; j++) uacc[j] += a * vp[lane + 32 * j];
            rsum += a;
        }
        __syncthreads();
    }
    float* up = g_U + (b * NS + warp) * DD;
    #pragma unroll
    for (int j = 0; j < 8; j++) atomicAdd(&up[lane + 32 * j], uacc[j]);
    if (lane == 0) atomicAdd(&g_rowsum[b * NS + warp], rsum);
}

// ---------------- GRU cell + residual pre-LN MLP ----------------
__global__ void __launch_bounds__(256)
gru_mlp_kernel(const float* __restrict__ bih, const float* __restrict__ bhh,
               const float* __restrict__ mlng, const float* __restrict__ mlnb,
               const float* __restrict__ w1, const float* __restrict__ b1,
               const float* __restrict__ w2, const float* __restrict__ b2) {
    __shared__ float upd[DD], sp[DD], mmx[DD];
    __shared__ float hh[4 * DD];
    __shared__ float r1[8], r2[8];
    int row = blockIdx.x, tid = threadIdx.x;
    float rs = g_rowsum[row];
    upd[tid] = g_U[row * DD + tid] / rs;
    sp[tid]  = g_slots[row * DD + tid];
    __syncthreads();

    float ir = bih[tid], iz = bih[tid + 256], inn = bih[tid + 512];
    float hr = bhh[tid], hz = bhh[tid + 256], hn = bhh[tid + 512];
    #pragma unroll 4
    for (int d = 0; d < DD; d++) {
        float u = upd[d], s = sp[d];
        const float* wi = &g_wihT[d * 768];
        const float* wh = &g_whhT[d * 768];
        ir  += u * wi[tid];       hr  += s * wh[tid];
        iz  += u * wi[tid + 256]; hz  += s * wh[tid + 256];
        inn += u * wi[tid + 512]; hn  += s * wh[tid + 512];
    }
    float r = 1.f / (1.f + expf(-(ir + hr)));
    float z = 1.f / (1.f + expf(-(iz + hz)));
    float n = tanhf(inn + r * hn);
    float h = (1.f - z) * n + z * sp[tid];
    __syncthreads();

    float2 mv = block_meanvar_256(h, r1, r2);
    mmx[tid] = (h - mv.x) * mv.y * mlng[tid] + mlnb[tid];
    __syncthreads();

    #pragma unroll
    for (int jj = 0; jj < 4; jj++) {
        int o = tid + jj * 256;
        float a = b1[o];
        #pragma unroll 8
        for (int d = 0; d < DD; d++) a += mmx[d] * w1[d * 1024 + o];
        hh[o] = fmaxf(a, 0.f);
    }
    __syncthreads();
    float a2 = b2[tid];
    #pragma unroll 8
    for (int j = 0; j < 1024; j++) a2 += hh[j] * w2[j * 256 + tid];
    g_slots[row * DD + tid] = h + a2;
}

// ---------------- launch ----------------
extern "C" void kernel_launch(void* const* d_in, const int* in_sizes, int n_in,
                              void* d_out, int out_size) {
    const float* inputs   = (const float*)d_in[0];
    const float* slots_in = (const float*)d_in[1];
    const float* ln1g = (const float*)d_in[2];
    const float* ln1b = (const float*)d_in[3];
    const float* w1   = (const float*)d_in[4];
    const float* b1   = (const float*)d_in[5];
    const float* w2   = (const float*)d_in[6];
    const float* b2   = (const float*)d_in[7];
    const float* ln2g = (const float*)d_in[8];
    const float* ln2b = (const float*)d_in[9];
    const float* wq   = (const float*)d_in[10];
    const float* wk   = (const float*)d_in[11];
    const float* wv   = (const float*)d_in[12];
    const float* normg = (const float*)d_in[13];
    const float* normb = (const float*)d_in[14];
    const float* gwih = (const float*)d_in[15];
    const float* gwhh = (const float*)d_in[16];
    const float* gbih = (const float*)d_in[17];
    const float* gbhh = (const float*)d_in[18];
    const float* mlng = (const float*)d_in[19];
    const float* mlnb = (const float*)d_in[20];
    const float* mw1  = (const float*)d_in[21];
    const float* mb1  = (const float*)d_in[22];
    const float* mw2  = (const float*)d_in[23];
    const float* mb2  = (const float*)d_in[24];
    float* out = (float*)d_out;

    float *p_h1, *p_h2, *p_feats, *p_kv, *p_w1p, *p_wkvT, *p_wqT, *p_wihT, *p_whhT;
    cudaGetSymbolAddress((void**)&p_h1,   g_h1);
    cudaGetSymbolAddress((void**)&p_h2,   g_h2);
    cudaGetSymbolAddress((void**)&p_feats, g_feats);
    cudaGetSymbolAddress((void**)&p_kv,   g_kv);
    cudaGetSymbolAddress((void**)&p_w1p,  g_w1p);
    cudaGetSymbolAddress((void**)&p_wkvT, g_wkvT);
    cudaGetSymbolAddress((void**)&p_wqT,  g_wqT);
    cudaGetSymbolAddress((void**)&p_wihT, g_wihT);
    cudaGetSymbolAddress((void**)&p_whhT, g_whhT);

    cudaFuncSetAttribute(tf32_gemm_kernel<true, false, true>,
                         cudaFuncAttributeMaxDynamicSharedMemorySize, G_SMEM_BYTES);
    cudaFuncSetAttribute(tf32_gemm_kernel<false, true, false>,
                         cudaFuncAttributeMaxDynamicSharedMemorySize, G_SMEM_BYTES);
    cudaFuncSetAttribute(tf32_gemm_kernel<false, false, false>,
                         cudaFuncAttributeMaxDynamicSharedMemorySize, G_SMEM_BYTES);

    // launches 0..4 (puts GEMM1 at index 5 for ncu -s 5 -c 1)
    ln_stats_kernel<<<MROWS / 8, 256>>>(inputs);                              // 0
    prep_scale_kernel<<<FDIN * FDIN / 256, 256>>>(w1, ln1g);                  // 1
    prep_sums_kernel<<<FDIN, 256>>>(w1, ln1g, ln1b, b1);                      // 2
    transpose_kernel<<<(DD * DD + 255) / 256, 256>>>(wq, p_wqT, DD, DD);      // 3
    wkv_kernel<<<DD * DD / 256, 256>>>(wk, wv);                               // 4

    // GEMM1: h1 = relu(LN(inputs) @ w1 + b1)  [LN folded]                    // 5
    tf32_gemm_kernel<true, false, true>
        <<<dim3(FDIN / 128, MROWS / 128), 256, G_SMEM_BYTES>>>(
        inputs, p_w1p, nullptr, p_h1, MROWS, FDIN, FDIN);
    // GEMM2: h2 = h1 @ w2 + b2                                               // 6
    tf32_gemm_kernel<false, true, false>
        <<<dim3(DD / 128, MROWS / 128), 256, G_SMEM_BYTES>>>(
        p_h1, w2, b2, p_h2, MROWS, DD, FDIN);
    ln256_kernel<<<MROWS, 256>>>(p_h2, p_feats, ln2g, ln2b);                  // 7
    // KV: kv = feats @ [wk^T | wv^T]                                         // 8
    tf32_gemm_kernel<false, false, false>
        <<<dim3(2 * DD / 128, MROWS / 128), 256, G_SMEM_BYTES>>>(
        p_feats, p_wkvT, nullptr, p_kv, MROWS, 2 * DD, DD);

    transpose_kernel<<<(3 * DD * DD + 255) / 256, 256>>>(gwih, p_wihT, 3 * DD, DD);
    transpose_kernel<<<(3 * DD * DD + 255) / 256, 256>>>(gwhh, p_whhT, 3 * DD, DD);
    slots_init_kernel<<<BNUM * NS * DD / 256, 256>>>(slots_in);

    for (int t = 0; t < ITERS; t++) {
        qproj_kernel<<<BNUM * NS, 256>>>(normg, normb);
        zero_ur_kernel<<<BNUM * NS * DD / 256, 256>>>();
        attn_kernel<<<dim3(BNUM, 8), 256>>>();
        gru_mlp_kernel<<<BNUM * NS, 256>>>(gbih, gbhh, mlng, mlnb, mw1, mb1, mw2, mb2);
    }

    copy_out_kernel<<<BNUM * NS * DD / 256, 256>>>(out);
}

// round 6
// speedup vs baseline: 1.2189x; 1.2189x over previous
#include <cuda_runtime.h>
#include <cuda_fp16.h>
#include <math.h>
#include <stdint.h>

#define BNUM 32
#define NTOK 4096
#define FDIN 768
#define DD 256
#define NS 8
#define MROWS (BNUM * NTOK)   // 131072
#define ITERS 3

// ---------------- scratch (static __device__ — no allocation) ----------------
__device__ float  g_mean[MROWS];
__device__ float  g_rstd[MROWS];
__device__ __half g_inh[(size_t)MROWS * FDIN];    // inputs fp16
__device__ __half g_h1h[(size_t)MROWS * FDIN];    // h1 fp16
__device__ float  g_h2[(size_t)MROWS * DD];       // h2 fp32
__device__ __half g_featsh[(size_t)MROWS * DD];   // feats fp16
__device__ float  g_kv[(size_t)MROWS * 2 * DD];   // [row][512]: keys | vals fp32
__device__ __half g_w1h[FDIN * FDIN];             // [N=768][K=768] fp16, scaled by ln1g
__device__ float  g_gB[FDIN];                     // g^T w1
__device__ float  g_bBp[FDIN];                    // b^T w1 + b1
__device__ __half g_w2h[DD * FDIN];               // [N=256][K=768] fp16
__device__ __half g_wkvh[2 * DD * DD];            // [N=512][K=256] fp16 = wk | wv
__device__ float  g_wqT[DD * DD];
__device__ float  g_wihT[DD * 3 * DD];
__device__ float  g_whhT[DD * 3 * DD];
__device__ float  g_slots[BNUM * NS * DD];
__device__ float  g_q[BNUM * NS * DD];
__device__ float  g_U[BNUM * NS * DD];
__device__ float  g_rowsum[BNUM * NS];

// ================= asm helpers =================
#define CP_ASYNC16(dst, src) \
    asm volatile("cp.async.cg.shared.global [%0], [%1], 16;\n" :: "r"(dst), "l"(src))
#define CP_COMMIT() asm volatile("cp.async.commit_group;\n" ::: "memory")
#define CP_WAIT1()  asm volatile("cp.async.wait_group 1;\n" ::: "memory")

__device__ __forceinline__ void ldmx4(uint32_t& r0, uint32_t& r1, uint32_t& r2,
                                      uint32_t& r3, uint32_t addr) {
    asm volatile("ldmatrix.sync.aligned.m8n8.x4.shared.b16 {%0,%1,%2,%3}, [%4];"
                 : "=r"(r0), "=r"(r1), "=r"(r2), "=r"(r3) : "r"(addr));
}

__device__ __forceinline__ void mma_f16(float* c, const uint32_t* a, const uint32_t* b) {
    asm volatile(
        "mma.sync.aligned.m16n8k16.row.col.f32.f16.f16.f32 "
        "{%0,%1,%2,%3}, {%4,%5,%6,%7}, {%8,%9}, {%0,%1,%2,%3};"
        : "+f"(c[0]), "+f"(c[1]), "+f"(c[2]), "+f"(c[3])
        : "r"(a[0]), "r"(a[1]), "r"(a[2]), "r"(a[3]), "r"(b[0]), "r"(b[1]));
}

// ================= fp16 tensor-core GEMM =================
// C[M,N] = A[M,K] @ B^T, A fp16 [M][K], B fp16 [N][K] (both K-major).
// Block 128x128, 8 warps (4x2), warp tile 32x64, BK=32, 3-stage cp.async.
// EPI 0: fp32 store. EPI 1: LN-fold + relu, fp16 store. EPI 2: +bias, fp32 store.
#define HROW 40                      // padded halves per smem row
#define STG_HALVES (128 * HROW * 2)  // A block + B block per stage
#define STG_BYTES (STG_HALVES * 2)   // 20480
#define H_DSMEM (3 * STG_BYTES)      // 61440

template<int EPI>
__global__ void __launch_bounds__(256)
hgemm_kernel(const __half* __restrict__ A, const __half* __restrict__ Bw,
             int Nn, int K, float* __restrict__ Cf, __half* __restrict__ Ch,
             const float* __restrict__ bias) {
    extern __shared__ __align__(16) __half smh[];
    uint32_t smb;
    asm("{ .reg .u64 t; cvta.to.shared.u64 t, %1; cvt.u32.u64 %0, t; }"
        : "=r"(smb) : "l"(smh));

    int tid = threadIdx.x;
    int lane = tid & 31;
    int warp = tid >> 5;
    int grp = lane >> 2;       // 0..7
    int tig = lane & 3;        // 0..3
    int wm = (warp & 3) * 32;
    int wn = (warp >> 2) * 64;
    int bm = blockIdx.y * 128;
    int bn = blockIdx.x * 128;

    const __half* Abm = A + (size_t)bm * K;
    const __half* Bbn = Bw + (size_t)bn * K;

    float acc[2][8][4];
    #pragma unroll
    for (int mt = 0; mt < 2; mt++)
        #pragma unroll
        for (int nt = 0; nt < 8; nt++)
            #pragma unroll
            for (int i = 0; i < 4; i++) acc[mt][nt][i] = 0.f;

    int nit = K / 32;

    // prologue: stages 0,1
    #pragma unroll
    for (int s = 0; s < 2; s++) {
        uint32_t base = smb + s * STG_BYTES;
        #pragma unroll
        for (int j = 0; j < 2; j++) {
            int e = tid + j * 256;
            int r = e >> 2, c = e & 3;
            CP_ASYNC16(base + (r * HROW + c * 8) * 2, Abm + (size_t)r * K + s * 32 + c * 8);
            CP_ASYNC16(base + (128 * HROW + r * HROW + c * 8) * 2,
                       Bbn + (size_t)r * K + s * 32 + c * 8);
        }
        CP_COMMIT();
    }

    for (int it = 0; it < nit; it++) {
        CP_WAIT1();
        __syncthreads();

        uint32_t sa = smb + (it % 3) * STG_BYTES;
        uint32_t sb = sa + 128 * HROW * 2;

        // prefetch stage it+2
        if (it + 2 < nit) {
            uint32_t base = smb + ((it + 2) % 3) * STG_BYTES;
            #pragma unroll
            for (int j = 0; j < 2; j++) {
                int e = tid + j * 256;
                int r = e >> 2, c = e & 3;
                CP_ASYNC16(base + (r * HROW + c * 8) * 2,
                           Abm + (size_t)r * K + (it + 2) * 32 + c * 8);
                CP_ASYNC16(base + (128 * HROW + r * HROW + c * 8) * 2,
                           Bbn + (size_t)r * K + (it + 2) * 32 + c * 8);
            }
        }
        CP_COMMIT();

        #pragma unroll
        for (int kc = 0; kc < 2; kc++) {
            uint32_t afr[2][4], bfr[8][2];
            #pragma unroll
            for (int mt = 0; mt < 2; mt++) {
                uint32_t addr = sa + ((wm + mt * 16 + (lane & 15)) * HROW
                                      + kc * 16 + (lane >> 4) * 8) * 2;
                ldmx4(afr[mt][0], afr[mt][1], afr[mt][2], afr[mt][3], addr);
            }
            #pragma unroll
            for (int ng = 0; ng < 4; ng++) {
                uint32_t r0, r1, r2, r3;
                uint32_t addr = sb + ((wn + ng * 16 + (lane & 15)) * HROW
                                      + kc * 16 + (lane >> 4) * 8) * 2;
                ldmx4(r0, r1, r2, r3, addr);
                bfr[2 * ng][0] = r0; bfr[2 * ng + 1][0] = r1;
                bfr[2 * ng][1] = r2; bfr[2 * ng + 1][1] = r3;
            }
            #pragma unroll
            for (int mt = 0; mt < 2; mt++)
                #pragma unroll
                for (int nt = 0; nt < 8; nt++)
                    mma_f16(acc[mt][nt], afr[mt], bfr[nt]);
        }
        __syncthreads();
    }

    // ----------------- epilogue -----------------
    #pragma unroll
    for (int mt = 0; mt < 2; mt++) {
        int r0 = bm + wm + mt * 16 + grp;
        float mu0 = 0.f, rs0 = 0.f, mu1 = 0.f, rs1 = 0.f;
        if (EPI == 1) {
            mu0 = g_mean[r0]; rs0 = g_rstd[r0];
            mu1 = g_mean[r0 + 8]; rs1 = g_rstd[r0 + 8];
        }
        #pragma unroll
        for (int nt = 0; nt < 8; nt++) {
            int col = bn + wn + nt * 8 + tig * 2;
            float c0 = acc[mt][nt][0], c1 = acc[mt][nt][1];
            float c2 = acc[mt][nt][2], c3 = acc[mt][nt][3];
            if (EPI == 1) {
                float gb0 = __ldg(&g_gB[col]), gb1 = __ldg(&g_gB[col + 1]);
                float bb0 = __ldg(&g_bBp[col]), bb1 = __ldg(&g_bBp[col + 1]);
                c0 = fmaxf(c0 * rs0 - mu0 * rs0 * gb0 + bb0, 0.f);
                c1 = fmaxf(c1 * rs0 - mu0 * rs0 * gb1 + bb1, 0.f);
                c2 = fmaxf(c2 * rs1 - mu1 * rs1 * gb0 + bb0, 0.f);
                c3 = fmaxf(c3 * rs1 - mu1 * rs1 * gb1 + bb1, 0.f);
                *(__half2*)(Ch + (size_t)r0 * Nn + col) = __floats2half2_rn(c0, c1);
                *(__half2*)(Ch + (size_t)(r0 + 8) * Nn + col) = __floats2half2_rn(c2, c3);
            } else if (EPI == 2) {
                float b0 = __ldg(&bias[col]), b1 = __ldg(&bias[col + 1]);
                *(float2*)(Cf + (size_t)r0 * Nn + col)       = make_float2(c0 + b0, c1 + b1);
                *(float2*)(Cf + (size_t)(r0 + 8) * Nn + col) = make_float2(c2 + b0, c3 + b1);
            } else {
                *(float2*)(Cf + (size_t)r0 * Nn + col)       = make_float2(c0, c1);
                *(float2*)(Cf + (size_t)(r0 + 8) * Nn + col) = make_float2(c2, c3);
            }
        }
    }
}

// ================= prep / small kernels =================
__global__ void conv_f2h_kernel(const float* __restrict__ in, __half* __restrict__ out) {
    size_t i = ((size_t)blockIdx.x * 256 + threadIdx.x) * 4;
    float4 v = *(const float4*)(in + i);
    __half2 a = __floats2half2_rn(v.x, v.y);
    __half2 b = __floats2half2_rn(v.z, v.w);
    *(__half2*)(out + i) = a;
    *(__half2*)(out + i + 2) = b;
}

// out[c][r] = (half)(in[r][c] * scale[r]) — fp32 in, fp16 out, [R][C] -> [C][R]
__global__ void trans_h_kernel(const float* __restrict__ in, __half* __restrict__ out,
                               int R, int C, const float* __restrict__ scale) {
    __shared__ float t[32][33];
    int bx = blockIdx.x * 32, by = blockIdx.y * 32;
    int x = bx + threadIdx.x;
    #pragma unroll
    for (int j = 0; j < 32; j += 8) {
        int y = by + threadIdx.y + j;
        float s = scale ? scale[y] : 1.f;
        t[threadIdx.y + j][threadIdx.x] = in[(size_t)y * C + x] * s;
    }
    __syncthreads();
    int x2 = by + threadIdx.x;
    #pragma unroll
    for (int j = 0; j < 32; j += 8) {
        int y2 = bx + threadIdx.y + j;
        out[(size_t)y2 * R + x2] = __float2half(t[threadIdx.x][threadIdx.y + j]);
    }
}

// fp32 transpose (for wq/wih/whh used by fp32 small kernels)
__global__ void trans_f_kernel(const float* __restrict__ in, float* __restrict__ out,
                               int R, int C) {
    __shared__ float t[32][33];
    int bx = blockIdx.x * 32, by = blockIdx.y * 32;
    int x = bx + threadIdx.x;
    #pragma unroll
    for (int j = 0; j < 32; j += 8)
        t[threadIdx.y + j][threadIdx.x] = in[(size_t)(by + threadIdx.y + j) * C + x];
    __syncthreads();
    int x2 = by + threadIdx.x;
    #pragma unroll
    for (int j = 0; j < 32; j += 8)
        out[(size_t)(bx + threadIdx.y + j) * R + x2] = t[threadIdx.x][threadIdx.y + j];
}

__global__ void wkv_h_kernel(const float* __restrict__ wk, const float* __restrict__ wv) {
    int i = blockIdx.x * 256 + threadIdx.x;   // over DD*DD
    g_wkvh[i] = __float2half(wk[i]);
    g_wkvh[DD * DD + i] = __float2half(wv[i]);
}

__global__ void prep_sums_kernel(const float* __restrict__ w1,
                                 const float* __restrict__ g,
                                 const float* __restrict__ b,
                                 const float* __restrict__ b1) {
    __shared__ float r1[8], r2[8];
    int n = blockIdx.x, t = threadIdx.x;
    float s1 = 0.f, s2 = 0.f;
    for (int k = t; k < FDIN; k += 256) {
        float w = w1[(size_t)k * FDIN + n];
        s1 += g[k] * w;
        s2 += b[k] * w;
    }
    #pragma unroll
    for (int o = 16; o; o >>= 1) {
        s1 += __shfl_xor_sync(0xffffffffu, s1, o);
        s2 += __shfl_xor_sync(0xffffffffu, s2, o);
    }
    int w = t >> 5, lane = t & 31;
    if (lane == 0) { r1[w] = s1; r2[w] = s2; }
    __syncthreads();
    if (t == 0) {
        float a = 0.f, c = 0.f;
        #pragma unroll
        for (int i = 0; i < 8; i++) { a += r1[i]; c += r2[i]; }
        g_gB[n] = a;
        g_bBp[n] = c + b1[n];
    }
}

__global__ void ln_stats_kernel(const float* __restrict__ x) {
    int row = blockIdx.x * 8 + (threadIdx.x >> 5);
    int lane = threadIdx.x & 31;
    const float* p = x + (size_t)row * FDIN;
    float s = 0.f, ss = 0.f;
    #pragma unroll
    for (int j = lane; j < FDIN; j += 32) { float v = p[j]; s += v; ss += v * v; }
    #pragma unroll
    for (int o = 16; o; o >>= 1) {
        s  += __shfl_xor_sync(0xffffffffu, s, o);
        ss += __shfl_xor_sync(0xffffffffu, ss, o);
    }
    float m = s * (1.f / FDIN);
    float var = ss * (1.f / FDIN) - m * m;
    if (lane == 0) { g_mean[row] = m; g_rstd[row] = rsqrtf(var + 1e-5f); }
}

__global__ void slots_init_kernel(const float* __restrict__ si) {
    int i = blockIdx.x * 256 + threadIdx.x;
    g_slots[i] = si[i & (NS * DD - 1)];
}

__device__ __forceinline__ float2 block_meanvar_256(float v, float* r1, float* r2) {
    float s = v, q = v * v;
    #pragma unroll
    for (int o = 16; o; o >>= 1) {
        s += __shfl_xor_sync(0xffffffffu, s, o);
        q += __shfl_xor_sync(0xffffffffu, q, o);
    }
    int w = threadIdx.x >> 5, lane = threadIdx.x & 31;
    if (lane == 0) { r1[w] = s; r2[w] = q; }
    __syncthreads();
    float sum = 0.f, sq = 0.f;
    #pragma unroll
    for (int i = 0; i < 8; i++) { sum += r1[i]; sq += r2[i]; }
    __syncthreads();
    float m = sum * (1.f / 256.f);
    float var = sq * (1.f / 256.f) - m * m;
    return make_float2(m, rsqrtf(var + 1e-5f));
}

// feats = (half) LN(h2) over 256-wide rows
__global__ void ln256_kernel(const float* __restrict__ x, __half* __restrict__ y,
                             const float* __restrict__ g, const float* __restrict__ b) {
    __shared__ float r1[8], r2[8];
    size_t row = blockIdx.x;
    int tid = threadIdx.x;
    float v = x[row * DD + tid];
    float2 mv = block_meanvar_256(v, r1, r2);
    y[row * DD + tid] = __float2half((v - mv.x) * mv.y * g[tid] + b[tid]);
}

// q = LN(slots) @ wq^T ; zero U/rowsum for upcoming attention pass
__global__ void qproj_kernel(const float* __restrict__ ng, const float* __restrict__ nb) {
    __shared__ float sln[DD];
    __shared__ float r1[8], r2[8];
    int row = blockIdx.x, tid = threadIdx.x;
    float v = g_slots[row * DD + tid];
    float2 mv = block_meanvar_256(v, r1, r2);
    sln[tid] = (v - mv.x) * mv.y * ng[tid] + nb[tid];
    g_U[row * DD + tid] = 0.f;
    if (tid == 0) g_rowsum[row] = 0.f;
    __syncthreads();
    float acc = 0.f;
    #pragma unroll 8
    for (int d = 0; d < DD; d++) acc += sln[d] * g_wqT[d * DD + tid];
    g_q[row * DD + tid] = acc;
}

__global__ void __launch_bounds__(256)
attn_kernel() {
    int b = blockIdx.x, ch = blockIdx.y;
    int warp = threadIdx.x >> 5, lane = threadIdx.x & 31;
    __shared__ float qs[NS * DD];
    __shared__ float dots[8][NS];
    for (int i = threadIdx.x; i < NS * DD; i += 256) qs[i] = g_q[b * NS * DD + i];
    __syncthreads();
    float qreg[8];
    #pragma unroll
    for (int j = 0; j < 8; j++) qreg[j] = qs[warp * DD + lane + 32 * j];
    float uacc[8];
    #pragma unroll
    for (int j = 0; j < 8; j++) uacc[j] = 0.f;
    float rsum = 0.f;
    const float scale = 0.0625f;
    int t0 = ch * 512;
    const float* kvb = g_kv + ((size_t)b * NTOK + t0) * 512;

    for (int tt = 0; tt < 512; tt += 8) {
        #pragma unroll
        for (int u = 0; u < 8; u++) {
            const float* kp = kvb + (size_t)(tt + u) * 512;
            float d = 0.f;
            #pragma unroll
            for (int j = 0; j < 8; j++) d += qreg[j] * kp[lane + 32 * j];
            #pragma unroll
            for (int o = 16; o; o >>= 1) d += __shfl_xor_sync(0xffffffffu, d, o);
            if (lane == 0) dots[u][warp] = d * scale;
        }
        __syncthreads();
        #pragma unroll
        for (int u = 0; u < 8; u++) {
            float mx = -1e30f;
            #pragma unroll
            for (int s2 = 0; s2 < NS; s2++) mx = fmaxf(mx, dots[u][s2]);
            float sume = 0.f;
            #pragma unroll
            for (int s2 = 0; s2 < NS; s2++) sume += expf(dots[u][s2] - mx);
            float a = expf(dots[u][warp] - mx) / sume + 1e-8f;
            const float* vp = kvb + (size_t)(tt + u) * 512 + 256;
            #pragma unroll
            for (int j = 0; j < 8; j++) uacc[j] += a * vp[lane + 32 * j];
            rsum += a;
        }
        __syncthreads();
    }
    float* up = g_U + (b * NS + warp) * DD;
    #pragma unroll
    for (int j = 0; j < 8; j++) atomicAdd(&up[lane + 32 * j], uacc[j]);
    if (lane == 0) atomicAdd(&g_rowsum[b * NS + warp], rsum);
}

__global__ void __launch_bounds__(256)
gru_mlp_kernel(const float* __restrict__ bih, const float* __restrict__ bhh,
               const float* __restrict__ mlng, const float* __restrict__ mlnb,
               const float* __restrict__ w1, const float* __restrict__ b1,
               const float* __restrict__ w2, const float* __restrict__ b2,
               float* __restrict__ dst) {
    __shared__ float upd[DD], sp[DD], mmx[DD];
    __shared__ float hh[4 * DD];
    __shared__ float r1[8], r2[8];
    int row = blockIdx.x, tid = threadIdx.x;
    float rs = g_rowsum[row];
    upd[tid] = g_U[row * DD + tid] / rs;
    sp[tid]  = g_slots[row * DD + tid];
    __syncthreads();

    float ir = bih[tid], iz = bih[tid + 256], inn = bih[tid + 512];
    float hr = bhh[tid], hz = bhh[tid + 256], hn = bhh[tid + 512];
    #pragma unroll 4
    for (int d = 0; d < DD; d++) {
        float u = upd[d], s = sp[d];
        const float* wi = &g_wihT[d * 768];
        const float* wh = &g_whhT[d * 768];
        ir  += u * wi[tid];       hr  += s * wh[tid];
        iz  += u * wi[tid + 256]; hz  += s * wh[tid + 256];
        inn += u * wi[tid + 512]; hn  += s * wh[tid + 512];
    }
    float r = 1.f / (1.f + expf(-(ir + hr)));
    float z = 1.f / (1.f + expf(-(iz + hz)));
    float n = tanhf(inn + r * hn);
    float h = (1.f - z) * n + z * sp[tid];
    __syncthreads();

    float2 mv = block_meanvar_256(h, r1, r2);
    mmx[tid] = (h - mv.x) * mv.y * mlng[tid] + mlnb[tid];
    __syncthreads();

    #pragma unroll
    for (int jj = 0; jj < 4; jj++) {
        int o = tid + jj * 256;
        float a = b1[o];
        #pragma unroll 8
        for (int d = 0; d < DD; d++) a += mmx[d] * w1[d * 1024 + o];
        hh[o] = fmaxf(a, 0.f);
    }
    __syncthreads();
    float a2 = b2[tid];
    #pragma unroll 8
    for (int j = 0; j < 1024; j++) a2 += hh[j] * w2[j * 256 + tid];
    dst[row * DD + tid] = h + a2;
}

// ================= launch =================
extern "C" void kernel_launch(void* const* d_in, const int* in_sizes, int n_in,
                              void* d_out, int out_size) {
    const float* inputs   = (const float*)d_in[0];
    const float* slots_in = (const float*)d_in[1];
    const float* ln1g = (const float*)d_in[2];
    const float* ln1b = (const float*)d_in[3];
    const float* w1   = (const float*)d_in[4];
    const float* b1   = (const float*)d_in[5];
    const float* w2   = (const float*)d_in[6];
    const float* b2   = (const float*)d_in[7];
    const float* ln2g = (const float*)d_in[8];
    const float* ln2b = (const float*)d_in[9];
    const float* wq   = (const float*)d_in[10];
    const float* wk   = (const float*)d_in[11];
    const float* wv   = (const float*)d_in[12];
    const float* normg = (const float*)d_in[13];
    const float* normb = (const float*)d_in[14];
    const float* gwih = (const float*)d_in[15];
    const float* gwhh = (const float*)d_in[16];
    const float* gbih = (const float*)d_in[17];
    const float* gbhh = (const float*)d_in[18];
    const float* mlng = (const float*)d_in[19];
    const float* mlnb = (const float*)d_in[20];
    const float* mw1  = (const float*)d_in[21];
    const float* mb1  = (const float*)d_in[22];
    const float* mw2  = (const float*)d_in[23];
    const float* mb2  = (const float*)d_in[24];
    float* out = (float*)d_out;

    __half *p_inh, *p_h1h, *p_featsh, *p_w1h, *p_w2h, *p_wkvh;
    float *p_h2, *p_kv, *p_wqT, *p_wihT, *p_whhT, *p_slots;
    cudaGetSymbolAddress((void**)&p_inh,    g_inh);
    cudaGetSymbolAddress((void**)&p_h1h,    g_h1h);
    cudaGetSymbolAddress((void**)&p_featsh, g_featsh);
    cudaGetSymbolAddress((void**)&p_w1h,    g_w1h);
    cudaGetSymbolAddress((void**)&p_w2h,    g_w2h);
    cudaGetSymbolAddress((void**)&p_wkvh,   g_wkvh);
    cudaGetSymbolAddress((void**)&p_h2,     g_h2);
    cudaGetSymbolAddress((void**)&p_kv,     g_kv);
    cudaGetSymbolAddress((void**)&p_wqT,    g_wqT);
    cudaGetSymbolAddress((void**)&p_wihT,   g_wihT);
    cudaGetSymbolAddress((void**)&p_whhT,   g_whhT);
    cudaGetSymbolAddress((void**)&p_slots,  g_slots);

    cudaFuncSetAttribute(hgemm_kernel<0>, cudaFuncAttributeMaxDynamicSharedMemorySize, H_DSMEM);
    cudaFuncSetAttribute(hgemm_kernel<1>, cudaFuncAttributeMaxDynamicSharedMemorySize, H_DSMEM);
    cudaFuncSetAttribute(hgemm_kernel<2>, cudaFuncAttributeMaxDynamicSharedMemorySize, H_DSMEM);

    dim3 tb(32, 8);
    // 0: inputs -> fp16
    conv_f2h_kernel<<<(size_t)MROWS * FDIN / 1024, 256>>>(inputs, p_inh);
    // 1: w1 -> [N][K] fp16 scaled by ln1g
    trans_h_kernel<<<dim3(FDIN / 32, FDIN / 32), tb>>>(w1, p_w1h, FDIN, FDIN, ln1g);
    // 2: epilogue fold vectors
    prep_sums_kernel<<<FDIN, 256>>>(w1, ln1g, ln1b, b1);
    // 3: LN stats
    ln_stats_kernel<<<MROWS / 8, 256>>>(inputs);
    // 4: w2 -> [N][K] fp16
    trans_h_kernel<<<dim3(DD / 32, FDIN / 32), tb>>>(w2, p_w2h, FDIN, DD, nullptr);
    // 5: GEMM1  h1 = relu(LN(inputs) @ w1 + b1)  [LN folded] -> fp16
    hgemm_kernel<1><<<dim3(FDIN / 128, MROWS / 128), 256, H_DSMEM>>>(
        p_inh, p_w1h, FDIN, FDIN, nullptr, p_h1h, nullptr);
    // 6: GEMM2  h2 = h1 @ w2 + b2 -> fp32
    hgemm_kernel<2><<<dim3(DD / 128, MROWS / 128), 256, H_DSMEM>>>(
        p_h1h, p_w2h, DD, FDIN, p_h2, nullptr, b2);
    // 7: feats = LN(h2) -> fp16
    ln256_kernel<<<MROWS, 256>>>(p_h2, p_featsh, ln2g, ln2b);
    // 8: wk|wv -> fp16 [N=512][K=256]
    wkv_h_kernel<<<DD * DD / 256, 256>>>(wk, wv);
    // 9: KV GEMM: kv = feats @ [wk^T | wv^T] -> fp32
    hgemm_kernel<0><<<dim3(2 * DD / 128, MROWS / 128), 256, H_DSMEM>>>(
        p_featsh, p_wkvh, 2 * DD, DD, p_kv, nullptr, nullptr);

    trans_f_kernel<<<dim3(DD / 32, DD / 32), tb>>>(wq, p_wqT, DD, DD);
    trans_f_kernel<<<dim3(DD / 32, 3 * DD / 32), tb>>>(gwih, p_wihT, 3 * DD, DD);
    trans_f_kernel<<<dim3(DD / 32, 3 * DD / 32), tb>>>(gwhh, p_whhT, 3 * DD, DD);
    slots_init_kernel<<<BNUM * NS * DD / 256, 256>>>(slots_in);

    for (int t = 0; t < ITERS; t++) {
        qproj_kernel<<<BNUM * NS, 256>>>(normg, normb);
        attn_kernel<<<dim3(BNUM, 8), 256>>>();
        gru_mlp_kernel<<<BNUM * NS, 256>>>(gbih, gbhh, mlng, mlnb, mw1, mb1, mw2, mb2,
                                           (t == ITERS - 1) ? out : p_slots);
    }
}

// round 7
// speedup vs baseline: 1.7667x; 1.4495x over previous
#include <cuda_runtime.h>
#include <cuda_fp16.h>
#include <math.h>
#include <stdint.h>

#define BNUM 32
#define NTOK 4096
#define FDIN 768
#define DD 256
#define NS 8
#define MROWS (BNUM * NTOK)   // 131072
#define ITERS 3

// ---------------- scratch (static __device__ — no allocation) ----------------
__device__ float  g_mean[MROWS];
__device__ float  g_rstd[MROWS];
__device__ __half g_inh[(size_t)MROWS * FDIN];    // inputs fp16
__device__ __half g_h1h[(size_t)MROWS * FDIN];    // h1 fp16
__device__ float  g_h2[(size_t)MROWS * DD];       // h2 fp32
__device__ __half g_featsh[(size_t)MROWS * DD];   // feats fp16
__device__ __half g_kvh[(size_t)MROWS * 2 * DD];  // [row][512]: keys | vals fp16
__device__ __half g_w1h[FDIN * FDIN];             // [N=768][K=768] fp16, scaled by ln1g
__device__ float  g_gB[FDIN];                     // g^T w1
__device__ float  g_bBp[FDIN];                    // b^T w1 + b1
__device__ __half g_w2h[DD * FDIN];               // [N=256][K=768] fp16
__device__ __half g_wkvh[2 * DD * DD];            // [N=512][K=256] fp16 = wk | wv
__device__ float  g_wqT[DD * DD];
__device__ float  g_wihT[DD * 3 * DD];
__device__ float  g_whhT[DD * 3 * DD];
__device__ float  g_slots[BNUM * NS * DD];
__device__ float  g_q[BNUM * NS * DD];
__device__ float  g_U[BNUM * NS * DD];
__device__ float  g_rowsum[BNUM * NS];

// ================= asm helpers =================
#define CP_ASYNC16(dst, src) \
    asm volatile("cp.async.cg.shared.global [%0], [%1], 16;\n" :: "r"(dst), "l"(src))
#define CP_COMMIT() asm volatile("cp.async.commit_group;\n" ::: "memory")
#define CP_WAIT1()  asm volatile("cp.async.wait_group 1;\n" ::: "memory")

__device__ __forceinline__ void ldmx4(uint32_t& r0, uint32_t& r1, uint32_t& r2,
                                      uint32_t& r3, uint32_t addr) {
    asm volatile("ldmatrix.sync.aligned.m8n8.x4.shared.b16 {%0,%1,%2,%3}, [%4];"
                 : "=r"(r0), "=r"(r1), "=r"(r2), "=r"(r3) : "r"(addr));
}

__device__ __forceinline__ void mma_f16(float* c, const uint32_t* a, const uint32_t* b) {
    asm volatile(
        "mma.sync.aligned.m16n8k16.row.col.f32.f16.f16.f32 "
        "{%0,%1,%2,%3}, {%4,%5,%6,%7}, {%8,%9}, {%0,%1,%2,%3};"
        : "+f"(c[0]), "+f"(c[1]), "+f"(c[2]), "+f"(c[3])
        : "r"(a[0]), "r"(a[1]), "r"(a[2]), "r"(a[3]), "r"(b[0]), "r"(b[1]));
}

// ================= fp16 tensor-core GEMM =================
// C[M,N] = A[M,K] @ B^T, A fp16 [M][K], B fp16 [N][K] (both K-major).
// Block 128x128, 8 warps (4x2), warp tile 32x64, BK=32, 3-stage cp.async.
// EPI 0: fp32. EPI 1: LN-fold+relu fp16. EPI 2: +bias fp32. EPI 3: raw fp16.
#define HROW 40                      // padded halves per smem row
#define STG_HALVES (128 * HROW * 2)  // A block + B block per stage
#define STG_BYTES (STG_HALVES * 2)   // 20480
#define H_DSMEM (3 * STG_BYTES)      // 61440

template<int EPI>
__global__ void __launch_bounds__(256)
hgemm_kernel(const __half* __restrict__ A, const __half* __restrict__ Bw,
             int Nn, int K, float* __restrict__ Cf, __half* __restrict__ Ch,
             const float* __restrict__ bias) {
    extern __shared__ __align__(16) __half smh[];
    uint32_t smb;
    asm("{ .reg .u64 t; cvta.to.shared.u64 t, %1; cvt.u32.u64 %0, t; }"
        : "=r"(smb) : "l"(smh));

    int tid = threadIdx.x;
    int lane = tid & 31;
    int warp = tid >> 5;
    int grp = lane >> 2;       // 0..7
    int tig = lane & 3;        // 0..3
    int wm = (warp & 3) * 32;
    int wn = (warp >> 2) * 64;
    int bm = blockIdx.y * 128;
    int bn = blockIdx.x * 128;

    const __half* Abm = A + (size_t)bm * K;
    const __half* Bbn = Bw + (size_t)bn * K;

    float acc[2][8][4];
    #pragma unroll
    for (int mt = 0; mt < 2; mt++)
        #pragma unroll
        for (int nt = 0; nt < 8; nt++)
            #pragma unroll
            for (int i = 0; i < 4; i++) acc[mt][nt][i] = 0.f;

    int nit = K / 32;

    // prologue: stages 0,1
    #pragma unroll
    for (int s = 0; s < 2; s++) {
        uint32_t base = smb + s * STG_BYTES;
        #pragma unroll
        for (int j = 0; j < 2; j++) {
            int e = tid + j * 256;
            int r = e >> 2, c = e & 3;
            CP_ASYNC16(base + (r * HROW + c * 8) * 2, Abm + (size_t)r * K + s * 32 + c * 8);
            CP_ASYNC16(base + (128 * HROW + r * HROW + c * 8) * 2,
                       Bbn + (size_t)r * K + s * 32 + c * 8);
        }
        CP_COMMIT();
    }

    for (int it = 0; it < nit; it++) {
        CP_WAIT1();
        __syncthreads();   // data visibility + protects buffer (it+2)%3 from overwrite

        uint32_t sa = smb + (it % 3) * STG_BYTES;
        uint32_t sb = sa + 128 * HROW * 2;

        // prefetch stage it+2
        if (it + 2 < nit) {
            uint32_t base = smb + ((it + 2) % 3) * STG_BYTES;
            #pragma unroll
            for (int j = 0; j < 2; j++) {
                int e = tid + j * 256;
                int r = e >> 2, c = e & 3;
                CP_ASYNC16(base + (r * HROW + c * 8) * 2,
                           Abm + (size_t)r * K + (it + 2) * 32 + c * 8);
                CP_ASYNC16(base + (128 * HROW + r * HROW + c * 8) * 2,
                           Bbn + (size_t)r * K + (it + 2) * 32 + c * 8);
            }
        }
        CP_COMMIT();

        #pragma unroll
        for (int kc = 0; kc < 2; kc++) {
            uint32_t afr[2][4], bfr[8][2];
            #pragma unroll
            for (int mt = 0; mt < 2; mt++) {
                uint32_t addr = sa + ((wm + mt * 16 + (lane & 15)) * HROW
                                      + kc * 16 + (lane >> 4) * 8) * 2;
                ldmx4(afr[mt][0], afr[mt][1], afr[mt][2], afr[mt][3], addr);
            }
            #pragma unroll
            for (int ng = 0; ng < 4; ng++) {
                uint32_t r0, r1, r2, r3;
                uint32_t addr = sb + ((wn + ng * 16 + (lane & 15)) * HROW
                                      + kc * 16 + (lane >> 4) * 8) * 2;
                ldmx4(r0, r1, r2, r3, addr);
                bfr[2 * ng][0] = r0; bfr[2 * ng + 1][0] = r1;
                bfr[2 * ng][1] = r2; bfr[2 * ng + 1][1] = r3;
            }
            #pragma unroll
            for (int mt = 0; mt < 2; mt++)
                #pragma unroll
                for (int nt = 0; nt < 8; nt++)
                    mma_f16(acc[mt][nt], afr[mt], bfr[nt]);
        }
        // no bottom barrier needed: next iter's top barrier orders reads
        // before the only conflicting prefetch (stage (it+3)%3 == it%3)
    }

    // ----------------- epilogue -----------------
    #pragma unroll
    for (int mt = 0; mt < 2; mt++) {
        int r0 = bm + wm + mt * 16 + grp;
        float mu0 = 0.f, rs0 = 0.f, mu1 = 0.f, rs1 = 0.f;
        if (EPI == 1) {
            mu0 = g_mean[r0]; rs0 = g_rstd[r0];
            mu1 = g_mean[r0 + 8]; rs1 = g_rstd[r0 + 8];
        }
        #pragma unroll
        for (int nt = 0; nt < 8; nt++) {
            int col = bn + wn + nt * 8 + tig * 2;
            float c0 = acc[mt][nt][0], c1 = acc[mt][nt][1];
            float c2 = acc[mt][nt][2], c3 = acc[mt][nt][3];
            if (EPI == 1) {
                float gb0 = __ldg(&g_gB[col]), gb1 = __ldg(&g_gB[col + 1]);
                float bb0 = __ldg(&g_bBp[col]), bb1 = __ldg(&g_bBp[col + 1]);
                c0 = fmaxf(c0 * rs0 - mu0 * rs0 * gb0 + bb0, 0.f);
                c1 = fmaxf(c1 * rs0 - mu0 * rs0 * gb1 + bb1, 0.f);
                c2 = fmaxf(c2 * rs1 - mu1 * rs1 * gb0 + bb0, 0.f);
                c3 = fmaxf(c3 * rs1 - mu1 * rs1 * gb1 + bb1, 0.f);
                *(__half2*)(Ch + (size_t)r0 * Nn + col) = __floats2half2_rn(c0, c1);
                *(__half2*)(Ch + (size_t)(r0 + 8) * Nn + col) = __floats2half2_rn(c2, c3);
            } else if (EPI == 2) {
                float b0 = __ldg(&bias[col]), b1 = __ldg(&bias[col + 1]);
                *(float2*)(Cf + (size_t)r0 * Nn + col)       = make_float2(c0 + b0, c1 + b1);
                *(float2*)(Cf + (size_t)(r0 + 8) * Nn + col) = make_float2(c2 + b0, c3 + b1);
            } else if (EPI == 3) {
                *(__half2*)(Ch + (size_t)r0 * Nn + col)       = __floats2half2_rn(c0, c1);
                *(__half2*)(Ch + (size_t)(r0 + 8) * Nn + col) = __floats2half2_rn(c2, c3);
            } else {
                *(float2*)(Cf + (size_t)r0 * Nn + col)       = make_float2(c0, c1);
                *(float2*)(Cf + (size_t)(r0 + 8) * Nn + col) = make_float2(c2, c3);
            }
        }
    }
}

// ================= prep / small kernels =================
// Fused: LN stats for inputs AND fp32->fp16 conversion (single read pass).
__global__ void ln_stats_f2h_kernel(const float* __restrict__ x, __half* __restrict__ xh) {
    int row = blockIdx.x * 8 + (threadIdx.x >> 5);
    int lane = threadIdx.x & 31;
    const float* p = x + (size_t)row * FDIN;
    __half* ph = xh + (size_t)row * FDIN;
    float v[24];
    float s = 0.f, ss = 0.f;
    #pragma unroll
    for (int k = 0; k < 24; k++) {
        v[k] = p[lane + 32 * k];
        s += v[k];
        ss += v[k] * v[k];
    }
    #pragma unroll
    for (int k = 0; k < 24; k++) ph[lane + 32 * k] = __float2half(v[k]);
    #pragma unroll
    for (int o = 16; o; o >>= 1) {
        s  += __shfl_xor_sync(0xffffffffu, s, o);
        ss += __shfl_xor_sync(0xffffffffu, ss, o);
    }
    float m = s * (1.f / FDIN);
    float var = ss * (1.f / FDIN) - m * m;
    if (lane == 0) { g_mean[row] = m; g_rstd[row] = rsqrtf(var + 1e-5f); }
}

// out[c][r] = (half)(in[r][c] * scale[r]) — fp32 in, fp16 out, [R][C] -> [C][R]
__global__ void trans_h_kernel(const float* __restrict__ in, __half* __restrict__ out,
                               int R, int C, const float* __restrict__ scale) {
    __shared__ float t[32][33];
    int bx = blockIdx.x * 32, by = blockIdx.y * 32;
    int x = bx + threadIdx.x;
    #pragma unroll
    for (int j = 0; j < 32; j += 8) {
        int y = by + threadIdx.y + j;
        float s = scale ? scale[y] : 1.f;
        t[threadIdx.y + j][threadIdx.x] = in[(size_t)y * C + x] * s;
    }
    __syncthreads();
    int x2 = by + threadIdx.x;
    #pragma unroll
    for (int j = 0; j < 32; j += 8) {
        int y2 = bx + threadIdx.y + j;
        out[(size_t)y2 * R + x2] = __float2half(t[threadIdx.x][threadIdx.y + j]);
    }
}

__global__ void trans_f_kernel(const float* __restrict__ in, float* __restrict__ out,
                               int R, int C) {
    __shared__ float t[32][33];
    int bx = blockIdx.x * 32, by = blockIdx.y * 32;
    int x = bx + threadIdx.x;
    #pragma unroll
    for (int j = 0; j < 32; j += 8)
        t[threadIdx.y + j][threadIdx.x] = in[(size_t)(by + threadIdx.y + j) * C + x];
    __syncthreads();
    int x2 = by + threadIdx.x;
    #pragma unroll
    for (int j = 0; j < 32; j += 8)
        out[(size_t)(bx + threadIdx.y + j) * R + x2] = t[threadIdx.x][threadIdx.y + j];
}

__global__ void wkv_h_kernel(const float* __restrict__ wk, const float* __restrict__ wv) {
    int i = blockIdx.x * 256 + threadIdx.x;   // over DD*DD
    g_wkvh[i] = __float2half(wk[i]);
    g_wkvh[DD * DD + i] = __float2half(wv[i]);
}

__global__ void prep_sums_kernel(const float* __restrict__ w1,
                                 const float* __restrict__ g,
                                 const float* __restrict__ b,
                                 const float* __restrict__ b1) {
    __shared__ float r1[8], r2[8];
    int n = blockIdx.x, t = threadIdx.x;
    float s1 = 0.f, s2 = 0.f;
    for (int k = t; k < FDIN; k += 256) {
        float w = w1[(size_t)k * FDIN + n];
        s1 += g[k] * w;
        s2 += b[k] * w;
    }
    #pragma unroll
    for (int o = 16; o; o >>= 1) {
        s1 += __shfl_xor_sync(0xffffffffu, s1, o);
        s2 += __shfl_xor_sync(0xffffffffu, s2, o);
    }
    int w = t >> 5, lane = t & 31;
    if (lane == 0) { r1[w] = s1; r2[w] = s2; }
    __syncthreads();
    if (t == 0) {
        float a = 0.f, c = 0.f;
        #pragma unroll
        for (int i = 0; i < 8; i++) { a += r1[i]; c += r2[i]; }
        g_gB[n] = a;
        g_bBp[n] = c + b1[n];
    }
}

__global__ void slots_init_kernel(const float* __restrict__ si) {
    int i = blockIdx.x * 256 + threadIdx.x;
    g_slots[i] = si[i & (NS * DD - 1)];
}

__device__ __forceinline__ float2 block_meanvar_256(float v, float* r1, float* r2) {
    float s = v, q = v * v;
    #pragma unroll
    for (int o = 16; o; o >>= 1) {
        s += __shfl_xor_sync(0xffffffffu, s, o);
        q += __shfl_xor_sync(0xffffffffu, q, o);
    }
    int w = threadIdx.x >> 5, lane = threadIdx.x & 31;
    if (lane == 0) { r1[w] = s; r2[w] = q; }
    __syncthreads();
    float sum = 0.f, sq = 0.f;
    #pragma unroll
    for (int i = 0; i < 8; i++) { sum += r1[i]; sq += r2[i]; }
    __syncthreads();
    float m = sum * (1.f / 256.f);
    float var = sq * (1.f / 256.f) - m * m;
    return make_float2(m, rsqrtf(var + 1e-5f));
}

// feats = (half) LN(h2) over 256-wide rows
__global__ void ln256_kernel(const float* __restrict__ x, __half* __restrict__ y,
                             const float* __restrict__ g, const float* __restrict__ b) {
    __shared__ float r1[8], r2[8];
    size_t row = blockIdx.x;
    int tid = threadIdx.x;
    float v = x[row * DD + tid];
    float2 mv = block_meanvar_256(v, r1, r2);
    y[row * DD + tid] = __float2half((v - mv.x) * mv.y * g[tid] + b[tid]);
}

// q = LN(slots) @ wq^T ; zero U/rowsum for upcoming attention pass
__global__ void qproj_kernel(const float* __restrict__ ng, const float* __restrict__ nb) {
    __shared__ float sln[DD];
    __shared__ float r1[8], r2[8];
    int row = blockIdx.x, tid = threadIdx.x;
    float v = g_slots[row * DD + tid];
    float2 mv = block_meanvar_256(v, r1, r2);
    sln[tid] = (v - mv.x) * mv.y * ng[tid] + nb[tid];
    g_U[row * DD + tid] = 0.f;
    if (tid == 0) g_rowsum[row] = 0.f;
    __syncthreads();
    float acc = 0.f;
    #pragma unroll 8
    for (int d = 0; d < DD; d++) acc += sln[d] * g_wqT[d * DD + tid];
    g_q[row * DD + tid] = acc;
}

// attention over fp16 kv: U += attn_u @ V, rowsum += sum_t attn_u
__global__ void __launch_bounds__(256)
attn_kernel() {
    int b = blockIdx.x, ch = blockIdx.y;       // 16 chunks of 256 tokens
    int warp = threadIdx.x >> 5, lane = threadIdx.x & 31;
    __shared__ float qs[NS * DD];
    __shared__ float dots[8][NS];
    for (int i = threadIdx.x; i < NS * DD; i += 256) qs[i] = g_q[b * NS * DD + i];
    __syncthreads();
    float qreg[8];
    #pragma unroll
    for (int k = 0; k < 4; k++) {
        qreg[2 * k]     = qs[warp * DD + 2 * (lane + 32 * k)];
        qreg[2 * k + 1] = qs[warp * DD + 2 * (lane + 32 * k) + 1];
    }
    float2 uacc[4];
    #pragma unroll
    for (int k = 0; k < 4; k++) uacc[k] = make_float2(0.f, 0.f);
    float rsum = 0.f;
    const float scale = 0.0625f;
    int t0 = ch * 256;
    const __half* kvb = g_kvh + ((size_t)b * NTOK + t0) * 512;

    for (int tt = 0; tt < 256; tt += 8) {
        #pragma unroll
        for (int u = 0; u < 8; u++) {
            const __half2* kp = (const __half2*)(kvb + (size_t)(tt + u) * 512);
            float d = 0.f;
            #pragma unroll
            for (int k = 0; k < 4; k++) {
                float2 kv2 = __half22float2(kp[lane + 32 * k]);
                d += qreg[2 * k] * kv2.x + qreg[2 * k + 1] * kv2.y;
            }
            #pragma unroll
            for (int o = 16; o; o >>= 1) d += __shfl_xor_sync(0xffffffffu, d, o);
            if (lane == 0) dots[u][warp] = d * scale;
        }
        __syncthreads();
        #pragma unroll
        for (int u = 0; u < 8; u++) {
            float mx = -1e30f;
            #pragma unroll
            for (int s2 = 0; s2 < NS; s2++) mx = fmaxf(mx, dots[u][s2]);
            float sume = 0.f;
            #pragma unroll
            for (int s2 = 0; s2 < NS; s2++) sume += expf(dots[u][s2] - mx);
            float a = expf(dots[u][warp] - mx) / sume + 1e-8f;
            const __half2* vp = (const __half2*)(kvb + (size_t)(tt + u) * 512 + 256);
            #pragma unroll
            for (int k = 0; k < 4; k++) {
                float2 vv = __half22float2(vp[lane + 32 * k]);
                uacc[k].x += a * vv.x;
                uacc[k].y += a * vv.y;
            }
            rsum += a;
        }
        __syncthreads();
    }
    float* up = g_U + (b * NS + warp) * DD;
    #pragma unroll
    for (int k = 0; k < 4; k++) {
        atomicAdd(&up[2 * (lane + 32 * k)], uacc[k].x);
        atomicAdd(&up[2 * (lane + 32 * k) + 1], uacc[k].y);
    }
    if (lane == 0) atomicAdd(&g_rowsum[b * NS + warp], rsum);
}

__global__ void __launch_bounds__(256)
gru_mlp_kernel(const float* __restrict__ bih, const float* __restrict__ bhh,
               const float* __restrict__ mlng, const float* __restrict__ mlnb,
               const float* __restrict__ w1, const float* __restrict__ b1,
               const float* __restrict__ w2, const float* __restrict__ b2,
               float* __restrict__ dst) {
    __shared__ float upd[DD], sp[DD], mmx[DD];
    __shared__ float hh[4 * DD];
    __shared__ float r1[8], r2[8];
    int row = blockIdx.x, tid = threadIdx.x;
    float rs = g_rowsum[row];
    upd[tid] = g_U[row * DD + tid] / rs;
    sp[tid]  = g_slots[row * DD + tid];
    __syncthreads();

    float ir = bih[tid], iz = bih[tid + 256], inn = bih[tid + 512];
    float hr = bhh[tid], hz = bhh[tid + 256], hn = bhh[tid + 512];
    #pragma unroll 4
    for (int d = 0; d < DD; d++) {
        float u = upd[d], s = sp[d];
        const float* wi = &g_wihT[d * 768];
        const float* wh = &g_whhT[d * 768];
        ir  += u * wi[tid];       hr  += s * wh[tid];
        iz  += u * wi[tid + 256]; hz  += s * wh[tid + 256];
        inn += u * wi[tid + 512]; hn  += s * wh[tid + 512];
    }
    float r = 1.f / (1.f + expf(-(ir + hr)));
    float z = 1.f / (1.f + expf(-(iz + hz)));
    float n = tanhf(inn + r * hn);
    float h = (1.f - z) * n + z * sp[tid];
    __syncthreads();

    float2 mv = block_meanvar_256(h, r1, r2);
    mmx[tid] = (h - mv.x) * mv.y * mlng[tid] + mlnb[tid];
    __syncthreads();

    #pragma unroll
    for (int jj = 0; jj < 4; jj++) {
        int o = tid + jj * 256;
        float a = b1[o];
        #pragma unroll 8
        for (int d = 0; d < DD; d++) a += mmx[d] * w1[d * 1024 + o];
        hh[o] = fmaxf(a, 0.f);
    }
    __syncthreads();
    float a2 = b2[tid];
    #pragma unroll 8
    for (int j = 0; j < 1024; j++) a2 += hh[j] * w2[j * 256 + tid];
    dst[row * DD + tid] = h + a2;
}

// ================= launch =================
extern "C" void kernel_launch(void* const* d_in, const int* in_sizes, int n_in,
                              void* d_out, int out_size) {
    const float* inputs   = (const float*)d_in[0];
    const float* slots_in = (const float*)d_in[1];
    const float* ln1g = (const float*)d_in[2];
    const float* ln1b = (const float*)d_in[3];
    const float* w1   = (const float*)d_in[4];
    const float* b1   = (const float*)d_in[5];
    const float* w2   = (const float*)d_in[6];
    const float* b2   = (const float*)d_in[7];
    const float* ln2g = (const float*)d_in[8];
    const float* ln2b = (const float*)d_in[9];
    const float* wq   = (const float*)d_in[10];
    const float* wk   = (const float*)d_in[11];
    const float* wv   = (const float*)d_in[12];
    const float* normg = (const float*)d_in[13];
    const float* normb = (const float*)d_in[14];
    const float* gwih = (const float*)d_in[15];
    const float* gwhh = (const float*)d_in[16];
    const float* gbih = (const float*)d_in[17];
    const float* gbhh = (const float*)d_in[18];
    const float* mlng = (const float*)d_in[19];
    const float* mlnb = (const float*)d_in[20];
    const float* mw1  = (const float*)d_in[21];
    const float* mb1  = (const float*)d_in[22];
    const float* mw2  = (const float*)d_in[23];
    const float* mb2  = (const float*)d_in[24];
    float* out = (float*)d_out;

    __half *p_inh, *p_h1h, *p_featsh, *p_kvh, *p_w1h, *p_w2h, *p_wkvh;
    float *p_h2, *p_wqT, *p_wihT, *p_whhT, *p_slots;
    cudaGetSymbolAddress((void**)&p_inh,    g_inh);
    cudaGetSymbolAddress((void**)&p_h1h,    g_h1h);
    cudaGetSymbolAddress((void**)&p_featsh, g_featsh);
    cudaGetSymbolAddress((void**)&p_kvh,    g_kvh);
    cudaGetSymbolAddress((void**)&p_w1h,    g_w1h);
    cudaGetSymbolAddress((void**)&p_w2h,    g_w2h);
    cudaGetSymbolAddress((void**)&p_wkvh,   g_wkvh);
    cudaGetSymbolAddress((void**)&p_h2,     g_h2);
    cudaGetSymbolAddress((void**)&p_wqT,    g_wqT);
    cudaGetSymbolAddress((void**)&p_wihT,   g_wihT);
    cudaGetSymbolAddress((void**)&p_whhT,   g_whhT);
    cudaGetSymbolAddress((void**)&p_slots,  g_slots);

    cudaFuncSetAttribute(hgemm_kernel<1>, cudaFuncAttributeMaxDynamicSharedMemorySize, H_DSMEM);
    cudaFuncSetAttribute(hgemm_kernel<2>, cudaFuncAttributeMaxDynamicSharedMemorySize, H_DSMEM);
    cudaFuncSetAttribute(hgemm_kernel<3>, cudaFuncAttributeMaxDynamicSharedMemorySize, H_DSMEM);

    dim3 tb(32, 8);
    // 0: fused LN stats + fp16 conversion of inputs
    ln_stats_f2h_kernel<<<MROWS / 8, 256>>>(inputs, p_inh);
    // 1: w1 -> [N][K] fp16 scaled by ln1g
    trans_h_kernel<<<dim3(FDIN / 32, FDIN / 32), tb>>>(w1, p_w1h, FDIN, FDIN, ln1g);
    // 2: epilogue fold vectors
    prep_sums_kernel<<<FDIN, 256>>>(w1, ln1g, ln1b, b1);
    // 3: GEMM1  h1 = relu(LN(inputs) @ w1 + b1)  [LN folded] -> fp16   << ncu window
    hgemm_kernel<1><<<dim3(FDIN / 128, MROWS / 128), 256, H_DSMEM>>>(
        p_inh, p_w1h, FDIN, FDIN, nullptr, p_h1h, nullptr);
    // 4: w2 -> [N][K] fp16
    trans_h_kernel<<<dim3(DD / 32, FDIN / 32), tb>>>(w2, p_w2h, FDIN, DD, nullptr);
    // 5: GEMM2  h2 = h1 @ w2 + b2 -> fp32
    hgemm_kernel<2><<<dim3(DD / 128, MROWS / 128), 256, H_DSMEM>>>(
        p_h1h, p_w2h, DD, FDIN, p_h2, nullptr, b2);
    // 6: feats = LN(h2) -> fp16
    ln256_kernel<<<MROWS, 256>>>(p_h2, p_featsh, ln2g, ln2b);
    // 7: wk|wv -> fp16 [N=512][K=256]
    wkv_h_kernel<<<DD * DD / 256, 256>>>(wk, wv);
    // 8: KV GEMM: kv = feats @ [wk^T | wv^T] -> fp16
    hgemm_kernel<3><<<dim3(2 * DD / 128, MROWS / 128), 256, H_DSMEM>>>(
        p_featsh, p_wkvh, 2 * DD, DD, nullptr, p_kvh, nullptr);

    trans_f_kernel<<<dim3(DD / 32, DD / 32), tb>>>(wq, p_wqT, DD, DD);
    trans_f_kernel<<<dim3(DD / 32, 3 * DD / 32), tb>>>(gwih, p_wihT, 3 * DD, DD);
    trans_f_kernel<<<dim3(DD / 32, 3 * DD / 32), tb>>>(gwhh, p_whhT, 3 * DD, DD);
    slots_init_kernel<<<BNUM * NS * DD / 256, 256>>>(slots_in);

    for (int t = 0; t < ITERS; t++) {
        qproj_kernel<<<BNUM * NS, 256>>>(normg, normb);
        attn_kernel<<<dim3(BNUM, 16), 256>>>();
        gru_mlp_kernel<<<BNUM * NS, 256>>>(gbih, gbhh, mlng, mlnb, mw1, mb1, mw2, mb2,
                                           (t == ITERS - 1) ? out : p_slots);
    }
}

// round 8
// speedup vs baseline: 1.8986x; 1.0746x over previous
#include <cuda_runtime.h>
#include <cuda_fp16.h>
#include <math.h>
#include <stdint.h>

#define BNUM 32
#define NTOK 4096
#define FDIN 768
#define DD 256
#define NS 8
#define MROWS (BNUM * NTOK)   // 131072
#define ITERS 3

// ---------------- scratch (static __device__ — no allocation) ----------------
__device__ float  g_mean[MROWS];
__device__ float  g_rstd[MROWS];
__device__ __half g_inh[(size_t)MROWS * FDIN];    // inputs fp16
__device__ __half g_h1h[(size_t)MROWS * FDIN];    // h1 fp16
__device__ float  g_h2[(size_t)MROWS * DD];       // h2 fp32
__device__ __half g_featsh[(size_t)MROWS * DD];   // feats fp16
__device__ __half g_kvh[(size_t)MROWS * 2 * DD];  // [row][512]: keys | vals fp16
__device__ __half g_w1h[FDIN * FDIN];             // [N=768][K=768] fp16, scaled by ln1g
__device__ float  g_gB[FDIN];                     // g^T w1
__device__ float  g_bBp[FDIN];                    // b^T w1 + b1
__device__ __half g_w2h[DD * FDIN];               // [N=256][K=768] fp16
__device__ __half g_wkvh[2 * DD * DD];            // [N=512][K=256] fp16 = wk | wv
__device__ float  g_wqT[DD * DD];
__device__ float  g_wihT[DD * 3 * DD];
__device__ float  g_whhT[DD * 3 * DD];
__device__ float  g_slots[BNUM * NS * DD];
__device__ float  g_q[BNUM * NS * DD];
__device__ float  g_U[BNUM * NS * DD];
__device__ float  g_rowsum[BNUM * NS];

// ================= asm helpers =================
#define CP_ASYNC16(dst, src) \
    asm volatile("cp.async.cg.shared.global [%0], [%1], 16;\n" :: "r"(dst), "l"(src))
#define CP_COMMIT() asm volatile("cp.async.commit_group;\n" ::: "memory")
#define CP_WAIT1()  asm volatile("cp.async.wait_group 1;\n" ::: "memory")

__device__ __forceinline__ void ldmx4(uint32_t& r0, uint32_t& r1, uint32_t& r2,
                                      uint32_t& r3, uint32_t addr) {
    asm volatile("ldmatrix.sync.aligned.m8n8.x4.shared.b16 {%0,%1,%2,%3}, [%4];"
                 : "=r"(r0), "=r"(r1), "=r"(r2), "=r"(r3) : "r"(addr));
}

__device__ __forceinline__ void mma_f16(float* c, const uint32_t* a, const uint32_t* b) {
    asm volatile(
        "mma.sync.aligned.m16n8k16.row.col.f32.f16.f16.f32 "
        "{%0,%1,%2,%3}, {%4,%5,%6,%7}, {%8,%9}, {%0,%1,%2,%3};"
        : "+f"(c[0]), "+f"(c[1]), "+f"(c[2]), "+f"(c[3])
        : "r"(a[0]), "r"(a[1]), "r"(a[2]), "r"(a[3]), "r"(b[0]), "r"(b[1]));
}

// ================= fp16 tensor-core GEMM =================
// C[M,N] = A[M,K] @ B^T, A fp16 [M][K], B fp16 [N][K] (both K-major).
// Block 128x64, 8 warps (4x2), warp tile 32x32, BK=32, 3-stage cp.async.
// Small tile -> 32 acc regs/thread -> 3 CTAs/SM (occupancy fix, per R7 ncu).
// EPI 0: fp32. EPI 1: LN-fold+relu fp16. EPI 2: +bias fp32. EPI 3: raw fp16.
#define HROW 40                        // padded halves per smem row
#define STG_HALVES ((128 + 64) * HROW) // A block + B block per stage
#define STG_BYTES (STG_HALVES * 2)     // 15360
#define H_DSMEM (3 * STG_BYTES)        // 46080

template<int EPI>
__global__ void __launch_bounds__(256, 3)
hgemm_kernel(const __half* __restrict__ A, const __half* __restrict__ Bw,
             int Nn, int K, float* __restrict__ Cf, __half* __restrict__ Ch,
             const float* __restrict__ bias) {
    extern __shared__ __align__(16) __half smh[];
    uint32_t smb;
    asm("{ .reg .u64 t; cvta.to.shared.u64 t, %1; cvt.u32.u64 %0, t; }"
        : "=r"(smb) : "l"(smh));

    int tid = threadIdx.x;
    int lane = tid & 31;
    int warp = tid >> 5;
    int grp = lane >> 2;       // 0..7
    int tig = lane & 3;        // 0..3
    int wm = (warp & 3) * 32;
    int wn = (warp >> 2) * 32;
    int bm = blockIdx.y * 128;
    int bn = blockIdx.x * 64;

    const __half* Abm = A + (size_t)bm * K;
    const __half* Bbn = Bw + (size_t)bn * K;

    // A loader: 512 16B-chunks -> 2/thread; B loader: 256 chunks -> 1/thread
    int ar0 = tid >> 1;            // with j stride 128 rows? use e = tid + j*256
    (void)ar0;

    float acc[2][4][4];
    #pragma unroll
    for (int mt = 0; mt < 2; mt++)
        #pragma unroll
        for (int nt = 0; nt < 4; nt++)
            #pragma unroll
            for (int i = 0; i < 4; i++) acc[mt][nt][i] = 0.f;

    int nit = K / 32;

    // prologue: stages 0,1
    #pragma unroll
    for (int s = 0; s < 2; s++) {
        uint32_t base = smb + s * STG_BYTES;
        #pragma unroll
        for (int j = 0; j < 2; j++) {
            int e = tid + j * 256;
            int r = e >> 2, c = e & 3;
            CP_ASYNC16(base + (r * HROW + c * 8) * 2, Abm + (size_t)r * K + s * 32 + c * 8);
        }
        {
            int r = tid >> 2, c = tid & 3;
            CP_ASYNC16(base + (128 * HROW + r * HROW + c * 8) * 2,
                       Bbn + (size_t)r * K + s * 32 + c * 8);
        }
        CP_COMMIT();
    }

    for (int it = 0; it < nit; it++) {
        CP_WAIT1();
        __syncthreads();

        uint32_t sa = smb + (it % 3) * STG_BYTES;
        uint32_t sb = sa + 128 * HROW * 2;

        // prefetch stage it+2
        if (it + 2 < nit) {
            uint32_t base = smb + ((it + 2) % 3) * STG_BYTES;
            #pragma unroll
            for (int j = 0; j < 2; j++) {
                int e = tid + j * 256;
                int r = e >> 2, c = e & 3;
                CP_ASYNC16(base + (r * HROW + c * 8) * 2,
                           Abm + (size_t)r * K + (it + 2) * 32 + c * 8);
            }
            {
                int r = tid >> 2, c = tid & 3;
                CP_ASYNC16(base + (128 * HROW + r * HROW + c * 8) * 2,
                           Bbn + (size_t)r * K + (it + 2) * 32 + c * 8);
            }
        }
        CP_COMMIT();

        #pragma unroll
        for (int kc = 0; kc < 2; kc++) {
            uint32_t afr[2][4], bfr[4][2];
            #pragma unroll
            for (int mt = 0; mt < 2; mt++) {
                uint32_t addr = sa + ((wm + mt * 16 + (lane & 15)) * HROW
                                      + kc * 16 + (lane >> 4) * 8) * 2;
                ldmx4(afr[mt][0], afr[mt][1], afr[mt][2], afr[mt][3], addr);
            }
            #pragma unroll
            for (int ng = 0; ng < 2; ng++) {
                uint32_t r0, r1, r2, r3;
                uint32_t addr = sb + ((wn + ng * 16 + (lane & 15)) * HROW
                                      + kc * 16 + (lane >> 4) * 8) * 2;
                ldmx4(r0, r1, r2, r3, addr);
                bfr[2 * ng][0] = r0; bfr[2 * ng + 1][0] = r1;
                bfr[2 * ng][1] = r2; bfr[2 * ng + 1][1] = r3;
            }
            #pragma unroll
            for (int mt = 0; mt < 2; mt++)
                #pragma unroll
                for (int nt = 0; nt < 4; nt++)
                    mma_f16(acc[mt][nt], afr[mt], bfr[nt]);
        }
    }

    // ----------------- epilogue -----------------
    #pragma unroll
    for (int mt = 0; mt < 2; mt++) {
        int r0 = bm + wm + mt * 16 + grp;
        float mu0 = 0.f, rs0 = 0.f, mu1 = 0.f, rs1 = 0.f;
        if (EPI == 1) {
            mu0 = g_mean[r0]; rs0 = g_rstd[r0];
            mu1 = g_mean[r0 + 8]; rs1 = g_rstd[r0 + 8];
        }
        #pragma unroll
        for (int nt = 0; nt < 4; nt++) {
            int col = bn + wn + nt * 8 + tig * 2;
            float c0 = acc[mt][nt][0], c1 = acc[mt][nt][1];
            float c2 = acc[mt][nt][2], c3 = acc[mt][nt][3];
            if (EPI == 1) {
                float gb0 = __ldg(&g_gB[col]), gb1 = __ldg(&g_gB[col + 1]);
                float bb0 = __ldg(&g_bBp[col]), bb1 = __ldg(&g_bBp[col + 1]);
                c0 = fmaxf(c0 * rs0 - mu0 * rs0 * gb0 + bb0, 0.f);
                c1 = fmaxf(c1 * rs0 - mu0 * rs0 * gb1 + bb1, 0.f);
                c2 = fmaxf(c2 * rs1 - mu1 * rs1 * gb0 + bb0, 0.f);
                c3 = fmaxf(c3 * rs1 - mu1 * rs1 * gb1 + bb1, 0.f);
                *(__half2*)(Ch + (size_t)r0 * Nn + col) = __floats2half2_rn(c0, c1);
                *(__half2*)(Ch + (size_t)(r0 + 8) * Nn + col) = __floats2half2_rn(c2, c3);
            } else if (EPI == 2) {
                float b0 = __ldg(&bias[col]), b1 = __ldg(&bias[col + 1]);
                *(float2*)(Cf + (size_t)r0 * Nn + col)       = make_float2(c0 + b0, c1 + b1);
                *(float2*)(Cf + (size_t)(r0 + 8) * Nn + col) = make_float2(c2 + b0, c3 + b1);
            } else if (EPI == 3) {
                *(__half2*)(Ch + (size_t)r0 * Nn + col)       = __floats2half2_rn(c0, c1);
                *(__half2*)(Ch + (size_t)(r0 + 8) * Nn + col) = __floats2half2_rn(c2, c3);
            } else {
                *(float2*)(Cf + (size_t)r0 * Nn + col)       = make_float2(c0, c1);
                *(float2*)(Cf + (size_t)(r0 + 8) * Nn + col) = make_float2(c2, c3);
            }
        }
    }
}

// ================= prep / small kernels =================
__global__ void ln_stats_f2h_kernel(const float* __restrict__ x, __half* __restrict__ xh) {
    int row = blockIdx.x * 8 + (threadIdx.x >> 5);
    int lane = threadIdx.x & 31;
    const float* p = x + (size_t)row * FDIN;
    __half* ph = xh + (size_t)row * FDIN;
    float v[24];
    float s = 0.f, ss = 0.f;
    #pragma unroll
    for (int k = 0; k < 24; k++) {
        v[k] = p[lane + 32 * k];
        s += v[k];
        ss += v[k] * v[k];
    }
    #pragma unroll
    for (int k = 0; k < 24; k++) ph[lane + 32 * k] = __float2half(v[k]);
    #pragma unroll
    for (int o = 16; o; o >>= 1) {
        s  += __shfl_xor_sync(0xffffffffu, s, o);
        ss += __shfl_xor_sync(0xffffffffu, ss, o);
    }
    float m = s * (1.f / FDIN);
    float var = ss * (1.f / FDIN) - m * m;
    if (lane == 0) { g_mean[row] = m; g_rstd[row] = rsqrtf(var + 1e-5f); }
}

__global__ void trans_h_kernel(const float* __restrict__ in, __half* __restrict__ out,
                               int R, int C, const float* __restrict__ scale) {
    __shared__ float t[32][33];
    int bx = blockIdx.x * 32, by = blockIdx.y * 32;
    int x = bx + threadIdx.x;
    #pragma unroll
    for (int j = 0; j < 32; j += 8) {
        int y = by + threadIdx.y + j;
        float s = scale ? scale[y] : 1.f;
        t[threadIdx.y + j][threadIdx.x] = in[(size_t)y * C + x] * s;
    }
    __syncthreads();
    int x2 = by + threadIdx.x;
    #pragma unroll
    for (int j = 0; j < 32; j += 8) {
        int y2 = bx + threadIdx.y + j;
        out[(size_t)y2 * R + x2] = __float2half(t[threadIdx.x][threadIdx.y + j]);
    }
}

__global__ void trans_f_kernel(const float* __restrict__ in, float* __restrict__ out,
                               int R, int C) {
    __shared__ float t[32][33];
    int bx = blockIdx.x * 32, by = blockIdx.y * 32;
    int x = bx + threadIdx.x;
    #pragma unroll
    for (int j = 0; j < 32; j += 8)
        t[threadIdx.y + j][threadIdx.x] = in[(size_t)(by + threadIdx.y + j) * C + x];
    __syncthreads();
    int x2 = by + threadIdx.x;
    #pragma unroll
    for (int j = 0; j < 32; j += 8)
        out[(size_t)(bx + threadIdx.y + j) * R + x2] = t[threadIdx.x][threadIdx.y + j];
}

__global__ void wkv_h_kernel(const float* __restrict__ wk, const float* __restrict__ wv) {
    int i = blockIdx.x * 256 + threadIdx.x;
    g_wkvh[i] = __float2half(wk[i]);
    g_wkvh[DD * DD + i] = __float2half(wv[i]);
}

__global__ void prep_sums_kernel(const float* __restrict__ w1,
                                 const float* __restrict__ g,
                                 const float* __restrict__ b,
                                 const float* __restrict__ b1) {
    __shared__ float r1[8], r2[8];
    int n = blockIdx.x, t = threadIdx.x;
    float s1 = 0.f, s2 = 0.f;
    for (int k = t; k < FDIN; k += 256) {
        float w = w1[(size_t)k * FDIN + n];
        s1 += g[k] * w;
        s2 += b[k] * w;
    }
    #pragma unroll
    for (int o = 16; o; o >>= 1) {
        s1 += __shfl_xor_sync(0xffffffffu, s1, o);
        s2 += __shfl_xor_sync(0xffffffffu, s2, o);
    }
    int w = t >> 5, lane = t & 31;
    if (lane == 0) { r1[w] = s1; r2[w] = s2; }
    __syncthreads();
    if (t == 0) {
        float a = 0.f, c = 0.f;
        #pragma unroll
        for (int i = 0; i < 8; i++) { a += r1[i]; c += r2[i]; }
        g_gB[n] = a;
        g_bBp[n] = c + b1[n];
    }
}

__global__ void slots_init_kernel(const float* __restrict__ si) {
    int i = blockIdx.x * 256 + threadIdx.x;
    g_slots[i] = si[i & (NS * DD - 1)];
}

__device__ __forceinline__ float2 block_meanvar_256(float v, float* r1, float* r2) {
    float s = v, q = v * v;
    #pragma unroll
    for (int o = 16; o; o >>= 1) {
        s += __shfl_xor_sync(0xffffffffu, s, o);
        q += __shfl_xor_sync(0xffffffffu, q, o);
    }
    int w = threadIdx.x >> 5, lane = threadIdx.x & 31;
    if (lane == 0) { r1[w] = s; r2[w] = q; }
    __syncthreads();
    float sum = 0.f, sq = 0.f;
    #pragma unroll
    for (int i = 0; i < 8; i++) { sum += r1[i]; sq += r2[i]; }
    __syncthreads();
    float m = sum * (1.f / 256.f);
    float var = sq * (1.f / 256.f) - m * m;
    return make_float2(m, rsqrtf(var + 1e-5f));
}

__global__ void ln256_kernel(const float* __restrict__ x, __half* __restrict__ y,
                             const float* __restrict__ g, const float* __restrict__ b) {
    __shared__ float r1[8], r2[8];
    size_t row = blockIdx.x;
    int tid = threadIdx.x;
    float v = x[row * DD + tid];
    float2 mv = block_meanvar_256(v, r1, r2);
    y[row * DD + tid] = __float2half((v - mv.x) * mv.y * g[tid] + b[tid]);
}

__global__ void qproj_kernel(const float* __restrict__ ng, const float* __restrict__ nb) {
    __shared__ float sln[DD];
    __shared__ float r1[8], r2[8];
    int row = blockIdx.x, tid = threadIdx.x;
    float v = g_slots[row * DD + tid];
    float2 mv = block_meanvar_256(v, r1, r2);
    sln[tid] = (v - mv.x) * mv.y * ng[tid] + nb[tid];
    g_U[row * DD + tid] = 0.f;
    if (tid == 0) g_rowsum[row] = 0.f;
    __syncthreads();
    float acc = 0.f;
    #pragma unroll 8
    for (int d = 0; d < DD; d++) acc += sln[d] * g_wqT[d * DD + tid];
    g_q[row * DD + tid] = acc;
}

// attention: cooperative softmax (attn weights computed once, not per-warp)
__global__ void __launch_bounds__(256)
attn_kernel() {
    int b = blockIdx.x, ch = blockIdx.y;       // 16 chunks of 256 tokens
    int warp = threadIdx.x >> 5, lane = threadIdx.x & 31;
    __shared__ float qs[NS * DD];
    __shared__ float dots[8][NS];
    __shared__ float aw[8][NS];
    for (int i = threadIdx.x; i < NS * DD; i += 256) qs[i] = g_q[b * NS * DD + i];
    __syncthreads();
    float qreg[8];
    #pragma unroll
    for (int k = 0; k < 4; k++) {
        qreg[2 * k]     = qs[warp * DD + 2 * (lane + 32 * k)];
        qreg[2 * k + 1] = qs[warp * DD + 2 * (lane + 32 * k) + 1];
    }
    float2 uacc[4];
    #pragma unroll
    for (int k = 0; k < 4; k++) uacc[k] = make_float2(0.f, 0.f);
    float rsum = 0.f;
    const float scale = 0.0625f;
    int t0 = ch * 256;
    const __half* kvb = g_kvh + ((size_t)b * NTOK + t0) * 512;

    for (int tt = 0; tt < 256; tt += 8) {
        // phase 1: warp = slot, 8 tokens of dots
        #pragma unroll
        for (int u = 0; u < 8; u++) {
            const __half2* kp = (const __half2*)(kvb + (size_t)(tt + u) * 512);
            float d = 0.f;
            #pragma unroll
            for (int k = 0; k < 4; k++) {
                float2 kv2 = __half22float2(kp[lane + 32 * k]);
                d += qreg[2 * k] * kv2.x + qreg[2 * k + 1] * kv2.y;
            }
            #pragma unroll
            for (int o = 16; o; o >>= 1) d += __shfl_xor_sync(0xffffffffu, d, o);
            if (lane == 0) dots[u][warp] = d * scale;
        }
        __syncthreads();
        // phase 2a: threads 0..63 compute attn weights once (u=tid>>3, s=tid&7)
        if (threadIdx.x < 64) {
            int u = threadIdx.x >> 3, s = threadIdx.x & 7;
            float mx = -1e30f;
            #pragma unroll
            for (int s2 = 0; s2 < NS; s2++) mx = fmaxf(mx, dots[u][s2]);
            float e = expf(dots[u][s] - mx);
            float sum = e;
            #pragma unroll
            for (int o = 1; o < 8; o <<= 1) sum += __shfl_xor_sync(0xffffffffu, sum, o);
            aw[u][s] = e / sum + 1e-8f;
        }
        __syncthreads();
        // phase 2b: accumulate updates with precomputed weights
        #pragma unroll
        for (int u = 0; u < 8; u++) {
            float a = aw[u][warp];
            const __half2* vp = (const __half2*)(kvb + (size_t)(tt + u) * 512 + 256);
            #pragma unroll
            for (int k = 0; k < 4; k++) {
                float2 vv = __half22float2(vp[lane + 32 * k]);
                uacc[k].x += a * vv.x;
                uacc[k].y += a * vv.y;
            }
            rsum += a;
        }
        __syncthreads();
    }
    float* up = g_U + (b * NS + warp) * DD;
    #pragma unroll
    for (int k = 0; k < 4; k++) {
        atomicAdd(&up[2 * (lane + 32 * k)], uacc[k].x);
        atomicAdd(&up[2 * (lane + 32 * k) + 1], uacc[k].y);
    }
    if (lane == 0) atomicAdd(&g_rowsum[b * NS + warp], rsum);
}

__global__ void __launch_bounds__(256)
gru_mlp_kernel(const float* __restrict__ bih, const float* __restrict__ bhh,
               const float* __restrict__ mlng, const float* __restrict__ mlnb,
               const float* __restrict__ w1, const float* __restrict__ b1,
               const float* __restrict__ w2, const float* __restrict__ b2,
               float* __restrict__ dst) {
    __shared__ float upd[DD], sp[DD], mmx[DD];
    __shared__ float hh[4 * DD];
    __shared__ float r1[8], r2[8];
    int row = blockIdx.x, tid = threadIdx.x;
    float rs = g_rowsum[row];
    upd[tid] = g_U[row * DD + tid] / rs;
    sp[tid]  = g_slots[row * DD + tid];
    __syncthreads();

    float ir = bih[tid], iz = bih[tid + 256], inn = bih[tid + 512];
    float hr = bhh[tid], hz = bhh[tid + 256], hn = bhh[tid + 512];
    #pragma unroll 4
    for (int d = 0; d < DD; d++) {
        float u = upd[d], s = sp[d];
        const float* wi = &g_wihT[d * 768];
        const float* wh = &g_whhT[d * 768];
        ir  += u * wi[tid];       hr  += s * wh[tid];
        iz  += u * wi[tid + 256]; hz  += s * wh[tid + 256];
        inn += u * wi[tid + 512]; hn  += s * wh[tid + 512];
    }
    float r = 1.f / (1.f + expf(-(ir + hr)));
    float z = 1.f / (1.f + expf(-(iz + hz)));
    float n = tanhf(inn + r * hn);
    float h = (1.f - z) * n + z * sp[tid];
    __syncthreads();

    float2 mv = block_meanvar_256(h, r1, r2);
    mmx[tid] = (h - mv.x) * mv.y * mlng[tid] + mlnb[tid];
    __syncthreads();

    #pragma unroll
    for (int jj = 0; jj < 4; jj++) {
        int o = tid + jj * 256;
        float a = b1[o];
        #pragma unroll 8
        for (int d = 0; d < DD; d++) a += mmx[d] * w1[d * 1024 + o];
        hh[o] = fmaxf(a, 0.f);
    }
    __syncthreads();
    float a2 = b2[tid];
    #pragma unroll 8
    for (int j = 0; j < 1024; j++) a2 += hh[j] * w2[j * 256 + tid];
    dst[row * DD + tid] = h + a2;
}

// ================= launch =================
extern "C" void kernel_launch(void* const* d_in, const int* in_sizes, int n_in,
                              void* d_out, int out_size) {
    const float* inputs   = (const float*)d_in[0];
    const float* slots_in = (const float*)d_in[1];
    const float* ln1g = (const float*)d_in[2];
    const float* ln1b = (const float*)d_in[3];
    const float* w1   = (const float*)d_in[4];
    const float* b1   = (const float*)d_in[5];
    const float* w2   = (const float*)d_in[6];
    const float* b2   = (const float*)d_in[7];
    const float* ln2g = (const float*)d_in[8];
    const float* ln2b = (const float*)d_in[9];
    const float* wq   = (const float*)d_in[10];
    const float* wk   = (const float*)d_in[11];
    const float* wv   = (const float*)d_in[12];
    const float* normg = (const float*)d_in[13];
    const float* normb = (const float*)d_in[14];
    const float* gwih = (const float*)d_in[15];
    const float* gwhh = (const float*)d_in[16];
    const float* gbih = (const float*)d_in[17];
    const float* gbhh = (const float*)d_in[18];
    const float* mlng = (const float*)d_in[19];
    const float* mlnb = (const float*)d_in[20];
    const float* mw1  = (const float*)d_in[21];
    const float* mb1  = (const float*)d_in[22];
    const float* mw2  = (const float*)d_in[23];
    const float* mb2  = (const float*)d_in[24];
    float* out = (float*)d_out;

    __half *p_inh, *p_h1h, *p_featsh, *p_kvh, *p_w1h, *p_w2h, *p_wkvh;
    float *p_h2, *p_wqT, *p_wihT, *p_whhT, *p_slots;
    cudaGetSymbolAddress((void**)&p_inh,    g_inh);
    cudaGetSymbolAddress((void**)&p_h1h,    g_h1h);
    cudaGetSymbolAddress((void**)&p_featsh, g_featsh);
    cudaGetSymbolAddress((void**)&p_kvh,    g_kvh);
    cudaGetSymbolAddress((void**)&p_w1h,    g_w1h);
    cudaGetSymbolAddress((void**)&p_w2h,    g_w2h);
    cudaGetSymbolAddress((void**)&p_wkvh,   g_wkvh);
    cudaGetSymbolAddress((void**)&p_h2,     g_h2);
    cudaGetSymbolAddress((void**)&p_wqT,    g_wqT);
    cudaGetSymbolAddress((void**)&p_wihT,   g_wihT);
    cudaGetSymbolAddress((void**)&p_whhT,   g_whhT);
    cudaGetSymbolAddress((void**)&p_slots,  g_slots);

    dim3 tb(32, 8);
    // 0: fused LN stats + fp16 conversion of inputs
    ln_stats_f2h_kernel<<<MROWS / 8, 256>>>(inputs, p_inh);
    // 1: w1 -> [N][K] fp16 scaled by ln1g
    trans_h_kernel<<<dim3(FDIN / 32, FDIN / 32), tb>>>(w1, p_w1h, FDIN, FDIN, ln1g);
    // 2: epilogue fold vectors
    prep_sums_kernel<<<FDIN, 256>>>(w1, ln1g, ln1b, b1);
    // 3: GEMM1  h1 = relu(LN(inputs) @ w1 + b1)  [LN folded] -> fp16   << ncu window
    hgemm_kernel<1><<<dim3(FDIN / 64, MROWS / 128), 256, H_DSMEM>>>(
        p_inh, p_w1h, FDIN, FDIN, nullptr, p_h1h, nullptr);
    // 4: w2 -> [N][K] fp16
    trans_h_kernel<<<dim3(DD / 32, FDIN / 32), tb>>>(w2, p_w2h, FDIN, DD, nullptr);
    // 5: GEMM2  h2 = h1 @ w2 + b2 -> fp32
    hgemm_kernel<2><<<dim3(DD / 64, MROWS / 128), 256, H_DSMEM>>>(
        p_h1h, p_w2h, DD, FDIN, p_h2, nullptr, b2);
    // 6: feats = LN(h2) -> fp16
    ln256_kernel<<<MROWS, 256>>>(p_h2, p_featsh, ln2g, ln2b);
    // 7: wk|wv -> fp16 [N=512][K=256]
    wkv_h_kernel<<<DD * DD / 256, 256>>>(wk, wv);
    // 8: KV GEMM: kv = feats @ [wk^T | wv^T] -> fp16
    hgemm_kernel<3><<<dim3(2 * DD / 64, MROWS / 128), 256, H_DSMEM>>>(
        p_featsh, p_wkvh, 2 * DD, DD, nullptr, p_kvh, nullptr);

    trans_f_kernel<<<dim3(DD / 32, DD / 32), tb>>>(wq, p_wqT, DD, DD);
    trans_f_kernel<<<dim3(DD / 32, 3 * DD / 32), tb>>>(gwih, p_wihT, 3 * DD, DD);
    trans_f_kernel<<<dim3(DD / 32, 3 * DD / 32), tb>>>(gwhh, p_whhT, 3 * DD, DD);
    slots_init_kernel<<<BNUM * NS * DD / 256, 256>>>(slots_in);

    for (int t = 0; t < ITERS; t++) {
        qproj_kernel<<<BNUM * NS, 256>>>(normg, normb);
        attn_kernel<<<dim3(BNUM, 16), 256>>>();
        gru_mlp_kernel<<<BNUM * NS, 256>>>(gbih, gbhh, mlng, mlnb, mw1, mb1, mw2, mb2,
                                           (t == ITERS - 1) ? out : p_slots);
    }
}

// round 10
// speedup vs baseline: 2.4914x; 1.3122x over previous
#include <cuda_runtime.h>
#include <cuda_fp16.h>
#include <math.h>
#include <stdint.h>

#define BNUM 32
#define NTOK 4096
#define FDIN 768
#define DD 256
#define NS 8
#define MROWS (BNUM * NTOK)   // 131072
#define SROWS (BNUM * NS)     // 768 slot rows
#define ITERS 3

// ---------------- scratch (static __device__ — no allocation) ----------------
__device__ float  g_mean[MROWS];
__device__ float  g_rstd[MROWS];
__device__ __half g_inh[(size_t)MROWS * FDIN];
__device__ __half g_h1h[(size_t)MROWS * FDIN];
__device__ float  g_h2[(size_t)MROWS * DD];
__device__ __half g_featsh[(size_t)MROWS * DD];
__device__ __half g_kvh[(size_t)MROWS * 2 * DD];  // [row][512]: keys | vals fp16
__device__ __half g_w1h[FDIN * FDIN];             // [N=768][K=768], scaled by ln1g
__device__ float  g_gB[FDIN];
__device__ float  g_bBp[FDIN];
__device__ __half g_w2h[DD * FDIN];               // [N=256][K=768]
__device__ __half g_wkvh[2 * DD * DD];            // [N=512][K=256]
__device__ float  g_wqT[DD * DD];
// GRU / MLP weights fp16 (K-major)
__device__ __half g_wihh[3 * DD * DD];            // [768][256] as-is
__device__ __half g_whhh[3 * DD * DD];            // [768][256] as-is
__device__ __half g_mw1h[4 * DD * DD];            // [1024][256] (transposed)
__device__ __half g_mw2h[DD * 4 * DD];            // [256][1024] (transposed)
// iteration state
__device__ float  g_slots[SROWS * DD];
__device__ __half g_slotsh[SROWS * DD];
__device__ float  g_q[SROWS * DD];
__device__ float  g_U[SROWS * DD];
__device__ float  g_rowsum[SROWS];
__device__ __half g_updh[SROWS * DD];
__device__ float  g_gi[SROWS * 3 * DD];
__device__ float  g_gh[SROWS * 3 * DD];
__device__ float  g_hbuf[SROWS * DD];
__device__ __half g_mlpinh[SROWS * DD];
__device__ __half g_hhh[SROWS * 4 * DD];

// ================= asm helpers =================
#define CP_ASYNC16(dst, src) \
    asm volatile("cp.async.cg.shared.global [%0], [%1], 16;\n" :: "r"(dst), "l"(src))
#define CP_COMMIT() asm volatile("cp.async.commit_group;\n" ::: "memory")
#define CP_WAIT1()  asm volatile("cp.async.wait_group 1;\n" ::: "memory")

__device__ __forceinline__ void ldmx4(uint32_t& r0, uint32_t& r1, uint32_t& r2,
                                      uint32_t& r3, uint32_t addr) {
    asm volatile("ldmatrix.sync.aligned.m8n8.x4.shared.b16 {%0,%1,%2,%3}, [%4];"
                 : "=r"(r0), "=r"(r1), "=r"(r2), "=r"(r3) : "r"(addr));
}

__device__ __forceinline__ void mma_f16(float* c, const uint32_t* a, const uint32_t* b) {
    asm volatile(
        "mma.sync.aligned.m16n8k16.row.col.f32.f16.f16.f32 "
        "{%0,%1,%2,%3}, {%4,%5,%6,%7}, {%8,%9}, {%0,%1,%2,%3};"
        : "+f"(c[0]), "+f"(c[1]), "+f"(c[2]), "+f"(c[3])
        : "r"(a[0]), "r"(a[1]), "r"(a[2]), "r"(a[3]), "r"(b[0]), "r"(b[1]));
}

#define HROW 40

// ================= big-tile fp16 GEMM (feature path): 128x128, 8 warps ======
// EPI 1: LN-fold+relu -> fp16. EPI 2: +bias -> fp32. EPI 3: raw -> fp16.
#define STG128_BYTES (256 * HROW * 2)   // 20480
#define H128_DSMEM (3 * STG128_BYTES)   // 61440

template<int EPI>
__global__ void __launch_bounds__(256)
hgemm128_kernel(const __half* __restrict__ A, const __half* __restrict__ Bw,
                int Nn, int K, float* __restrict__ Cf, __half* __restrict__ Ch,
                const float* __restrict__ bias) {
    extern __shared__ __align__(16) __half smh[];
    uint32_t smb;
    asm("{ .reg .u64 t; cvta.to.shared.u64 t, %1; cvt.u32.u64 %0, t; }"
        : "=r"(smb) : "l"(smh));

    int tid = threadIdx.x;
    int lane = tid & 31;
    int warp = tid >> 5;
    int grp = lane >> 2, tig = lane & 3;
    int wm = (warp & 3) * 32;
    int wn = (warp >> 2) * 64;
    int bm = blockIdx.y * 128;
    int bn = blockIdx.x * 128;

    const __half* Abm = A + (size_t)bm * K;
    const __half* Bbn = Bw + (size_t)bn * K;

    float acc[2][8][4];
    #pragma unroll
    for (int mt = 0; mt < 2; mt++)
        #pragma unroll
        for (int nt = 0; nt < 8; nt++)
            #pragma unroll
            for (int i = 0; i < 4; i++) acc[mt][nt][i] = 0.f;

    int nit = K / 32;
    #pragma unroll
    for (int s = 0; s < 2; s++) {
        uint32_t base = smb + s * STG128_BYTES;
        #pragma unroll
        for (int j = 0; j < 2; j++) {
            int e = tid + j * 256;
            int r = e >> 2, c = e & 3;
            CP_ASYNC16(base + (r * HROW + c * 8) * 2, Abm + (size_t)r * K + s * 32 + c * 8);
            CP_ASYNC16(base + (128 * HROW + r * HROW + c * 8) * 2,
                       Bbn + (size_t)r * K + s * 32 + c * 8);
        }
        CP_COMMIT();
    }

    for (int it = 0; it < nit; it++) {
        CP_WAIT1();
        __syncthreads();
        uint32_t sa = smb + (it % 3) * STG128_BYTES;
        uint32_t sb = sa + 128 * HROW * 2;
        if (it + 2 < nit) {
            uint32_t base = smb + ((it + 2) % 3) * STG128_BYTES;
            #pragma unroll
            for (int j = 0; j < 2; j++) {
                int e = tid + j * 256;
                int r = e >> 2, c = e & 3;
                CP_ASYNC16(base + (r * HROW + c * 8) * 2,
                           Abm + (size_t)r * K + (it + 2) * 32 + c * 8);
                CP_ASYNC16(base + (128 * HROW + r * HROW + c * 8) * 2,
                           Bbn + (size_t)r * K + (it + 2) * 32 + c * 8);
            }
        }
        CP_COMMIT();

        #pragma unroll
        for (int kc = 0; kc < 2; kc++) {
            uint32_t afr[2][4], bfr[8][2];
            #pragma unroll
            for (int mt = 0; mt < 2; mt++) {
                uint32_t addr = sa + ((wm + mt * 16 + (lane & 15)) * HROW
                                      + kc * 16 + (lane >> 4) * 8) * 2;
                ldmx4(afr[mt][0], afr[mt][1], afr[mt][2], afr[mt][3], addr);
            }
            #pragma unroll
            for (int ng = 0; ng < 4; ng++) {
                uint32_t r0, r1, r2, r3;
                uint32_t addr = sb + ((wn + ng * 16 + (lane & 15)) * HROW
                                      + kc * 16 + (lane >> 4) * 8) * 2;
                ldmx4(r0, r1, r2, r3, addr);
                bfr[2 * ng][0] = r0; bfr[2 * ng + 1][0] = r1;
                bfr[2 * ng][1] = r2; bfr[2 * ng + 1][1] = r3;
            }
            #pragma unroll
            for (int mt = 0; mt < 2; mt++)
                #pragma unroll
                for (int nt = 0; nt < 8; nt++)
                    mma_f16(acc[mt][nt], afr[mt], bfr[nt]);
        }
    }

    #pragma unroll
    for (int mt = 0; mt < 2; mt++) {
        int r0 = bm + wm + mt * 16 + grp;
        float mu0 = 0.f, rs0 = 0.f, mu1 = 0.f, rs1 = 0.f;
        if (EPI == 1) {
            mu0 = g_mean[r0]; rs0 = g_rstd[r0];
            mu1 = g_mean[r0 + 8]; rs1 = g_rstd[r0 + 8];
        }
        #pragma unroll
        for (int nt = 0; nt < 8; nt++) {
            int col = bn + wn + nt * 8 + tig * 2;
            float c0 = acc[mt][nt][0], c1 = acc[mt][nt][1];
            float c2 = acc[mt][nt][2], c3 = acc[mt][nt][3];
            if (EPI == 1) {
                float gb0 = __ldg(&g_gB[col]), gb1 = __ldg(&g_gB[col + 1]);
                float bb0 = __ldg(&g_bBp[col]), bb1 = __ldg(&g_bBp[col + 1]);
                c0 = fmaxf(c0 * rs0 - mu0 * rs0 * gb0 + bb0, 0.f);
                c1 = fmaxf(c1 * rs0 - mu0 * rs0 * gb1 + bb1, 0.f);
                c2 = fmaxf(c2 * rs1 - mu1 * rs1 * gb0 + bb0, 0.f);
                c3 = fmaxf(c3 * rs1 - mu1 * rs1 * gb1 + bb1, 0.f);
                *(__half2*)(Ch + (size_t)r0 * Nn + col) = __floats2half2_rn(c0, c1);
                *(__half2*)(Ch + (size_t)(r0 + 8) * Nn + col) = __floats2half2_rn(c2, c3);
            } else if (EPI == 2) {
                float b0 = __ldg(&bias[col]), b1 = __ldg(&bias[col + 1]);
                *(float2*)(Cf + (size_t)r0 * Nn + col)       = make_float2(c0 + b0, c1 + b1);
                *(float2*)(Cf + (size_t)(r0 + 8) * Nn + col) = make_float2(c2 + b0, c3 + b1);
            } else {
                *(__half2*)(Ch + (size_t)r0 * Nn + col)       = __floats2half2_rn(c0, c1);
                *(__half2*)(Ch + (size_t)(r0 + 8) * Nn + col) = __floats2half2_rn(c2, c3);
            }
        }
    }
}

// ================= small-tile fp16 GEMM (slot path): 128x64 ==================
// EPI 10: +bias -> fp32. EPI 11: relu(+bias) -> fp16.
// EPI 12: +bias +res -> fp32 Cf AND fp16 Ch (new slots).
#define STG64_BYTES ((128 + 64) * HROW * 2)   // 15360
#define H64_DSMEM (3 * STG64_BYTES)           // 46080

template<int EPI>
__global__ void __launch_bounds__(256, 3)
hgemm64_kernel(const __half* __restrict__ A, const __half* __restrict__ Bw,
               int Nn, int K, float* __restrict__ Cf, __half* __restrict__ Ch,
               const float* __restrict__ bias, const float* __restrict__ res) {
    extern __shared__ __align__(16) __half smh[];
    uint32_t smb;
    asm("{ .reg .u64 t; cvta.to.shared.u64 t, %1; cvt.u32.u64 %0, t; }"
        : "=r"(smb) : "l"(smh));

    int tid = threadIdx.x;
    int lane = tid & 31;
    int warp = tid >> 5;
    int grp = lane >> 2, tig = lane & 3;
    int wm = (warp & 3) * 32;
    int wn = (warp >> 2) * 32;
    int bm = blockIdx.y * 128;
    int bn = blockIdx.x * 64;

    const __half* Abm = A + (size_t)bm * K;
    const __half* Bbn = Bw + (size_t)bn * K;

    float acc[2][4][4];
    #pragma unroll
    for (int mt = 0; mt < 2; mt++)
        #pragma unroll
        for (int nt = 0; nt < 4; nt++)
            #pragma unroll
            for (int i = 0; i < 4; i++) acc[mt][nt][i] = 0.f;

    int nit = K / 32;
    #pragma unroll
    for (int s = 0; s < 2; s++) {
        uint32_t base = smb + s * STG64_BYTES;
        #pragma unroll
        for (int j = 0; j < 2; j++) {
            int e = tid + j * 256;
            int r = e >> 2, c = e & 3;
            CP_ASYNC16(base + (r * HROW + c * 8) * 2, Abm + (size_t)r * K + s * 32 + c * 8);
        }
        {
            int r = tid >> 2, c = tid & 3;
            CP_ASYNC16(base + (128 * HROW + r * HROW + c * 8) * 2,
                       Bbn + (size_t)r * K + s * 32 + c * 8);
        }
        CP_COMMIT();
    }

    for (int it = 0; it < nit; it++) {
        CP_WAIT1();
        __syncthreads();
        uint32_t sa = smb + (it % 3) * STG64_BYTES;
        uint32_t sb = sa + 128 * HROW * 2;
        if (it + 2 < nit) {
            uint32_t base = smb + ((it + 2) % 3) * STG64_BYTES;
            #pragma unroll
            for (int j = 0; j < 2; j++) {
                int e = tid + j * 256;
                int r = e >> 2, c = e & 3;
                CP_ASYNC16(base + (r * HROW + c * 8) * 2,
                           Abm + (size_t)r * K + (it + 2) * 32 + c * 8);
            }
            {
                int r = tid >> 2, c = tid & 3;
                CP_ASYNC16(base + (128 * HROW + r * HROW + c * 8) * 2,
                           Bbn + (size_t)r * K + (it + 2) * 32 + c * 8);
            }
        }
        CP_COMMIT();

        #pragma unroll
        for (int kc = 0; kc < 2; kc++) {
            uint32_t afr[2][4], bfr[4][2];
            #pragma unroll
            for (int mt = 0; mt < 2; mt++) {
                uint32_t addr = sa + ((wm + mt * 16 + (lane & 15)) * HROW
                                      + kc * 16 + (lane >> 4) * 8) * 2;
                ldmx4(afr[mt][0], afr[mt][1], afr[mt][2], afr[mt][3], addr);
            }
            #pragma unroll
            for (int ng = 0; ng < 2; ng++) {
                uint32_t r0, r1, r2, r3;
                uint32_t addr = sb + ((wn + ng * 16 + (lane & 15)) * HROW
                                      + kc * 16 + (lane >> 4) * 8) * 2;
                ldmx4(r0, r1, r2, r3, addr);
                bfr[2 * ng][0] = r0; bfr[2 * ng + 1][0] = r1;
                bfr[2 * ng][1] = r2; bfr[2 * ng + 1][1] = r3;
            }
            #pragma unroll
            for (int mt = 0; mt < 2; mt++)
                #pragma unroll
                for (int nt = 0; nt < 4; nt++)
                    mma_f16(acc[mt][nt], afr[mt], bfr[nt]);
        }
    }

    #pragma unroll
    for (int mt = 0; mt < 2; mt++) {
        int r0 = bm + wm + mt * 16 + grp;
        #pragma unroll
        for (int nt = 0; nt < 4; nt++) {
            int col = bn + wn + nt * 8 + tig * 2;
            float b0 = __ldg(&bias[col]), b1 = __ldg(&bias[col + 1]);
            float c0 = acc[mt][nt][0] + b0, c1 = acc[mt][nt][1] + b1;
            float c2 = acc[mt][nt][2] + b0, c3 = acc[mt][nt][3] + b1;
            if (EPI == 10) {
                *(float2*)(Cf + (size_t)r0 * Nn + col)       = make_float2(c0, c1);
                *(float2*)(Cf + (size_t)(r0 + 8) * Nn + col) = make_float2(c2, c3);
            } else if (EPI == 11) {
                c0 = fmaxf(c0, 0.f); c1 = fmaxf(c1, 0.f);
                c2 = fmaxf(c2, 0.f); c3 = fmaxf(c3, 0.f);
                *(__half2*)(Ch + (size_t)r0 * Nn + col)       = __floats2half2_rn(c0, c1);
                *(__half2*)(Ch + (size_t)(r0 + 8) * Nn + col) = __floats2half2_rn(c2, c3);
            } else {   // EPI 12: residual + dual store
                float2 ra = *(const float2*)(res + (size_t)r0 * Nn + col);
                float2 rb = *(const float2*)(res + (size_t)(r0 + 8) * Nn + col);
                c0 += ra.x; c1 += ra.y; c2 += rb.x; c3 += rb.y;
                *(float2*)(Cf + (size_t)r0 * Nn + col)       = make_float2(c0, c1);
                *(float2*)(Cf + (size_t)(r0 + 8) * Nn + col) = make_float2(c2, c3);
                *(__half2*)(Ch + (size_t)r0 * Nn + col)       = __floats2half2_rn(c0, c1);
                *(__half2*)(Ch + (size_t)(r0 + 8) * Nn + col) = __floats2half2_rn(c2, c3);
            }
        }
    }
}

// ================= prep / small kernels =================
__global__ void ln_stats_f2h_kernel(const float* __restrict__ x, __half* __restrict__ xh) {
    int row = blockIdx.x * 8 + (threadIdx.x >> 5);
    int lane = threadIdx.x & 31;
    const float* p = x + (size_t)row * FDIN;
    __half* ph = xh + (size_t)row * FDIN;
    float v[24];
    float s = 0.f, ss = 0.f;
    #pragma unroll
    for (int k = 0; k < 24; k++) {
        v[k] = p[lane + 32 * k];
        s += v[k];
        ss += v[k] * v[k];
    }
    #pragma unroll
    for (int k = 0; k < 24; k++) ph[lane + 32 * k] = __float2half(v[k]);
    #pragma unroll
    for (int o = 16; o; o >>= 1) {
        s  += __shfl_xor_sync(0xffffffffu, s, o);
        ss += __shfl_xor_sync(0xffffffffu, ss, o);
    }
    float m = s * (1.f / FDIN);
    float var = ss * (1.f / FDIN) - m * m;
    if (lane == 0) { g_mean[row] = m; g_rstd[row] = rsqrtf(var + 1e-5f); }
}

__global__ void conv_f2h_kernel(const float* __restrict__ in, __half* __restrict__ out) {
    size_t i = ((size_t)blockIdx.x * 256 + threadIdx.x) * 4;
    float4 v = *(const float4*)(in + i);
    *(__half2*)(out + i)     = __floats2half2_rn(v.x, v.y);
    *(__half2*)(out + i + 2) = __floats2half2_rn(v.z, v.w);
}

__global__ void trans_h_kernel(const float* __restrict__ in, __half* __restrict__ out,
                               int R, int C, const float* __restrict__ scale) {
    __shared__ float t[32][33];
    int bx = blockIdx.x * 32, by = blockIdx.y * 32;
    int x = bx + threadIdx.x;
    #pragma unroll
    for (int j = 0; j < 32; j += 8) {
        int y = by + threadIdx.y + j;
        float s = scale ? scale[y] : 1.f;
        t[threadIdx.y + j][threadIdx.x] = in[(size_t)y * C + x] * s;
    }
    __syncthreads();
    int x2 = by + threadIdx.x;
    #pragma unroll
    for (int j = 0; j < 32; j += 8) {
        int y2 = bx + threadIdx.y + j;
        out[(size_t)y2 * R + x2] = __float2half(t[threadIdx.x][threadIdx.y + j]);
    }
}

__global__ void trans_f_kernel(const float* __restrict__ in, float* __restrict__ out,
                               int R, int C) {
    __shared__ float t[32][33];
    int bx = blockIdx.x * 32, by = blockIdx.y * 32;
    int x = bx + threadIdx.x;
    #pragma unroll
    for (int j = 0; j < 32; j += 8)
        t[threadIdx.y + j][threadIdx.x] = in[(size_t)(by + threadIdx.y + j) * C + x];
    __syncthreads();
    int x2 = by + threadIdx.x;
    #pragma unroll
    for (int j = 0; j < 32; j += 8)
        out[(size_t)(bx + threadIdx.y + j) * R + x2] = t[threadIdx.x][threadIdx.y + j];
}

__global__ void wkv_h_kernel(const float* __restrict__ wk, const float* __restrict__ wv) {
    int i = blockIdx.x * 256 + threadIdx.x;
    g_wkvh[i] = __float2half(wk[i]);
    g_wkvh[DD * DD + i] = __float2half(wv[i]);
}

__global__ void prep_sums_kernel(const float* __restrict__ w1,
                                 const float* __restrict__ g,
                                 const float* __restrict__ b,
                                 const float* __restrict__ b1) {
    __shared__ float r1[8], r2[8];
    int n = blockIdx.x, t = threadIdx.x;
    float s1 = 0.f, s2 = 0.f;
    for (int k = t; k < FDIN; k += 256) {
        float w = w1[(size_t)k * FDIN + n];
        s1 += g[k] * w;
        s2 += b[k] * w;
    }
    #pragma unroll
    for (int o = 16; o; o >>= 1) {
        s1 += __shfl_xor_sync(0xffffffffu, s1, o);
        s2 += __shfl_xor_sync(0xffffffffu, s2, o);
    }
    int w = t >> 5, lane = t & 31;
    if (lane == 0) { r1[w] = s1; r2[w] = s2; }
    __syncthreads();
    if (t == 0) {
        float a = 0.f, c = 0.f;
        #pragma unroll
        for (int i = 0; i < 8; i++) { a += r1[i]; c += r2[i]; }
        g_gB[n] = a;
        g_bBp[n] = c + b1[n];
    }
}

__global__ void slots_init_kernel(const float* __restrict__ si) {
    int i = blockIdx.x * 256 + threadIdx.x;
    float v = si[i & (NS * DD - 1)];
    g_slots[i] = v;
    g_slotsh[i] = __float2half(v);
}

__device__ __forceinline__ float2 block_meanvar_256(float v, float* r1, float* r2) {
    float s = v, q = v * v;
    #pragma unroll
    for (int o = 16; o; o >>= 1) {
        s += __shfl_xor_sync(0xffffffffu, s, o);
        q += __shfl_xor_sync(0xffffffffu, q, o);
    }
    int w = threadIdx.x >> 5, lane = threadIdx.x & 31;
    if (lane == 0) { r1[w] = s; r2[w] = q; }
    __syncthreads();
    float sum = 0.f, sq = 0.f;
    #pragma unroll
    for (int i = 0; i < 8; i++) { sum += r1[i]; sq += r2[i]; }
    __syncthreads();
    float m = sum * (1.f / 256.f);
    float var = sq * (1.f / 256.f) - m * m;
    return make_float2(m, rsqrtf(var + 1e-5f));
}

__global__ void ln256_kernel(const float* __restrict__ x, __half* __restrict__ y,
                             const float* __restrict__ g, const float* __restrict__ b) {
    __shared__ float r1[8], r2[8];
    size_t row = blockIdx.x;
    int tid = threadIdx.x;
    float v = x[row * DD + tid];
    float2 mv = block_meanvar_256(v, r1, r2);
    y[row * DD + tid] = __float2half((v - mv.x) * mv.y * g[tid] + b[tid]);
}

__global__ void qproj_kernel(const float* __restrict__ ng, const float* __restrict__ nb) {
    __shared__ float sln[DD];
    __shared__ float r1[8], r2[8];
    int row = blockIdx.x, tid = threadIdx.x;
    float v = g_slots[row * DD + tid];
    float2 mv = block_meanvar_256(v, r1, r2);
    sln[tid] = (v - mv.x) * mv.y * ng[tid] + nb[tid];
    g_U[row * DD + tid] = 0.f;
    if (tid == 0) g_rowsum[row] = 0.f;
    __syncthreads();
    float acc = 0.f;
    #pragma unroll 8
    for (int d = 0; d < DD; d++) acc += sln[d] * g_wqT[d * DD + tid];
    g_q[row * DD + tid] = acc;
}

__global__ void __launch_bounds__(256)
attn_kernel() {
    int b = blockIdx.x, ch = blockIdx.y;
    int warp = threadIdx.x >> 5, lane = threadIdx.x & 31;
    __shared__ float qs[NS * DD];
    __shared__ float dots[8][NS];
    __shared__ float aw[8][NS];
    for (int i = threadIdx.x; i < NS * DD; i += 256) qs[i] = g_q[b * NS * DD + i];
    __syncthreads();
    float qreg[8];
    #pragma unroll
    for (int k = 0; k < 4; k++) {
        qreg[2 * k]     = qs[warp * DD + 2 * (lane + 32 * k)];
        qreg[2 * k + 1] = qs[warp * DD + 2 * (lane + 32 * k) + 1];
    }
    float2 uacc[4];
    #pragma unroll
    for (int k = 0; k < 4; k++) uacc[k] = make_float2(0.f, 0.f);
    float rsum = 0.f;
    const float scale = 0.0625f;
    int t0 = ch * 256;
    const __half* kvb = g_kvh + ((size_t)b * NTOK + t0) * 512;

    for (int tt = 0; tt < 256; tt += 8) {
        #pragma unroll
        for (int u = 0; u < 8; u++) {
            const __half2* kp = (const __half2*)(kvb + (size_t)(tt + u) * 512);
            float d = 0.f;
            #pragma unroll
            for (int k = 0; k < 4; k++) {
                float2 kv2 = __half22float2(kp[lane + 32 * k]);
                d += qreg[2 * k] * kv2.x + qreg[2 * k + 1] * kv2.y;
            }
            #pragma unroll
            for (int o = 16; o; o >>= 1) d += __shfl_xor_sync(0xffffffffu, d, o);
            if (lane == 0) dots[u][warp] = d * scale;
        }
        __syncthreads();
        if (threadIdx.x < 64) {
            int u = threadIdx.x >> 3, s = threadIdx.x & 7;
            float mx = -1e30f;
            #pragma unroll
            for (int s2 = 0; s2 < NS; s2++) mx = fmaxf(mx, dots[u][s2]);
            float e = expf(dots[u][s] - mx);
            float sum = e;
            #pragma unroll
            for (int o = 1; o < 8; o <<= 1) sum += __shfl_xor_sync(0xffffffffu, sum, o);
            aw[u][s] = e / sum + 1e-8f;
        }
        __syncthreads();
        #pragma unroll
        for (int u = 0; u < 8; u++) {
            float a = aw[u][warp];
            const __half2* vp = (const __half2*)(kvb + (size_t)(tt + u) * 512 + 256);
            #pragma unroll
            for (int k = 0; k < 4; k++) {
                float2 vv = __half22float2(vp[lane + 32 * k]);
                uacc[k].x += a * vv.x;
                uacc[k].y += a * vv.y;
            }
            rsum += a;
        }
        __syncthreads();
    }
    float* up = g_U + (b * NS + warp) * DD;
    #pragma unroll
    for (int k = 0; k < 4; k++) {
        atomicAdd(&up[2 * (lane + 32 * k)], uacc[k].x);
        atomicAdd(&up[2 * (lane + 32 * k) + 1], uacc[k].y);
    }
    if (lane == 0) atomicAdd(&g_rowsum[b * NS + warp], rsum);
}

// updh = (half)(U / rowsum)
__global__ void updfin_kernel() {
    int i = blockIdx.x * 256 + threadIdx.x;
    g_updh[i] = __float2half(g_U[i] / g_rowsum[i >> 8]);
}

// pointwise GRU + pre-LN: h = (1-z)n + z*slots_prev;  mlpin = LN(h)
__global__ void gru_pw_kernel(const float* __restrict__ mlng,
                              const float* __restrict__ mlnb) {
    __shared__ float r1[8], r2[8];
    int row = blockIdx.x, tid = threadIdx.x;
    const float* gi = g_gi + row * 3 * DD;
    const float* gh = g_gh + row * 3 * DD;
    float ir = gi[tid], iz = gi[tid + 256], inn = gi[tid + 512];
    float hr = gh[tid], hz = gh[tid + 256], hn = gh[tid + 512];
    float sprev = g_slots[row * DD + tid];
    float r = 1.f / (1.f + expf(-(ir + hr)));
    float z = 1.f / (1.f + expf(-(iz + hz)));
    float n = tanhf(inn + r * hn);
    float h = (1.f - z) * n + z * sprev;
    g_hbuf[row * DD + tid] = h;
    float2 mv = block_meanvar_256(h, r1, r2);
    g_mlpinh[row * DD + tid] = __float2half((h - mv.x) * mv.y * mlng[tid] + mlnb[tid]);
}

// ================= launch =================
extern "C" void kernel_launch(void* const* d_in, const int* in_sizes, int n_in,
                              void* d_out, int out_size) {
    const float* inputs   = (const float*)d_in[0];
    const float* slots_in = (const float*)d_in[1];
    const float* ln1g = (const float*)d_in[2];
    const float* ln1b = (const float*)d_in[3];
    const float* w1   = (const float*)d_in[4];
    const float* b1   = (const float*)d_in[5];
    const float* w2   = (const float*)d_in[6];
    const float* b2   = (const float*)d_in[7];
    const float* ln2g = (const float*)d_in[8];
    const float* ln2b = (const float*)d_in[9];
    const float* wq   = (const float*)d_in[10];
    const float* wk   = (const float*)d_in[11];
    const float* wv   = (const float*)d_in[12];
    const float* normg = (const float*)d_in[13];
    const float* normb = (const float*)d_in[14];
    const float* gwih = (const float*)d_in[15];
    const float* gwhh = (const float*)d_in[16];
    const float* gbih = (const float*)d_in[17];
    const float* gbhh = (const float*)d_in[18];
    const float* mlng = (const float*)d_in[19];
    const float* mlnb = (const float*)d_in[20];
    const float* mw1  = (const float*)d_in[21];
    const float* mb1  = (const float*)d_in[22];
    const float* mw2  = (const float*)d_in[23];
    const float* mb2  = (const float*)d_in[24];
    float* out = (float*)d_out;

    __half *p_inh, *p_h1h, *p_featsh, *p_kvh, *p_w1h, *p_w2h, *p_wkvh;
    __half *p_wihh, *p_whhh, *p_mw1h, *p_mw2h, *p_updh, *p_mlpinh, *p_hhh, *p_slotsh;
    float *p_h2, *p_wqT, *p_slots, *p_gi, *p_gh, *p_hbuf;
    cudaGetSymbolAddress((void**)&p_inh,    g_inh);
    cudaGetSymbolAddress((void**)&p_h1h,    g_h1h);
    cudaGetSymbolAddress((void**)&p_featsh, g_featsh);
    cudaGetSymbolAddress((void**)&p_kvh,    g_kvh);
    cudaGetSymbolAddress((void**)&p_w1h,    g_w1h);
    cudaGetSymbolAddress((void**)&p_w2h,    g_w2h);
    cudaGetSymbolAddress((void**)&p_wkvh,   g_wkvh);
    cudaGetSymbolAddress((void**)&p_wihh,   g_wihh);
    cudaGetSymbolAddress((void**)&p_whhh,   g_whhh);
    cudaGetSymbolAddress((void**)&p_mw1h,   g_mw1h);
    cudaGetSymbolAddress((void**)&p_mw2h,   g_mw2h);
    cudaGetSymbolAddress((void**)&p_updh,   g_updh);
    cudaGetSymbolAddress((void**)&p_mlpinh, g_mlpinh);
    cudaGetSymbolAddress((void**)&p_hhh,    g_hhh);
    cudaGetSymbolAddress((void**)&p_slotsh, g_slotsh);
    cudaGetSymbolAddress((void**)&p_h2,     g_h2);
    cudaGetSymbolAddress((void**)&p_wqT,    g_wqT);
    cudaGetSymbolAddress((void**)&p_slots,  g_slots);
    cudaGetSymbolAddress((void**)&p_gi,     g_gi);
    cudaGetSymbolAddress((void**)&p_gh,     g_gh);
    cudaGetSymbolAddress((void**)&p_hbuf,   g_hbuf);

    // REQUIRED: 61,440 B dynamic smem exceeds the 48 KB default opt-in
    cudaFuncSetAttribute(hgemm128_kernel<1>, cudaFuncAttributeMaxDynamicSharedMemorySize, H128_DSMEM);
    cudaFuncSetAttribute(hgemm128_kernel<2>, cudaFuncAttributeMaxDynamicSharedMemorySize, H128_DSMEM);
    cudaFuncSetAttribute(hgemm128_kernel<3>, cudaFuncAttributeMaxDynamicSharedMemorySize, H128_DSMEM);

    dim3 tb(32, 8);
    // 0: fused LN stats + fp16 conversion of inputs
    ln_stats_f2h_kernel<<<MROWS / 8, 256>>>(inputs, p_inh);
    // 1: w1 -> [N][K] fp16 scaled by ln1g
    trans_h_kernel<<<dim3(FDIN / 32, FDIN / 32), tb>>>(w1, p_w1h, FDIN, FDIN, ln1g);
    // 2: epilogue fold vectors
    prep_sums_kernel<<<FDIN, 256>>>(w1, ln1g, ln1b, b1);
    // 3: GEMM1 (128x128 tile)   << ncu window
    hgemm128_kernel<1><<<dim3(FDIN / 128, MROWS / 128), 256, H128_DSMEM>>>(
        p_inh, p_w1h, FDIN, FDIN, nullptr, p_h1h, nullptr);
    // 4: w2 -> [N][K] fp16
    trans_h_kernel<<<dim3(DD / 32, FDIN / 32), tb>>>(w2, p_w2h, FDIN, DD, nullptr);
    // 5: GEMM2 h2 = h1 @ w2 + b2 -> fp32
    hgemm128_kernel<2><<<dim3(DD / 128, MROWS / 128), 256, H128_DSMEM>>>(
        p_h1h, p_w2h, DD, FDIN, p_h2, nullptr, b2);
    // 6: feats = LN(h2) -> fp16
    ln256_kernel<<<MROWS, 256>>>(p_h2, p_featsh, ln2g, ln2b);
    // 7: wk|wv -> fp16
    wkv_h_kernel<<<DD * DD / 256, 256>>>(wk, wv);
    // 8: KV GEMM -> fp16
    hgemm128_kernel<3><<<dim3(2 * DD / 128, MROWS / 128), 256, H128_DSMEM>>>(
        p_featsh, p_wkvh, 2 * DD, DD, nullptr, p_kvh, nullptr);

    // slot-path weight prep
    trans_f_kernel<<<dim3(DD / 32, DD / 32), tb>>>(wq, p_wqT, DD, DD);
    conv_f2h_kernel<<<3 * DD * DD / 1024, 256>>>(gwih, p_wihh);
    conv_f2h_kernel<<<3 * DD * DD / 1024, 256>>>(gwhh, p_whhh);
    trans_h_kernel<<<dim3(4 * DD / 32, DD / 32), tb>>>(mw1, p_mw1h, DD, 4 * DD, nullptr);
    trans_h_kernel<<<dim3(DD / 32, 4 * DD / 32), tb>>>(mw2, p_mw2h, 4 * DD, DD, nullptr);
    slots_init_kernel<<<SROWS * DD / 256, 256>>>(slots_in);

    for (int t = 0; t < ITERS; t++) {
        qproj_kernel<<<SROWS, 256>>>(normg, normb);
        attn_kernel<<<dim3(BNUM, 16), 256>>>();
        updfin_kernel<<<SROWS, 256>>>();
        // gi = updh @ wih^T + bih   [768 x 768, K=256]
        hgemm64_kernel<10><<<dim3(3 * DD / 64, SROWS / 128), 256, H64_DSMEM>>>(
            p_updh, p_wihh, 3 * DD, DD, p_gi, nullptr, gbih, nullptr);
        // gh = slotsh @ whh^T + bhh
        hgemm64_kernel<10><<<dim3(3 * DD / 64, SROWS / 128), 256, H64_DSMEM>>>(
            p_slotsh, p_whhh, 3 * DD, DD, p_gh, nullptr, gbhh, nullptr);
        // pointwise GRU + LN
        gru_pw_kernel<<<SROWS, 256>>>(mlng, mlnb);
        // hh = relu(mlpin @ mw1 + mb1)   [768 x 1024, K=256]
        hgemm64_kernel<11><<<dim3(4 * DD / 64, SROWS / 128), 256, H64_DSMEM>>>(
            p_mlpinh, p_mw1h, 4 * DD, DD, nullptr, p_hhh, mb1, nullptr);
        // slots = h + hh @ mw2 + mb2   [768 x 256, K=1024]
        float* dst = (t == ITERS - 1) ? out : p_slots;
        hgemm64_kernel<12><<<dim3(DD / 64, SROWS / 128), 256, H64_DSMEM>>>(
            p_hhh, p_mw2h, DD, 4 * DD, dst, p_slotsh, mb2, p_hbuf);
    }
}

// round 11
// speedup vs baseline: 2.6902x; 1.0798x over previous
#include <cuda_runtime.h>
#include <cuda_fp16.h>
#include <math.h>
#include <stdint.h>

#define BNUM 32
#define NTOK 4096
#define FDIN 768
#define DD 256
#define NS 8
#define MROWS (BNUM * NTOK)   // 131072
#define SROWS (BNUM * NS)     // 768 slot rows
#define ITERS 3

// ---------------- scratch (static __device__ — no allocation) ----------------
__device__ float  g_mean[MROWS];
__device__ float  g_rstd[MROWS];
__device__ __half g_inh[(size_t)MROWS * FDIN];
__device__ __half g_h1h[(size_t)MROWS * FDIN];
__device__ float  g_h2[(size_t)MROWS * DD];
__device__ __half g_featsh[(size_t)MROWS * DD];
__device__ __half g_kvh[(size_t)MROWS * 2 * DD];  // [row][512]: keys | vals fp16
__device__ __half g_w1h[FDIN * FDIN];             // [N=768][K=768], scaled by ln1g
__device__ float  g_gB[FDIN];
__device__ float  g_bBp[FDIN];
__device__ __half g_w2h[DD * FDIN];               // [N=256][K=768]
__device__ __half g_wkvh[2 * DD * DD];            // [N=512][K=256]
__device__ float  g_wqT[DD * DD];
// GRU / MLP weights fp16 (K-major)
__device__ __half g_wihh[3 * DD * DD];            // [768][256] as-is
__device__ __half g_whhh[3 * DD * DD];            // [768][256] as-is
__device__ __half g_mw1h[4 * DD * DD];            // [1024][256] (transposed)
__device__ __half g_mw2h[DD * 4 * DD];            // [256][1024] (transposed)
// iteration state
__device__ float  g_slots[SROWS * DD];
__device__ __half g_slotsh[SROWS * DD];
__device__ float  g_q[SROWS * DD];
__device__ float  g_U[SROWS * DD];
__device__ float  g_rowsum[SROWS];
__device__ __half g_updh[SROWS * DD];
__device__ float  g_gi[SROWS * 3 * DD];
__device__ float  g_gh[SROWS * 3 * DD];
__device__ float  g_hbuf[SROWS * DD];
__device__ __half g_mlpinh[SROWS * DD];
__device__ __half g_hhh[SROWS * 4 * DD];

// ================= asm helpers =================
#define CP_ASYNC16(dst, src) \
    asm volatile("cp.async.cg.shared.global [%0], [%1], 16;\n" :: "r"(dst), "l"(src))
#define CP_COMMIT() asm volatile("cp.async.commit_group;\n" ::: "memory")
#define CP_WAIT1()  asm volatile("cp.async.wait_group 1;\n" ::: "memory")

__device__ __forceinline__ void ldmx4(uint32_t& r0, uint32_t& r1, uint32_t& r2,
                                      uint32_t& r3, uint32_t addr) {
    asm volatile("ldmatrix.sync.aligned.m8n8.x4.shared.b16 {%0,%1,%2,%3}, [%4];"
                 : "=r"(r0), "=r"(r1), "=r"(r2), "=r"(r3) : "r"(addr));
}

__device__ __forceinline__ void mma_f16(float* c, const uint32_t* a, const uint32_t* b) {
    asm volatile(
        "mma.sync.aligned.m16n8k16.row.col.f32.f16.f16.f32 "
        "{%0,%1,%2,%3}, {%4,%5,%6,%7}, {%8,%9}, {%0,%1,%2,%3};"
        : "+f"(c[0]), "+f"(c[1]), "+f"(c[2]), "+f"(c[3])
        : "r"(a[0]), "r"(a[1]), "r"(a[2]), "r"(a[3]), "r"(b[0]), "r"(b[1]));
}

// ================= big-tile fp16 GEMM (feature path): 128x128, BK=64 ========
// 8 warps (4x2), warp tile 32x64, 3-stage cp.async, 12 barriers for K=768.
// EPI 1: LN-fold+relu -> fp16. EPI 2: +bias -> fp32. EPI 3: raw -> fp16.
#define HR128 72                          // 64 + 8 pad halves per smem row
#define STG128_BYTES (256 * HR128 * 2)    // 36864
#define H128_DSMEM (3 * STG128_BYTES)     // 110592

template<int EPI>
__global__ void __launch_bounds__(256)
hgemm128_kernel(const __half* __restrict__ A, const __half* __restrict__ Bw,
                int Nn, int K, float* __restrict__ Cf, __half* __restrict__ Ch,
                const float* __restrict__ bias) {
    extern __shared__ __align__(16) __half smh[];
    uint32_t smb;
    asm("{ .reg .u64 t; cvta.to.shared.u64 t, %1; cvt.u32.u64 %0, t; }"
        : "=r"(smb) : "l"(smh));

    int tid = threadIdx.x;
    int lane = tid & 31;
    int warp = tid >> 5;
    int grp = lane >> 2, tig = lane & 3;
    int wm = (warp & 3) * 32;
    int wn = (warp >> 2) * 64;
    int bm = blockIdx.y * 128;
    int bn = blockIdx.x * 128;

    const __half* Abm = A + (size_t)bm * K;
    const __half* Bbn = Bw + (size_t)bn * K;

    float acc[2][8][4];
    #pragma unroll
    for (int mt = 0; mt < 2; mt++)
        #pragma unroll
        for (int nt = 0; nt < 8; nt++)
            #pragma unroll
            for (int i = 0; i < 4; i++) acc[mt][nt][i] = 0.f;

    int nit = K / 64;
    // prologue: stages 0,1  (per stage: A 1024 chunks + B 1024 chunks, 4 each/thread)
    #pragma unroll
    for (int s = 0; s < 2; s++) {
        uint32_t base = smb + s * STG128_BYTES;
        #pragma unroll
        for (int j = 0; j < 4; j++) {
            int e = tid + j * 256;
            int r = e >> 3, c = e & 7;
            CP_ASYNC16(base + (r * HR128 + c * 8) * 2,
                       Abm + (size_t)r * K + s * 64 + c * 8);
            CP_ASYNC16(base + (128 * HR128 + r * HR128 + c * 8) * 2,
                       Bbn + (size_t)r * K + s * 64 + c * 8);
        }
        CP_COMMIT();
    }

    for (int it = 0; it < nit; it++) {
        CP_WAIT1();
        __syncthreads();
        uint32_t sa = smb + (it % 3) * STG128_BYTES;
        uint32_t sb = sa + 128 * HR128 * 2;
        if (it + 2 < nit) {
            uint32_t base = smb + ((it + 2) % 3) * STG128_BYTES;
            #pragma unroll
            for (int j = 0; j < 4; j++) {
                int e = tid + j * 256;
                int r = e >> 3, c = e & 7;
                CP_ASYNC16(base + (r * HR128 + c * 8) * 2,
                           Abm + (size_t)r * K + (it + 2) * 64 + c * 8);
                CP_ASYNC16(base + (128 * HR128 + r * HR128 + c * 8) * 2,
                           Bbn + (size_t)r * K + (it + 2) * 64 + c * 8);
            }
        }
        CP_COMMIT();

        #pragma unroll
        for (int kc = 0; kc < 4; kc++) {
            uint32_t afr[2][4], bfr[8][2];
            #pragma unroll
            for (int mt = 0; mt < 2; mt++) {
                uint32_t addr = sa + ((wm + mt * 16 + (lane & 15)) * HR128
                                      + kc * 16 + (lane >> 4) * 8) * 2;
                ldmx4(afr[mt][0], afr[mt][1], afr[mt][2], afr[mt][3], addr);
            }
            #pragma unroll
            for (int ng = 0; ng < 4; ng++) {
                uint32_t r0, r1, r2, r3;
                uint32_t addr = sb + ((wn + ng * 16 + (lane & 15)) * HR128
                                      + kc * 16 + (lane >> 4) * 8) * 2;
                ldmx4(r0, r1, r2, r3, addr);
                bfr[2 * ng][0] = r0; bfr[2 * ng + 1][0] = r1;
                bfr[2 * ng][1] = r2; bfr[2 * ng + 1][1] = r3;
            }
            #pragma unroll
            for (int mt = 0; mt < 2; mt++)
                #pragma unroll
                for (int nt = 0; nt < 8; nt++)
                    mma_f16(acc[mt][nt], afr[mt], bfr[nt]);
        }
    }

    #pragma unroll
    for (int mt = 0; mt < 2; mt++) {
        int r0 = bm + wm + mt * 16 + grp;
        float mu0 = 0.f, rs0 = 0.f, mu1 = 0.f, rs1 = 0.f;
        if (EPI == 1) {
            mu0 = g_mean[r0]; rs0 = g_rstd[r0];
            mu1 = g_mean[r0 + 8]; rs1 = g_rstd[r0 + 8];
        }
        #pragma unroll
        for (int nt = 0; nt < 8; nt++) {
            int col = bn + wn + nt * 8 + tig * 2;
            float c0 = acc[mt][nt][0], c1 = acc[mt][nt][1];
            float c2 = acc[mt][nt][2], c3 = acc[mt][nt][3];
            if (EPI == 1) {
                float gb0 = __ldg(&g_gB[col]), gb1 = __ldg(&g_gB[col + 1]);
                float bb0 = __ldg(&g_bBp[col]), bb1 = __ldg(&g_bBp[col + 1]);
                c0 = fmaxf(c0 * rs0 - mu0 * rs0 * gb0 + bb0, 0.f);
                c1 = fmaxf(c1 * rs0 - mu0 * rs0 * gb1 + bb1, 0.f);
                c2 = fmaxf(c2 * rs1 - mu1 * rs1 * gb0 + bb0, 0.f);
                c3 = fmaxf(c3 * rs1 - mu1 * rs1 * gb1 + bb1, 0.f);
                *(__half2*)(Ch + (size_t)r0 * Nn + col) = __floats2half2_rn(c0, c1);
                *(__half2*)(Ch + (size_t)(r0 + 8) * Nn + col) = __floats2half2_rn(c2, c3);
            } else if (EPI == 2) {
                float b0 = __ldg(&bias[col]), b1 = __ldg(&bias[col + 1]);
                *(float2*)(Cf + (size_t)r0 * Nn + col)       = make_float2(c0 + b0, c1 + b1);
                *(float2*)(Cf + (size_t)(r0 + 8) * Nn + col) = make_float2(c2 + b0, c3 + b1);
            } else {
                *(__half2*)(Ch + (size_t)r0 * Nn + col)       = __floats2half2_rn(c0, c1);
                *(__half2*)(Ch + (size_t)(r0 + 8) * Nn + col) = __floats2half2_rn(c2, c3);
            }
        }
    }
}

// ================= small-tile fp16 GEMM (slot path): 128x64, BK=32 ===========
// EPI 10: +bias -> fp32. EPI 11: relu(+bias) -> fp16.
// EPI 12: +bias +res -> fp32 Cf AND fp16 Ch (new slots).
#define HROW 40
#define STG64_BYTES ((128 + 64) * HROW * 2)   // 15360
#define H64_DSMEM (3 * STG64_BYTES)           // 46080

template<int EPI>
__global__ void __launch_bounds__(256, 3)
hgemm64_kernel(const __half* __restrict__ A, const __half* __restrict__ Bw,
               int Nn, int K, float* __restrict__ Cf, __half* __restrict__ Ch,
               const float* __restrict__ bias, const float* __restrict__ res) {
    extern __shared__ __align__(16) __half smh[];
    uint32_t smb;
    asm("{ .reg .u64 t; cvta.to.shared.u64 t, %1; cvt.u32.u64 %0, t; }"
        : "=r"(smb) : "l"(smh));

    int tid = threadIdx.x;
    int lane = tid & 31;
    int warp = tid >> 5;
    int grp = lane >> 2, tig = lane & 3;
    int wm = (warp & 3) * 32;
    int wn = (warp >> 2) * 32;
    int bm = blockIdx.y * 128;
    int bn = blockIdx.x * 64;

    const __half* Abm = A + (size_t)bm * K;
    const __half* Bbn = Bw + (size_t)bn * K;

    float acc[2][4][4];
    #pragma unroll
    for (int mt = 0; mt < 2; mt++)
        #pragma unroll
        for (int nt = 0; nt < 4; nt++)
            #pragma unroll
            for (int i = 0; i < 4; i++) acc[mt][nt][i] = 0.f;

    int nit = K / 32;
    #pragma unroll
    for (int s = 0; s < 2; s++) {
        uint32_t base = smb + s * STG64_BYTES;
        #pragma unroll
        for (int j = 0; j < 2; j++) {
            int e = tid + j * 256;
            int r = e >> 2, c = e & 3;
            CP_ASYNC16(base + (r * HROW + c * 8) * 2, Abm + (size_t)r * K + s * 32 + c * 8);
        }
        {
            int r = tid >> 2, c = tid & 3;
            CP_ASYNC16(base + (128 * HROW + r * HROW + c * 8) * 2,
                       Bbn + (size_t)r * K + s * 32 + c * 8);
        }
        CP_COMMIT();
    }

    for (int it = 0; it < nit; it++) {
        CP_WAIT1();
        __syncthreads();
        uint32_t sa = smb + (it % 3) * STG64_BYTES;
        uint32_t sb = sa + 128 * HROW * 2;
        if (it + 2 < nit) {
            uint32_t base = smb + ((it + 2) % 3) * STG64_BYTES;
            #pragma unroll
            for (int j = 0; j < 2; j++) {
                int e = tid + j * 256;
                int r = e >> 2, c = e & 3;
                CP_ASYNC16(base + (r * HROW + c * 8) * 2,
                           Abm + (size_t)r * K + (it + 2) * 32 + c * 8);
            }
            {
                int r = tid >> 2, c = tid & 3;
                CP_ASYNC16(base + (128 * HROW + r * HROW + c * 8) * 2,
                           Bbn + (size_t)r * K + (it + 2) * 32 + c * 8);
            }
        }
        CP_COMMIT();

        #pragma unroll
        for (int kc = 0; kc < 2; kc++) {
            uint32_t afr[2][4], bfr[4][2];
            #pragma unroll
            for (int mt = 0; mt < 2; mt++) {
                uint32_t addr = sa + ((wm + mt * 16 + (lane & 15)) * HROW
                                      + kc * 16 + (lane >> 4) * 8) * 2;
                ldmx4(afr[mt][0], afr[mt][1], afr[mt][2], afr[mt][3], addr);
            }
            #pragma unroll
            for (int ng = 0; ng < 2; ng++) {
                uint32_t r0, r1, r2, r3;
                uint32_t addr = sb + ((wn + ng * 16 + (lane & 15)) * HROW
                                      + kc * 16 + (lane >> 4) * 8) * 2;
                ldmx4(r0, r1, r2, r3, addr);
                bfr[2 * ng][0] = r0; bfr[2 * ng + 1][0] = r1;
                bfr[2 * ng][1] = r2; bfr[2 * ng + 1][1] = r3;
            }
            #pragma unroll
            for (int mt = 0; mt < 2; mt++)
                #pragma unroll
                for (int nt = 0; nt < 4; nt++)
                    mma_f16(acc[mt][nt], afr[mt], bfr[nt]);
        }
    }

    #pragma unroll
    for (int mt = 0; mt < 2; mt++) {
        int r0 = bm + wm + mt * 16 + grp;
        #pragma unroll
        for (int nt = 0; nt < 4; nt++) {
            int col = bn + wn + nt * 8 + tig * 2;
            float b0 = __ldg(&bias[col]), b1 = __ldg(&bias[col + 1]);
            float c0 = acc[mt][nt][0] + b0, c1 = acc[mt][nt][1] + b1;
            float c2 = acc[mt][nt][2] + b0, c3 = acc[mt][nt][3] + b1;
            if (EPI == 10) {
                *(float2*)(Cf + (size_t)r0 * Nn + col)       = make_float2(c0, c1);
                *(float2*)(Cf + (size_t)(r0 + 8) * Nn + col) = make_float2(c2, c3);
            } else if (EPI == 11) {
                c0 = fmaxf(c0, 0.f); c1 = fmaxf(c1, 0.f);
                c2 = fmaxf(c2, 0.f); c3 = fmaxf(c3, 0.f);
                *(__half2*)(Ch + (size_t)r0 * Nn + col)       = __floats2half2_rn(c0, c1);
                *(__half2*)(Ch + (size_t)(r0 + 8) * Nn + col) = __floats2half2_rn(c2, c3);
            } else {   // EPI 12: residual + dual store
                float2 ra = *(const float2*)(res + (size_t)r0 * Nn + col);
                float2 rb = *(const float2*)(res + (size_t)(r0 + 8) * Nn + col);
                c0 += ra.x; c1 += ra.y; c2 += rb.x; c3 += rb.y;
                *(float2*)(Cf + (size_t)r0 * Nn + col)       = make_float2(c0, c1);
                *(float2*)(Cf + (size_t)(r0 + 8) * Nn + col) = make_float2(c2, c3);
                *(__half2*)(Ch + (size_t)r0 * Nn + col)       = __floats2half2_rn(c0, c1);
                *(__half2*)(Ch + (size_t)(r0 + 8) * Nn + col) = __floats2half2_rn(c2, c3);
            }
        }
    }
}

// ================= prep / small kernels =================
__global__ void ln_stats_f2h_kernel(const float* __restrict__ x, __half* __restrict__ xh) {
    int row = blockIdx.x * 8 + (threadIdx.x >> 5);
    int lane = threadIdx.x & 31;
    const float* p = x + (size_t)row * FDIN;
    __half* ph = xh + (size_t)row * FDIN;
    float v[24];
    float s = 0.f, ss = 0.f;
    #pragma unroll
    for (int k = 0; k < 24; k++) {
        v[k] = p[lane + 32 * k];
        s += v[k];
        ss += v[k] * v[k];
    }
    #pragma unroll
    for (int k = 0; k < 24; k++) ph[lane + 32 * k] = __float2half(v[k]);
    #pragma unroll
    for (int o = 16; o; o >>= 1) {
        s  += __shfl_xor_sync(0xffffffffu, s, o);
        ss += __shfl_xor_sync(0xffffffffu, ss, o);
    }
    float m = s * (1.f / FDIN);
    float var = ss * (1.f / FDIN) - m * m;
    if (lane == 0) { g_mean[row] = m; g_rstd[row] = rsqrtf(var + 1e-5f); }
}

__global__ void conv_f2h_kernel(const float* __restrict__ in, __half* __restrict__ out) {
    size_t i = ((size_t)blockIdx.x * 256 + threadIdx.x) * 4;
    float4 v = *(const float4*)(in + i);
    *(__half2*)(out + i)     = __floats2half2_rn(v.x, v.y);
    *(__half2*)(out + i + 2) = __floats2half2_rn(v.z, v.w);
}

__global__ void trans_h_kernel(const float* __restrict__ in, __half* __restrict__ out,
                               int R, int C, const float* __restrict__ scale) {
    __shared__ float t[32][33];
    int bx = blockIdx.x * 32, by = blockIdx.y * 32;
    int x = bx + threadIdx.x;
    #pragma unroll
    for (int j = 0; j < 32; j += 8) {
        int y = by + threadIdx.y + j;
        float s = scale ? scale[y] : 1.f;
        t[threadIdx.y + j][threadIdx.x] = in[(size_t)y * C + x] * s;
    }
    __syncthreads();
    int x2 = by + threadIdx.x;
    #pragma unroll
    for (int j = 0; j < 32; j += 8) {
        int y2 = bx + threadIdx.y + j;
        out[(size_t)y2 * R + x2] = __float2half(t[threadIdx.x][threadIdx.y + j]);
    }
}

__global__ void trans_f_kernel(const float* __restrict__ in, float* __restrict__ out,
                               int R, int C) {
    __shared__ float t[32][33];
    int bx = blockIdx.x * 32, by = blockIdx.y * 32;
    int x = bx + threadIdx.x;
    #pragma unroll
    for (int j = 0; j < 32; j += 8)
        t[threadIdx.y + j][threadIdx.x] = in[(size_t)(by + threadIdx.y + j) * C + x];
    __syncthreads();
    int x2 = by + threadIdx.x;
    #pragma unroll
    for (int j = 0; j < 32; j += 8)
        out[(size_t)(bx + threadIdx.y + j) * R + x2] = t[threadIdx.x][threadIdx.y + j];
}

__global__ void wkv_h_kernel(const float* __restrict__ wk, const float* __restrict__ wv) {
    int i = blockIdx.x * 256 + threadIdx.x;
    g_wkvh[i] = __float2half(wk[i]);
    g_wkvh[DD * DD + i] = __float2half(wv[i]);
}

__global__ void prep_sums_kernel(const float* __restrict__ w1,
                                 const float* __restrict__ g,
                                 const float* __restrict__ b,
                                 const float* __restrict__ b1) {
    __shared__ float r1[8], r2[8];
    int n = blockIdx.x, t = threadIdx.x;
    float s1 = 0.f, s2 = 0.f;
    for (int k = t; k < FDIN; k += 256) {
        float w = w1[(size_t)k * FDIN + n];
        s1 += g[k] * w;
        s2 += b[k] * w;
    }
    #pragma unroll
    for (int o = 16; o; o >>= 1) {
        s1 += __shfl_xor_sync(0xffffffffu, s1, o);
        s2 += __shfl_xor_sync(0xffffffffu, s2, o);
    }
    int w = t >> 5, lane = t & 31;
    if (lane == 0) { r1[w] = s1; r2[w] = s2; }
    __syncthreads();
    if (t == 0) {
        float a = 0.f, c = 0.f;
        #pragma unroll
        for (int i = 0; i < 8; i++) { a += r1[i]; c += r2[i]; }
        g_gB[n] = a;
        g_bBp[n] = c + b1[n];
    }
}

__global__ void slots_init_kernel(const float* __restrict__ si) {
    int i = blockIdx.x * 256 + threadIdx.x;
    float v = si[i & (NS * DD - 1)];
    g_slots[i] = v;
    g_slotsh[i] = __float2half(v);
}

__device__ __forceinline__ float2 block_meanvar_256(float v, float* r1, float* r2) {
    float s = v, q = v * v;
    #pragma unroll
    for (int o = 16; o; o >>= 1) {
        s += __shfl_xor_sync(0xffffffffu, s, o);
        q += __shfl_xor_sync(0xffffffffu, q, o);
    }
    int w = threadIdx.x >> 5, lane = threadIdx.x & 31;
    if (lane == 0) { r1[w] = s; r2[w] = q; }
    __syncthreads();
    float sum = 0.f, sq = 0.f;
    #pragma unroll
    for (int i = 0; i < 8; i++) { sum += r1[i]; sq += r2[i]; }
    __syncthreads();
    float m = sum * (1.f / 256.f);
    float var = sq * (1.f / 256.f) - m * m;
    return make_float2(m, rsqrtf(var + 1e-5f));
}

// feats = (half) LN(h2): warp per row, 8 rows/block (block-overhead fix)
__global__ void ln256_kernel(const float* __restrict__ x, __half* __restrict__ y,
                             const float* __restrict__ g, const float* __restrict__ b) {
    size_t row = (size_t)blockIdx.x * 8 + (threadIdx.x >> 5);
    int lane = threadIdx.x & 31;
    const float* p = x + row * DD;
    float4 a = *(const float4*)(p + lane * 4);
    float4 c = *(const float4*)(p + 128 + lane * 4);
    float s = a.x + a.y + a.z + a.w + c.x + c.y + c.z + c.w;
    float q = a.x * a.x + a.y * a.y + a.z * a.z + a.w * a.w
            + c.x * c.x + c.y * c.y + c.z * c.z + c.w * c.w;
    #pragma unroll
    for (int o = 16; o; o >>= 1) {
        s += __shfl_xor_sync(0xffffffffu, s, o);
        q += __shfl_xor_sync(0xffffffffu, q, o);
    }
    float m = s * (1.f / 256.f);
    float rs = rsqrtf(q * (1.f / 256.f) - m * m + 1e-5f);
    int c0 = lane * 4;
    __half* yp = y + row * DD;
    *(__half2*)(yp + c0) = __floats2half2_rn(
        (a.x - m) * rs * __ldg(&g[c0]) + __ldg(&b[c0]),
        (a.y - m) * rs * __ldg(&g[c0 + 1]) + __ldg(&b[c0 + 1]));
    *(__half2*)(yp + c0 + 2) = __floats2half2_rn(
        (a.z - m) * rs * __ldg(&g[c0 + 2]) + __ldg(&b[c0 + 2]),
        (a.w - m) * rs * __ldg(&g[c0 + 3]) + __ldg(&b[c0 + 3]));
    int c1 = 128 + c0;
    *(__half2*)(yp + c1) = __floats2half2_rn(
        (c.x - m) * rs * __ldg(&g[c1]) + __ldg(&b[c1]),
        (c.y - m) * rs * __ldg(&g[c1 + 1]) + __ldg(&b[c1 + 1]));
    *(__half2*)(yp + c1 + 2) = __floats2half2_rn(
        (c.z - m) * rs * __ldg(&g[c1 + 2]) + __ldg(&b[c1 + 2]),
        (c.w - m) * rs * __ldg(&g[c1 + 3]) + __ldg(&b[c1 + 3]));
}

__global__ void qproj_kernel(const float* __restrict__ ng, const float* __restrict__ nb) {
    __shared__ float sln[DD];
    __shared__ float r1[8], r2[8];
    int row = blockIdx.x, tid = threadIdx.x;
    float v = g_slots[row * DD + tid];
    float2 mv = block_meanvar_256(v, r1, r2);
    sln[tid] = (v - mv.x) * mv.y * ng[tid] + nb[tid];
    g_U[row * DD + tid] = 0.f;
    if (tid == 0) g_rowsum[row] = 0.f;
    __syncthreads();
    float acc = 0.f;
    #pragma unroll 8
    for (int d = 0; d < DD; d++) acc += sln[d] * g_wqT[d * DD + tid];
    g_q[row * DD + tid] = acc;
}

__global__ void __launch_bounds__(256)
attn_kernel() {
    int b = blockIdx.x, ch = blockIdx.y;
    int warp = threadIdx.x >> 5, lane = threadIdx.x & 31;
    __shared__ float qs[NS * DD];
    __shared__ float dots[8][NS];
    __shared__ float aw[8][NS];
    for (int i = threadIdx.x; i < NS * DD; i += 256) qs[i] = g_q[b * NS * DD + i];
    __syncthreads();
    float qreg[8];
    #pragma unroll
    for (int k = 0; k < 4; k++) {
        qreg[2 * k]     = qs[warp * DD + 2 * (lane + 32 * k)];
        qreg[2 * k + 1] = qs[warp * DD + 2 * (lane + 32 * k) + 1];
    }
    float2 uacc[4];
    #pragma unroll
    for (int k = 0; k < 4; k++) uacc[k] = make_float2(0.f, 0.f);
    float rsum = 0.f;
    const float scale = 0.0625f;
    int t0 = ch * 256;
    const __half* kvb = g_kvh + ((size_t)b * NTOK + t0) * 512;

    for (int tt = 0; tt < 256; tt += 8) {
        #pragma unroll
        for (int u = 0; u < 8; u++) {
            const __half2* kp = (const __half2*)(kvb + (size_t)(tt + u) * 512);
            float d = 0.f;
            #pragma unroll
            for (int k = 0; k < 4; k++) {
                float2 kv2 = __half22float2(kp[lane + 32 * k]);
                d += qreg[2 * k] * kv2.x + qreg[2 * k + 1] * kv2.y;
            }
            #pragma unroll
            for (int o = 16; o; o >>= 1) d += __shfl_xor_sync(0xffffffffu, d, o);
            if (lane == 0) dots[u][warp] = d * scale;
        }
        __syncthreads();
        if (threadIdx.x < 64) {
            int u = threadIdx.x >> 3, s = threadIdx.x & 7;
            float mx = -1e30f;
            #pragma unroll
            for (int s2 = 0; s2 < NS; s2++) mx = fmaxf(mx, dots[u][s2]);
            float e = expf(dots[u][s] - mx);
            float sum = e;
            #pragma unroll
            for (int o = 1; o < 8; o <<= 1) sum += __shfl_xor_sync(0xffffffffu, sum, o);
            aw[u][s] = e / sum + 1e-8f;
        }
        __syncthreads();
        #pragma unroll
        for (int u = 0; u < 8; u++) {
            float a = aw[u][warp];
            const __half2* vp = (const __half2*)(kvb + (size_t)(tt + u) * 512 + 256);
            #pragma unroll
            for (int k = 0; k < 4; k++) {
                float2 vv = __half22float2(vp[lane + 32 * k]);
                uacc[k].x += a * vv.x;
                uacc[k].y += a * vv.y;
            }
            rsum += a;
        }
        __syncthreads();
    }
    float* up = g_U + (b * NS + warp) * DD;
    #pragma unroll
    for (int k = 0; k < 4; k++) {
        atomicAdd(&up[2 * (lane + 32 * k)], uacc[k].x);
        atomicAdd(&up[2 * (lane + 32 * k) + 1], uacc[k].y);
    }
    if (lane == 0) atomicAdd(&g_rowsum[b * NS + warp], rsum);
}

// updh = (half)(U / rowsum)
__global__ void updfin_kernel() {
    int i = blockIdx.x * 256 + threadIdx.x;
    g_updh[i] = __float2half(g_U[i] / g_rowsum[i >> 8]);
}

// pointwise GRU + pre-LN: h = (1-z)n + z*slots_prev;  mlpin = LN(h)
__global__ void gru_pw_kernel(const float* __restrict__ mlng,
                              const float* __restrict__ mlnb) {
    __shared__ float r1[8], r2[8];
    int row = blockIdx.x, tid = threadIdx.x;
    const float* gi = g_gi + row * 3 * DD;
    const float* gh = g_gh + row * 3 * DD;
    float ir = gi[tid], iz = gi[tid + 256], inn = gi[tid + 512];
    float hr = gh[tid], hz = gh[tid + 256], hn = gh[tid + 512];
    float sprev = g_slots[row * DD + tid];
    float r = 1.f / (1.f + expf(-(ir + hr)));
    float z = 1.f / (1.f + expf(-(iz + hz)));
    float n = tanhf(inn + r * hn);
    float h = (1.f - z) * n + z * sprev;
    g_hbuf[row * DD + tid] = h;
    float2 mv = block_meanvar_256(h, r1, r2);
    g_mlpinh[row * DD + tid] = __float2half((h - mv.x) * mv.y * mlng[tid] + mlnb[tid]);
}

// ================= launch =================
extern "C" void kernel_launch(void* const* d_in, const int* in_sizes, int n_in,
                              void* d_out, int out_size) {
    const float* inputs   = (const float*)d_in[0];
    const float* slots_in = (const float*)d_in[1];
    const float* ln1g = (const float*)d_in[2];
    const float* ln1b = (const float*)d_in[3];
    const float* w1   = (const float*)d_in[4];
    const float* b1   = (const float*)d_in[5];
    const float* w2   = (const float*)d_in[6];
    const float* b2   = (const float*)d_in[7];
    const float* ln2g = (const float*)d_in[8];
    const float* ln2b = (const float*)d_in[9];
    const float* wq   = (const float*)d_in[10];
    const float* wk   = (const float*)d_in[11];
    const float* wv   = (const float*)d_in[12];
    const float* normg = (const float*)d_in[13];
    const float* normb = (const float*)d_in[14];
    const float* gwih = (const float*)d_in[15];
    const float* gwhh = (const float*)d_in[16];
    const float* gbih = (const float*)d_in[17];
    const float* gbhh = (const float*)d_in[18];
    const float* mlng = (const float*)d_in[19];
    const float* mlnb = (const float*)d_in[20];
    const float* mw1  = (const float*)d_in[21];
    const float* mb1  = (const float*)d_in[22];
    const float* mw2  = (const float*)d_in[23];
    const float* mb2  = (const float*)d_in[24];
    float* out = (float*)d_out;

    __half *p_inh, *p_h1h, *p_featsh, *p_kvh, *p_w1h, *p_w2h, *p_wkvh;
    __half *p_wihh, *p_whhh, *p_mw1h, *p_mw2h, *p_updh, *p_mlpinh, *p_hhh, *p_slotsh;
    float *p_h2, *p_wqT, *p_slots, *p_gi, *p_gh, *p_hbuf;
    cudaGetSymbolAddress((void**)&p_inh,    g_inh);
    cudaGetSymbolAddress((void**)&p_h1h,    g_h1h);
    cudaGetSymbolAddress((void**)&p_featsh, g_featsh);
    cudaGetSymbolAddress((void**)&p_kvh,    g_kvh);
    cudaGetSymbolAddress((void**)&p_w1h,    g_w1h);
    cudaGetSymbolAddress((void**)&p_w2h,    g_w2h);
    cudaGetSymbolAddress((void**)&p_wkvh,   g_wkvh);
    cudaGetSymbolAddress((void**)&p_wihh,   g_wihh);
    cudaGetSymbolAddress((void**)&p_whhh,   g_whhh);
    cudaGetSymbolAddress((void**)&p_mw1h,   g_mw1h);
    cudaGetSymbolAddress((void**)&p_mw2h,   g_mw2h);
    cudaGetSymbolAddress((void**)&p_updh,   g_updh);
    cudaGetSymbolAddress((void**)&p_mlpinh, g_mlpinh);
    cudaGetSymbolAddress((void**)&p_hhh,    g_hhh);
    cudaGetSymbolAddress((void**)&p_slotsh, g_slotsh);
    cudaGetSymbolAddress((void**)&p_h2,     g_h2);
    cudaGetSymbolAddress((void**)&p_wqT,    g_wqT);
    cudaGetSymbolAddress((void**)&p_slots,  g_slots);
    cudaGetSymbolAddress((void**)&p_gi,     g_gi);
    cudaGetSymbolAddress((void**)&p_gh,     g_gh);
    cudaGetSymbolAddress((void**)&p_hbuf,   g_hbuf);

    // REQUIRED: 110,592 B dynamic smem exceeds the 48 KB default opt-in
    cudaFuncSetAttribute(hgemm128_kernel<1>, cudaFuncAttributeMaxDynamicSharedMemorySize, H128_DSMEM);
    cudaFuncSetAttribute(hgemm128_kernel<2>, cudaFuncAttributeMaxDynamicSharedMemorySize, H128_DSMEM);
    cudaFuncSetAttribute(hgemm128_kernel<3>, cudaFuncAttributeMaxDynamicSharedMemorySize, H128_DSMEM);

    dim3 tb(32, 8);
    // 0: fused LN stats + fp16 conversion of inputs
    ln_stats_f2h_kernel<<<MROWS / 8, 256>>>(inputs, p_inh);
    // 1: w1 -> [N][K] fp16 scaled by ln1g
    trans_h_kernel<<<dim3(FDIN / 32, FDIN / 32), tb>>>(w1, p_w1h, FDIN, FDIN, ln1g);
    // 2: epilogue fold vectors
    prep_sums_kernel<<<FDIN, 256>>>(w1, ln1g, ln1b, b1);
    // 3: GEMM1 (128x128 tile, BK=64)   << ncu window
    hgemm128_kernel<1><<<dim3(FDIN / 128, MROWS / 128), 256, H128_DSMEM>>>(
        p_inh, p_w1h, FDIN, FDIN, nullptr, p_h1h, nullptr);
    // 4: w2 -> [N][K] fp16
    trans_h_kernel<<<dim3(DD / 32, FDIN / 32), tb>>>(w2, p_w2h, FDIN, DD, nullptr);
    // 5: GEMM2 h2 = h1 @ w2 + b2 -> fp32
    hgemm128_kernel<2><<<dim3(DD / 128, MROWS / 128), 256, H128_DSMEM>>>(
        p_h1h, p_w2h, DD, FDIN, p_h2, nullptr, b2);
    // 6: feats = LN(h2) -> fp16 (warp-per-row)
    ln256_kernel<<<MROWS / 8, 256>>>(p_h2, p_featsh, ln2g, ln2b);
    // 7: wk|wv -> fp16
    wkv_h_kernel<<<DD * DD / 256, 256>>>(wk, wv);
    // 8: KV GEMM -> fp16
    hgemm128_kernel<3><<<dim3(2 * DD / 128, MROWS / 128), 256, H128_DSMEM>>>(
        p_featsh, p_wkvh, 2 * DD, DD, nullptr, p_kvh, nullptr);

    // slot-path weight prep
    trans_f_kernel<<<dim3(DD / 32, DD / 32), tb>>>(wq, p_wqT, DD, DD);
    conv_f2h_kernel<<<3 * DD * DD / 1024, 256>>>(gwih, p_wihh);
    conv_f2h_kernel<<<3 * DD * DD / 1024, 256>>>(gwhh, p_whhh);
    trans_h_kernel<<<dim3(4 * DD / 32, DD / 32), tb>>>(mw1, p_mw1h, DD, 4 * DD, nullptr);
    trans_h_kernel<<<dim3(DD / 32, 4 * DD / 32), tb>>>(mw2, p_mw2h, 4 * DD, DD, nullptr);
    slots_init_kernel<<<SROWS * DD / 256, 256>>>(slots_in);

    for (int t = 0; t < ITERS; t++) {
        qproj_kernel<<<SROWS, 256>>>(normg, normb);
        attn_kernel<<<dim3(BNUM, 16), 256>>>();
        updfin_kernel<<<SROWS, 256>>>();
        // gi = updh @ wih^T + bih   [768 x 768, K=256]
        hgemm64_kernel<10><<<dim3(3 * DD / 64, SROWS / 128), 256, H64_DSMEM>>>(
            p_updh, p_wihh, 3 * DD, DD, p_gi, nullptr, gbih, nullptr);
        // gh = slotsh @ whh^T + bhh
        hgemm64_kernel<10><<<dim3(3 * DD / 64, SROWS / 128), 256, H64_DSMEM>>>(
            p_slotsh, p_whhh, 3 * DD, DD, p_gh, nullptr, gbhh, nullptr);
        // pointwise GRU + LN
        gru_pw_kernel<<<SROWS, 256>>>(mlng, mlnb);
        // hh = relu(mlpin @ mw1 + mb1)   [768 x 1024, K=256]
        hgemm64_kernel<11><<<dim3(4 * DD / 64, SROWS / 128), 256, H64_DSMEM>>>(
            p_mlpinh, p_mw1h, 4 * DD, DD, nullptr, p_hhh, mb1, nullptr);
        // slots = h + hh @ mw2 + mb2   [768 x 256, K=1024]
        float* dst = (t == ITERS - 1) ? out : p_slots;
        hgemm64_kernel<12><<<dim3(DD / 64, SROWS / 128), 256, H64_DSMEM>>>(
            p_hhh, p_mw2h, DD, 4 * DD, dst, p_slotsh, mb2, p_hbuf);
    }
}

// round 12
// speedup vs baseline: 2.7187x; 1.0106x over previous
#include <cuda_runtime.h>
#include <cuda_fp16.h>
#include <math.h>
#include <stdint.h>

#define BNUM 32
#define NTOK 4096
#define FDIN 768
#define DD 256
#define NS 8
#define MROWS (BNUM * NTOK)   // 131072
#define SROWS (BNUM * NS)     // 768 slot rows
#define ITERS 3

// ---------------- scratch (static __device__ — no allocation) ----------------
__device__ float  g_mean[MROWS];
__device__ float  g_rstd[MROWS];
__device__ __half g_inh[(size_t)MROWS * FDIN];
__device__ __half g_h1h[(size_t)MROWS * FDIN];
__device__ __half g_featsh[(size_t)MROWS * DD];
__device__ __half g_kvh[(size_t)MROWS * 2 * DD];  // [row][512]: keys | vals fp16
__device__ __half g_w1h[FDIN * FDIN];             // [N=768][K=768], scaled by ln1g
__device__ float  g_gB[FDIN];
__device__ float  g_bBp[FDIN];
__device__ __half g_w2h[DD * FDIN];               // [N=256][K=768]
__device__ __half g_wkvh[2 * DD * DD];            // [N=512][K=256]
__device__ float  g_wqT[DD * DD];
// GRU / MLP weights fp16 (K-major)
__device__ __half g_wihh[3 * DD * DD];
__device__ __half g_whhh[3 * DD * DD];
__device__ __half g_mw1h[4 * DD * DD];
__device__ __half g_mw2h[DD * 4 * DD];
// iteration state
__device__ float  g_slots[SROWS * DD];
__device__ __half g_slotsh[SROWS * DD];
__device__ float  g_q[SROWS * DD];
__device__ float  g_U[SROWS * DD];
__device__ float  g_rowsum[SROWS];
__device__ __half g_updh[SROWS * DD];
__device__ float  g_gi[SROWS * 3 * DD];
__device__ float  g_gh[SROWS * 3 * DD];
__device__ float  g_hbuf[SROWS * DD];
__device__ __half g_mlpinh[SROWS * DD];
__device__ __half g_hhh[SROWS * 4 * DD];

// ================= asm helpers =================
#define CP_ASYNC16(dst, src) \
    asm volatile("cp.async.cg.shared.global [%0], [%1], 16;\n" :: "r"(dst), "l"(src))
#define CP_COMMIT() asm volatile("cp.async.commit_group;\n" ::: "memory")
#define CP_WAIT1()  asm volatile("cp.async.wait_group 1;\n" ::: "memory")

__device__ __forceinline__ void ldmx4(uint32_t& r0, uint32_t& r1, uint32_t& r2,
                                      uint32_t& r3, uint32_t addr) {
    asm volatile("ldmatrix.sync.aligned.m8n8.x4.shared.b16 {%0,%1,%2,%3}, [%4];"
                 : "=r"(r0), "=r"(r1), "=r"(r2), "=r"(r3) : "r"(addr));
}

__device__ __forceinline__ void mma_f16(float* c, const uint32_t* a, const uint32_t* b) {
    asm volatile(
        "mma.sync.aligned.m16n8k16.row.col.f32.f16.f16.f32 "
        "{%0,%1,%2,%3}, {%4,%5,%6,%7}, {%8,%9}, {%0,%1,%2,%3};"
        : "+f"(c[0]), "+f"(c[1]), "+f"(c[2]), "+f"(c[3])
        : "r"(a[0]), "r"(a[1]), "r"(a[2]), "r"(a[3]), "r"(b[0]), "r"(b[1]));
}

// ================= big-tile fp16 GEMM (GEMM1/KV): 128x128, BK=64 ============
// EPI 1: LN-fold+relu -> fp16. EPI 3: raw -> fp16.
#define HR128 72
#define STG128_BYTES (256 * HR128 * 2)    // 36864
#define H128_DSMEM (3 * STG128_BYTES)     // 110592

template<int EPI>
__global__ void __launch_bounds__(256)
hgemm128_kernel(const __half* __restrict__ A, const __half* __restrict__ Bw,
                int Nn, int K, __half* __restrict__ Ch) {
    extern __shared__ __align__(16) __half smh[];
    uint32_t smb;
    asm("{ .reg .u64 t; cvta.to.shared.u64 t, %1; cvt.u32.u64 %0, t; }"
        : "=r"(smb) : "l"(smh));

    int tid = threadIdx.x;
    int lane = tid & 31;
    int warp = tid >> 5;
    int grp = lane >> 2, tig = lane & 3;
    int wm = (warp & 3) * 32;
    int wn = (warp >> 2) * 64;
    int bm = blockIdx.y * 128;
    int bn = blockIdx.x * 128;

    const __half* Abm = A + (size_t)bm * K;
    const __half* Bbn = Bw + (size_t)bn * K;

    float acc[2][8][4];
    #pragma unroll
    for (int mt = 0; mt < 2; mt++)
        #pragma unroll
        for (int nt = 0; nt < 8; nt++)
            #pragma unroll
            for (int i = 0; i < 4; i++) acc[mt][nt][i] = 0.f;

    int nit = K / 64;
    #pragma unroll
    for (int s = 0; s < 2; s++) {
        uint32_t base = smb + s * STG128_BYTES;
        #pragma unroll
        for (int j = 0; j < 4; j++) {
            int e = tid + j * 256;
            int r = e >> 3, c = e & 7;
            CP_ASYNC16(base + (r * HR128 + c * 8) * 2,
                       Abm + (size_t)r * K + s * 64 + c * 8);
            CP_ASYNC16(base + (128 * HR128 + r * HR128 + c * 8) * 2,
                       Bbn + (size_t)r * K + s * 64 + c * 8);
        }
        CP_COMMIT();
    }

    for (int it = 0; it < nit; it++) {
        CP_WAIT1();
        __syncthreads();
        uint32_t sa = smb + (it % 3) * STG128_BYTES;
        uint32_t sb = sa + 128 * HR128 * 2;
        if (it + 2 < nit) {
            uint32_t base = smb + ((it + 2) % 3) * STG128_BYTES;
            #pragma unroll
            for (int j = 0; j < 4; j++) {
                int e = tid + j * 256;
                int r = e >> 3, c = e & 7;
                CP_ASYNC16(base + (r * HR128 + c * 8) * 2,
                           Abm + (size_t)r * K + (it + 2) * 64 + c * 8);
                CP_ASYNC16(base + (128 * HR128 + r * HR128 + c * 8) * 2,
                           Bbn + (size_t)r * K + (it + 2) * 64 + c * 8);
            }
        }
        CP_COMMIT();

        #pragma unroll
        for (int kc = 0; kc < 4; kc++) {
            uint32_t afr[2][4], bfr[8][2];
            #pragma unroll
            for (int mt = 0; mt < 2; mt++) {
                uint32_t addr = sa + ((wm + mt * 16 + (lane & 15)) * HR128
                                      + kc * 16 + (lane >> 4) * 8) * 2;
                ldmx4(afr[mt][0], afr[mt][1], afr[mt][2], afr[mt][3], addr);
            }
            #pragma unroll
            for (int ng = 0; ng < 4; ng++) {
                uint32_t r0, r1, r2, r3;
                uint32_t addr = sb + ((wn + ng * 16 + (lane & 15)) * HR128
                                      + kc * 16 + (lane >> 4) * 8) * 2;
                ldmx4(r0, r1, r2, r3, addr);
                bfr[2 * ng][0] = r0; bfr[2 * ng + 1][0] = r1;
                bfr[2 * ng][1] = r2; bfr[2 * ng + 1][1] = r3;
            }
            #pragma unroll
            for (int mt = 0; mt < 2; mt++)
                #pragma unroll
                for (int nt = 0; nt < 8; nt++)
                    mma_f16(acc[mt][nt], afr[mt], bfr[nt]);
        }
    }

    #pragma unroll
    for (int mt = 0; mt < 2; mt++) {
        int r0 = bm + wm + mt * 16 + grp;
        float mu0 = 0.f, rs0 = 0.f, mu1 = 0.f, rs1 = 0.f;
        if (EPI == 1) {
            mu0 = g_mean[r0]; rs0 = g_rstd[r0];
            mu1 = g_mean[r0 + 8]; rs1 = g_rstd[r0 + 8];
        }
        #pragma unroll
        for (int nt = 0; nt < 8; nt++) {
            int col = bn + wn + nt * 8 + tig * 2;
            float c0 = acc[mt][nt][0], c1 = acc[mt][nt][1];
            float c2 = acc[mt][nt][2], c3 = acc[mt][nt][3];
            if (EPI == 1) {
                float gb0 = __ldg(&g_gB[col]), gb1 = __ldg(&g_gB[col + 1]);
                float bb0 = __ldg(&g_bBp[col]), bb1 = __ldg(&g_bBp[col + 1]);
                c0 = fmaxf(c0 * rs0 - mu0 * rs0 * gb0 + bb0, 0.f);
                c1 = fmaxf(c1 * rs0 - mu0 * rs0 * gb1 + bb1, 0.f);
                c2 = fmaxf(c2 * rs1 - mu1 * rs1 * gb0 + bb0, 0.f);
                c3 = fmaxf(c3 * rs1 - mu1 * rs1 * gb1 + bb1, 0.f);
            }
            *(__half2*)(Ch + (size_t)r0 * Nn + col)       = __floats2half2_rn(c0, c1);
            *(__half2*)(Ch + (size_t)(r0 + 8) * Nn + col) = __floats2half2_rn(c2, c3);
        }
    }
}

// ========== GEMM2 fused row-LN: 128x256 tile, 512 threads, BK=64 ============
// feats = fp16( LN_row(h1 @ w2 + b2) * ln2g + ln2b ).  N fixed = 256.
#define STG256_BYTES ((128 + 256) * HR128 * 2)   // 55296
#define H256_DSMEM (3 * STG256_BYTES)            // 165888

__global__ void __launch_bounds__(512)
hgemm2ln_kernel(const __half* __restrict__ A, const __half* __restrict__ Bw,
                int K, __half* __restrict__ Ch,
                const float* __restrict__ bias,
                const float* __restrict__ lng, const float* __restrict__ lnb) {
    extern __shared__ __align__(16) __half smh[];
    uint32_t smb;
    asm("{ .reg .u64 t; cvta.to.shared.u64 t, %1; cvt.u32.u64 %0, t; }"
        : "=r"(smb) : "l"(smh));

    const int Nn = 256;
    int tid = threadIdx.x;
    int lane = tid & 31;
    int warp = tid >> 5;                 // 0..15
    int grp = lane >> 2, tig = lane & 3;
    int wm = (warp & 3) * 32;            // 4 warps over M=128
    int wn = (warp >> 2) * 64;           // 4 warps over N=256
    int bm = blockIdx.y * 128;

    const __half* Abm = A + (size_t)bm * K;
    const __half* Bbn = Bw;              // full N=256

    float acc[2][8][4];
    #pragma unroll
    for (int mt = 0; mt < 2; mt++)
        #pragma unroll
        for (int nt = 0; nt < 8; nt++)
            #pragma unroll
            for (int i = 0; i < 4; i++) acc[mt][nt][i] = 0.f;

    int nit = K / 64;
    #pragma unroll
    for (int s = 0; s < 2; s++) {
        uint32_t base = smb + s * STG256_BYTES;
        #pragma unroll
        for (int j = 0; j < 2; j++) {        // A: 1024 chunks / 512 thr
            int e = tid + j * 512;
            int r = e >> 3, c = e & 7;
            CP_ASYNC16(base + (r * HR128 + c * 8) * 2,
                       Abm + (size_t)r * K + s * 64 + c * 8);
        }
        #pragma unroll
        for (int j = 0; j < 4; j++) {        // B: 2048 chunks / 512 thr
            int e = tid + j * 512;
            int r = e >> 3, c = e & 7;
            CP_ASYNC16(base + (128 * HR128 + r * HR128 + c * 8) * 2,
                       Bbn + (size_t)r * K + s * 64 + c * 8);
        }
        CP_COMMIT();
    }

    for (int it = 0; it < nit; it++) {
        CP_WAIT1();
        __syncthreads();
        uint32_t sa = smb + (it % 3) * STG256_BYTES;
        uint32_t sb = sa + 128 * HR128 * 2;
        if (it + 2 < nit) {
            uint32_t base = smb + ((it + 2) % 3) * STG256_BYTES;
            #pragma unroll
            for (int j = 0; j < 2; j++) {
                int e = tid + j * 512;
                int r = e >> 3, c = e & 7;
                CP_ASYNC16(base + (r * HR128 + c * 8) * 2,
                           Abm + (size_t)r * K + (it + 2) * 64 + c * 8);
            }
            #pragma unroll
            for (int j = 0; j < 4; j++) {
                int e = tid + j * 512;
                int r = e >> 3, c = e & 7;
                CP_ASYNC16(base + (128 * HR128 + r * HR128 + c * 8) * 2,
                           Bbn + (size_t)r * K + (it + 2) * 64 + c * 8);
            }
        }
        CP_COMMIT();

        #pragma unroll
        for (int kc = 0; kc < 4; kc++) {
            uint32_t afr[2][4], bfr[8][2];
            #pragma unroll
            for (int mt = 0; mt < 2; mt++) {
                uint32_t addr = sa + ((wm + mt * 16 + (lane & 15)) * HR128
                                      + kc * 16 + (lane >> 4) * 8) * 2;
                ldmx4(afr[mt][0], afr[mt][1], afr[mt][2], afr[mt][3], addr);
            }
            #pragma unroll
            for (int ng = 0; ng < 4; ng++) {
                uint32_t r0, r1, r2, r3;
                uint32_t addr = sb + ((wn + ng * 16 + (lane & 15)) * HR128
                                      + kc * 16 + (lane >> 4) * 8) * 2;
                ldmx4(r0, r1, r2, r3, addr);
                bfr[2 * ng][0] = r0; bfr[2 * ng + 1][0] = r1;
                bfr[2 * ng][1] = r2; bfr[2 * ng + 1][1] = r3;
            }
            #pragma unroll
            for (int mt = 0; mt < 2; mt++)
                #pragma unroll
                for (int nt = 0; nt < 8; nt++)
                    mma_f16(acc[mt][nt], afr[mt], bfr[nt]);
        }
    }

    // ---- fused row-LN epilogue ----
    __syncthreads();                       // done with stage smem
    float* s_sum = (float*)smh;            // [128]
    float* s_sq  = s_sum + 128;            // [128]
    float* s_mu  = s_sq + 128;
    float* s_rs  = s_mu + 128;
    if (tid < 128) { s_sum[tid] = 0.f; s_sq[tid] = 0.f; }
    __syncthreads();

    // add bias, accumulate per-row partial sums (rows rl, rl+8 for each mt)
    #pragma unroll
    for (int mt = 0; mt < 2; mt++) {
        int rl = wm + mt * 16 + grp;
        float s0 = 0.f, q0 = 0.f, s1 = 0.f, q1 = 0.f;
        #pragma unroll
        for (int nt = 0; nt < 8; nt++) {
            int col = wn + nt * 8 + tig * 2;
            float b0 = __ldg(&bias[col]), b1 = __ldg(&bias[col + 1]);
            float c0 = acc[mt][nt][0] + b0, c1 = acc[mt][nt][1] + b1;
            float c2 = acc[mt][nt][2] + b0, c3 = acc[mt][nt][3] + b1;
            acc[mt][nt][0] = c0; acc[mt][nt][1] = c1;
            acc[mt][nt][2] = c2; acc[mt][nt][3] = c3;
            s0 += c0 + c1; q0 += c0 * c0 + c1 * c1;
            s1 += c2 + c3; q1 += c2 * c2 + c3 * c3;
        }
        // reduce over tig (lane bits 0,1)
        #pragma unroll
        for (int o = 1; o < 4; o <<= 1) {
            s0 += __shfl_xor_sync(0xffffffffu, s0, o);
            q0 += __shfl_xor_sync(0xffffffffu, q0, o);
            s1 += __shfl_xor_sync(0xffffffffu, s1, o);
            q1 += __shfl_xor_sync(0xffffffffu, q1, o);
        }
        if (tig == 0) {
            atomicAdd(&s_sum[rl], s0);     atomicAdd(&s_sq[rl], q0);
            atomicAdd(&s_sum[rl + 8], s1); atomicAdd(&s_sq[rl + 8], q1);
        }
    }
    __syncthreads();
    if (tid < 128) {
        float m = s_sum[tid] * (1.f / 256.f);
        float var = s_sq[tid] * (1.f / 256.f) - m * m;
        s_mu[tid] = m;
        s_rs[tid] = rsqrtf(var + 1e-5f);
    }
    __syncthreads();

    #pragma unroll
    for (int mt = 0; mt < 2; mt++) {
        int rl = wm + mt * 16 + grp;
        float mu0 = s_mu[rl], rs0 = s_rs[rl];
        float mu1 = s_mu[rl + 8], rs1 = s_rs[rl + 8];
        int gr = bm + rl;
        #pragma unroll
        for (int nt = 0; nt < 8; nt++) {
            int col = wn + nt * 8 + tig * 2;
            float g0 = __ldg(&lng[col]), g1 = __ldg(&lng[col + 1]);
            float l0 = __ldg(&lnb[col]), l1 = __ldg(&lnb[col + 1]);
            float c0 = (acc[mt][nt][0] - mu0) * rs0 * g0 + l0;
            float c1 = (acc[mt][nt][1] - mu0) * rs0 * g1 + l1;
            float c2 = (acc[mt][nt][2] - mu1) * rs1 * g0 + l0;
            float c3 = (acc[mt][nt][3] - mu1) * rs1 * g1 + l1;
            *(__half2*)(Ch + (size_t)gr * Nn + col)       = __floats2half2_rn(c0, c1);
            *(__half2*)(Ch + (size_t)(gr + 8) * Nn + col) = __floats2half2_rn(c2, c3);
        }
    }
}

// ================= small-tile fp16 GEMM (slot path): 128x64, BK=32 ===========
#define HROW 40
#define STG64_BYTES ((128 + 64) * HROW * 2)
#define H64_DSMEM (3 * STG64_BYTES)

template<int EPI>
__global__ void __launch_bounds__(256, 3)
hgemm64_kernel(const __half* __restrict__ A, const __half* __restrict__ Bw,
               int Nn, int K, float* __restrict__ Cf, __half* __restrict__ Ch,
               const float* __restrict__ bias, const float* __restrict__ res) {
    extern __shared__ __align__(16) __half smh[];
    uint32_t smb;
    asm("{ .reg .u64 t; cvta.to.shared.u64 t, %1; cvt.u32.u64 %0, t; }"
        : "=r"(smb) : "l"(smh));

    int tid = threadIdx.x;
    int lane = tid & 31;
    int warp = tid >> 5;
    int grp = lane >> 2, tig = lane & 3;
    int wm = (warp & 3) * 32;
    int wn = (warp >> 2) * 32;
    int bm = blockIdx.y * 128;
    int bn = blockIdx.x * 64;

    const __half* Abm = A + (size_t)bm * K;
    const __half* Bbn = Bw + (size_t)bn * K;

    float acc[2][4][4];
    #pragma unroll
    for (int mt = 0; mt < 2; mt++)
        #pragma unroll
        for (int nt = 0; nt < 4; nt++)
            #pragma unroll
            for (int i = 0; i < 4; i++) acc[mt][nt][i] = 0.f;

    int nit = K / 32;
    #pragma unroll
    for (int s = 0; s < 2; s++) {
        uint32_t base = smb + s * STG64_BYTES;
        #pragma unroll
        for (int j = 0; j < 2; j++) {
            int e = tid + j * 256;
            int r = e >> 2, c = e & 3;
            CP_ASYNC16(base + (r * HROW + c * 8) * 2, Abm + (size_t)r * K + s * 32 + c * 8);
        }
        {
            int r = tid >> 2, c = tid & 3;
            CP_ASYNC16(base + (128 * HROW + r * HROW + c * 8) * 2,
                       Bbn + (size_t)r * K + s * 32 + c * 8);
        }
        CP_COMMIT();
    }

    for (int it = 0; it < nit; it++) {
        CP_WAIT1();
        __syncthreads();
        uint32_t sa = smb + (it % 3) * STG64_BYTES;
        uint32_t sb = sa + 128 * HROW * 2;
        if (it + 2 < nit) {
            uint32_t base = smb + ((it + 2) % 3) * STG64_BYTES;
            #pragma unroll
            for (int j = 0; j < 2; j++) {
                int e = tid + j * 256;
                int r = e >> 2, c = e & 3;
                CP_ASYNC16(base + (r * HROW + c * 8) * 2,
                           Abm + (size_t)r * K + (it + 2) * 32 + c * 8);
            }
            {
                int r = tid >> 2, c = tid & 3;
                CP_ASYNC16(base + (128 * HROW + r * HROW + c * 8) * 2,
                           Bbn + (size_t)r * K + (it + 2) * 32 + c * 8);
            }
        }
        CP_COMMIT();

        #pragma unroll
        for (int kc = 0; kc < 2; kc++) {
            uint32_t afr[2][4], bfr[4][2];
            #pragma unroll
            for (int mt = 0; mt < 2; mt++) {
                uint32_t addr = sa + ((wm + mt * 16 + (lane & 15)) * HROW
                                      + kc * 16 + (lane >> 4) * 8) * 2;
                ldmx4(afr[mt][0], afr[mt][1], afr[mt][2], afr[mt][3], addr);
            }
            #pragma unroll
            for (int ng = 0; ng < 2; ng++) {
                uint32_t r0, r1, r2, r3;
                uint32_t addr = sb + ((wn + ng * 16 + (lane & 15)) * HROW
                                      + kc * 16 + (lane >> 4) * 8) * 2;
                ldmx4(r0, r1, r2, r3, addr);
                bfr[2 * ng][0] = r0; bfr[2 * ng + 1][0] = r1;
                bfr[2 * ng][1] = r2; bfr[2 * ng + 1][1] = r3;
            }
            #pragma unroll
            for (int mt = 0; mt < 2; mt++)
                #pragma unroll
                for (int nt = 0; nt < 4; nt++)
                    mma_f16(acc[mt][nt], afr[mt], bfr[nt]);
        }
    }

    #pragma unroll
    for (int mt = 0; mt < 2; mt++) {
        int r0 = bm + wm + mt * 16 + grp;
        #pragma unroll
        for (int nt = 0; nt < 4; nt++) {
            int col = bn + wn + nt * 8 + tig * 2;
            float b0 = __ldg(&bias[col]), b1 = __ldg(&bias[col + 1]);
            float c0 = acc[mt][nt][0] + b0, c1 = acc[mt][nt][1] + b1;
            float c2 = acc[mt][nt][2] + b0, c3 = acc[mt][nt][3] + b1;
            if (EPI == 10) {
                *(float2*)(Cf + (size_t)r0 * Nn + col)       = make_float2(c0, c1);
                *(float2*)(Cf + (size_t)(r0 + 8) * Nn + col) = make_float2(c2, c3);
            } else if (EPI == 11) {
                c0 = fmaxf(c0, 0.f); c1 = fmaxf(c1, 0.f);
                c2 = fmaxf(c2, 0.f); c3 = fmaxf(c3, 0.f);
                *(__half2*)(Ch + (size_t)r0 * Nn + col)       = __floats2half2_rn(c0, c1);
                *(__half2*)(Ch + (size_t)(r0 + 8) * Nn + col) = __floats2half2_rn(c2, c3);
            } else {   // EPI 12: residual + dual store
                float2 ra = *(const float2*)(res + (size_t)r0 * Nn + col);
                float2 rb = *(const float2*)(res + (size_t)(r0 + 8) * Nn + col);
                c0 += ra.x; c1 += ra.y; c2 += rb.x; c3 += rb.y;
                *(float2*)(Cf + (size_t)r0 * Nn + col)       = make_float2(c0, c1);
                *(float2*)(Cf + (size_t)(r0 + 8) * Nn + col) = make_float2(c2, c3);
                *(__half2*)(Ch + (size_t)r0 * Nn + col)       = __floats2half2_rn(c0, c1);
                *(__half2*)(Ch + (size_t)(r0 + 8) * Nn + col) = __floats2half2_rn(c2, c3);
            }
        }
    }
}

// ================= prep / small kernels =================
__global__ void ln_stats_f2h_kernel(const float* __restrict__ x, __half* __restrict__ xh) {
    int row = blockIdx.x * 8 + (threadIdx.x >> 5);
    int lane = threadIdx.x & 31;
    const float* p = x + (size_t)row * FDIN;
    __half* ph = xh + (size_t)row * FDIN;
    float v[24];
    float s = 0.f, ss = 0.f;
    #pragma unroll
    for (int k = 0; k < 24; k++) {
        v[k] = p[lane + 32 * k];
        s += v[k];
        ss += v[k] * v[k];
    }
    #pragma unroll
    for (int k = 0; k < 24; k++) ph[lane + 32 * k] = __float2half(v[k]);
    #pragma unroll
    for (int o = 16; o; o >>= 1) {
        s  += __shfl_xor_sync(0xffffffffu, s, o);
        ss += __shfl_xor_sync(0xffffffffu, ss, o);
    }
    float m = s * (1.f / FDIN);
    float var = ss * (1.f / FDIN) - m * m;
    if (lane == 0) { g_mean[row] = m; g_rstd[row] = rsqrtf(var + 1e-5f); }
}

__global__ void conv_f2h_kernel(const float* __restrict__ in, __half* __restrict__ out) {
    size_t i = ((size_t)blockIdx.x * 256 + threadIdx.x) * 4;
    float4 v = *(const float4*)(in + i);
    *(__half2*)(out + i)     = __floats2half2_rn(v.x, v.y);
    *(__half2*)(out + i + 2) = __floats2half2_rn(v.z, v.w);
}

__global__ void trans_h_kernel(const float* __restrict__ in, __half* __restrict__ out,
                               int R, int C, const float* __restrict__ scale) {
    __shared__ float t[32][33];
    int bx = blockIdx.x * 32, by = blockIdx.y * 32;
    int x = bx + threadIdx.x;
    #pragma unroll
    for (int j = 0; j < 32; j += 8) {
        int y = by + threadIdx.y + j;
        float s = scale ? scale[y] : 1.f;
        t[threadIdx.y + j][threadIdx.x] = in[(size_t)y * C + x] * s;
    }
    __syncthreads();
    int x2 = by + threadIdx.x;
    #pragma unroll
    for (int j = 0; j < 32; j += 8) {
        int y2 = bx + threadIdx.y + j;
        out[(size_t)y2 * R + x2] = __float2half(t[threadIdx.x][threadIdx.y + j]);
    }
}

__global__ void trans_f_kernel(const float* __restrict__ in, float* __restrict__ out,
                               int R, int C) {
    __shared__ float t[32][33];
    int bx = blockIdx.x * 32, by = blockIdx.y * 32;
    int x = bx + threadIdx.x;
    #pragma unroll
    for (int j = 0; j < 32; j += 8)
        t[threadIdx.y + j][threadIdx.x] = in[(size_t)(by + threadIdx.y + j) * C + x];
    __syncthreads();
    int x2 = by + threadIdx.x;
    #pragma unroll
    for (int j = 0; j < 32; j += 8)
        out[(size_t)(bx + threadIdx.y + j) * R + x2] = t[threadIdx.x][threadIdx.y + j];
}

__global__ void wkv_h_kernel(const float* __restrict__ wk, const float* __restrict__ wv) {
    int i = blockIdx.x * 256 + threadIdx.x;
    g_wkvh[i] = __float2half(wk[i]);
    g_wkvh[DD * DD + i] = __float2half(wv[i]);
}

// coalesced prep_sums: grid (FDIN/256, 8); k-split with atomics (gB/bBp pre-zeroed)
__global__ void prep_sums_kernel(const float* __restrict__ w1,
                                 const float* __restrict__ g,
                                 const float* __restrict__ b,
                                 const float* __restrict__ b1) {
    int n = blockIdx.x * 256 + threadIdx.x;
    int k0 = blockIdx.y * 96;
    float s1 = 0.f, s2 = 0.f;
    #pragma unroll 8
    for (int k = k0; k < k0 + 96; k++) {
        float w = w1[(size_t)k * FDIN + n];
        s1 += g[k] * w;
        s2 += b[k] * w;
    }
    if (blockIdx.y == 0) s2 += b1[n];
    atomicAdd(&g_gB[n], s1);
    atomicAdd(&g_bBp[n], s2);
}

__global__ void slots_init_kernel(const float* __restrict__ si) {
    int i = blockIdx.x * 256 + threadIdx.x;
    float v = si[i & (NS * DD - 1)];
    g_slots[i] = v;
    g_slotsh[i] = __float2half(v);
}

__device__ __forceinline__ float2 block_meanvar_256(float v, float* r1, float* r2) {
    float s = v, q = v * v;
    #pragma unroll
    for (int o = 16; o; o >>= 1) {
        s += __shfl_xor_sync(0xffffffffu, s, o);
        q += __shfl_xor_sync(0xffffffffu, q, o);
    }
    int w = threadIdx.x >> 5, lane = threadIdx.x & 31;
    if (lane == 0) { r1[w] = s; r2[w] = q; }
    __syncthreads();
    float sum = 0.f, sq = 0.f;
    #pragma unroll
    for (int i = 0; i < 8; i++) { sum += r1[i]; sq += r2[i]; }
    __syncthreads();
    float m = sum * (1.f / 256.f);
    float var = sq * (1.f / 256.f) - m * m;
    return make_float2(m, rsqrtf(var + 1e-5f));
}

__global__ void qproj_kernel(const float* __restrict__ ng, const float* __restrict__ nb) {
    __shared__ float sln[DD];
    __shared__ float r1[8], r2[8];
    int row = blockIdx.x, tid = threadIdx.x;
    float v = g_slots[row * DD + tid];
    float2 mv = block_meanvar_256(v, r1, r2);
    sln[tid] = (v - mv.x) * mv.y * ng[tid] + nb[tid];
    g_U[row * DD + tid] = 0.f;
    if (tid == 0) g_rowsum[row] = 0.f;
    __syncthreads();
    float acc = 0.f;
    #pragma unroll 8
    for (int d = 0; d < DD; d++) acc += sln[d] * g_wqT[d * DD + tid];
    g_q[row * DD + tid] = acc;
}

__global__ void __launch_bounds__(256)
attn_kernel() {
    int b = blockIdx.x, ch = blockIdx.y;
    int warp = threadIdx.x >> 5, lane = threadIdx.x & 31;
    __shared__ float qs[NS * DD];
    __shared__ float dots[8][NS];
    __shared__ float aw[8][NS];
    for (int i = threadIdx.x; i < NS * DD; i += 256) qs[i] = g_q[b * NS * DD + i];
    __syncthreads();
    float qreg[8];
    #pragma unroll
    for (int k = 0; k < 4; k++) {
        qreg[2 * k]     = qs[warp * DD + 2 * (lane + 32 * k)];
        qreg[2 * k + 1] = qs[warp * DD + 2 * (lane + 32 * k) + 1];
    }
    float2 uacc[4];
    #pragma unroll
    for (int k = 0; k < 4; k++) uacc[k] = make_float2(0.f, 0.f);
    float rsum = 0.f;
    const float scale = 0.0625f;
    int t0 = ch * 256;
    const __half* kvb = g_kvh + ((size_t)b * NTOK + t0) * 512;

    for (int tt = 0; tt < 256; tt += 8) {
        #pragma unroll
        for (int u = 0; u < 8; u++) {
            const __half2* kp = (const __half2*)(kvb + (size_t)(tt + u) * 512);
            float d = 0.f;
            #pragma unroll
            for (int k = 0; k < 4; k++) {
                float2 kv2 = __half22float2(kp[lane + 32 * k]);
                d += qreg[2 * k] * kv2.x + qreg[2 * k + 1] * kv2.y;
            }
            #pragma unroll
            for (int o = 16; o; o >>= 1) d += __shfl_xor_sync(0xffffffffu, d, o);
            if (lane == 0) dots[u][warp] = d * scale;
        }
        __syncthreads();
        if (threadIdx.x < 64) {
            int u = threadIdx.x >> 3, s = threadIdx.x & 7;
            float mx = -1e30f;
            #pragma unroll
            for (int s2 = 0; s2 < NS; s2++) mx = fmaxf(mx, dots[u][s2]);
            float e = expf(dots[u][s] - mx);
            float sum = e;
            #pragma unroll
            for (int o = 1; o < 8; o <<= 1) sum += __shfl_xor_sync(0xffffffffu, sum, o);
            aw[u][s] = e / sum + 1e-8f;
        }
        __syncthreads();
        #pragma unroll
        for (int u = 0; u < 8; u++) {
            float a = aw[u][warp];
            const __half2* vp = (const __half2*)(kvb + (size_t)(tt + u) * 512 + 256);
            #pragma unroll
            for (int k = 0; k < 4; k++) {
                float2 vv = __half22float2(vp[lane + 32 * k]);
                uacc[k].x += a * vv.x;
                uacc[k].y += a * vv.y;
            }
            rsum += a;
        }
        __syncthreads();
    }
    float* up = g_U + (b * NS + warp) * DD;
    #pragma unroll
    for (int k = 0; k < 4; k++) {
        atomicAdd(&up[2 * (lane + 32 * k)], uacc[k].x);
        atomicAdd(&up[2 * (lane + 32 * k) + 1], uacc[k].y);
    }
    if (lane == 0) atomicAdd(&g_rowsum[b * NS + warp], rsum);
}

__global__ void updfin_kernel() {
    int i = blockIdx.x * 256 + threadIdx.x;
    g_updh[i] = __float2half(g_U[i] / g_rowsum[i >> 8]);
}

__global__ void gru_pw_kernel(const float* __restrict__ mlng,
                              const float* __restrict__ mlnb) {
    __shared__ float r1[8], r2[8];
    int row = blockIdx.x, tid = threadIdx.x;
    const float* gi = g_gi + row * 3 * DD;
    const float* gh = g_gh + row * 3 * DD;
    float ir = gi[tid], iz = gi[tid + 256], inn = gi[tid + 512];
    float hr = gh[tid], hz = gh[tid + 256], hn = gh[tid + 512];
    float sprev = g_slots[row * DD + tid];
    float r = 1.f / (1.f + expf(-(ir + hr)));
    float z = 1.f / (1.f + expf(-(iz + hz)));
    float n = tanhf(inn + r * hn);
    float h = (1.f - z) * n + z * sprev;
    g_hbuf[row * DD + tid] = h;
    float2 mv = block_meanvar_256(h, r1, r2);
    g_mlpinh[row * DD + tid] = __float2half((h - mv.x) * mv.y * mlng[tid] + mlnb[tid]);
}

// ================= launch =================
extern "C" void kernel_launch(void* const* d_in, const int* in_sizes, int n_in,
                              void* d_out, int out_size) {
    const float* inputs   = (const float*)d_in[0];
    const float* slots_in = (const float*)d_in[1];
    const float* ln1g = (const float*)d_in[2];
    const float* ln1b = (const float*)d_in[3];
    const float* w1   = (const float*)d_in[4];
    const float* b1   = (const float*)d_in[5];
    const float* w2   = (const float*)d_in[6];
    const float* b2   = (const float*)d_in[7];
    const float* ln2g = (const float*)d_in[8];
    const float* ln2b = (const float*)d_in[9];
    const float* wq   = (const float*)d_in[10];
    const float* wk   = (const float*)d_in[11];
    const float* wv   = (const float*)d_in[12];
    const float* normg = (const float*)d_in[13];
    const float* normb = (const float*)d_in[14];
    const float* gwih = (const float*)d_in[15];
    const float* gwhh = (const float*)d_in[16];
    const float* gbih = (const float*)d_in[17];
    const float* gbhh = (const float*)d_in[18];
    const float* mlng = (const float*)d_in[19];
    const float* mlnb = (const float*)d_in[20];
    const float* mw1  = (const float*)d_in[21];
    const float* mb1  = (const float*)d_in[22];
    const float* mw2  = (const float*)d_in[23];
    const float* mb2  = (const float*)d_in[24];
    float* out = (float*)d_out;

    __half *p_inh, *p_h1h, *p_featsh, *p_kvh, *p_w1h, *p_w2h, *p_wkvh;
    __half *p_wihh, *p_whhh, *p_mw1h, *p_mw2h, *p_updh, *p_mlpinh, *p_hhh, *p_slotsh;
    float *p_wqT, *p_slots, *p_gi, *p_gh, *p_hbuf, *p_gB, *p_bBp;
    cudaGetSymbolAddress((void**)&p_inh,    g_inh);
    cudaGetSymbolAddress((void**)&p_h1h,    g_h1h);
    cudaGetSymbolAddress((void**)&p_featsh, g_featsh);
    cudaGetSymbolAddress((void**)&p_kvh,    g_kvh);
    cudaGetSymbolAddress((void**)&p_w1h,    g_w1h);
    cudaGetSymbolAddress((void**)&p_w2h,    g_w2h);
    cudaGetSymbolAddress((void**)&p_wkvh,   g_wkvh);
    cudaGetSymbolAddress((void**)&p_wihh,   g_wihh);
    cudaGetSymbolAddress((void**)&p_whhh,   g_whhh);
    cudaGetSymbolAddress((void**)&p_mw1h,   g_mw1h);
    cudaGetSymbolAddress((void**)&p_mw2h,   g_mw2h);
    cudaGetSymbolAddress((void**)&p_updh,   g_updh);
    cudaGetSymbolAddress((void**)&p_mlpinh, g_mlpinh);
    cudaGetSymbolAddress((void**)&p_hhh,    g_hhh);
    cudaGetSymbolAddress((void**)&p_slotsh, g_slotsh);
    cudaGetSymbolAddress((void**)&p_wqT,    g_wqT);
    cudaGetSymbolAddress((void**)&p_slots,  g_slots);
    cudaGetSymbolAddress((void**)&p_gi,     g_gi);
    cudaGetSymbolAddress((void**)&p_gh,     g_gh);
    cudaGetSymbolAddress((void**)&p_hbuf,   g_hbuf);
    cudaGetSymbolAddress((void**)&p_gB,     g_gB);
    cudaGetSymbolAddress((void**)&p_bBp,    g_bBp);

    // smem opt-ins (above 48 KB default)
    cudaFuncSetAttribute(hgemm128_kernel<1>, cudaFuncAttributeMaxDynamicSharedMemorySize, H128_DSMEM);
    cudaFuncSetAttribute(hgemm128_kernel<3>, cudaFuncAttributeMaxDynamicSharedMemorySize, H128_DSMEM);
    cudaFuncSetAttribute(hgemm2ln_kernel,    cudaFuncAttributeMaxDynamicSharedMemorySize, H256_DSMEM);

    dim3 tb(32, 8);
    // zero fold-vector accumulators (async memset — graph-capturable)
    cudaMemsetAsync(p_gB, 0, FDIN * sizeof(float));
    cudaMemsetAsync(p_bBp, 0, FDIN * sizeof(float));
    // 0: fused LN stats + fp16 conversion of inputs
    ln_stats_f2h_kernel<<<MROWS / 8, 256>>>(inputs, p_inh);
    // 1: w1 -> [N][K] fp16 scaled by ln1g
    trans_h_kernel<<<dim3(FDIN / 32, FDIN / 32), tb>>>(w1, p_w1h, FDIN, FDIN, ln1g);
    // 2: epilogue fold vectors (coalesced, k-split atomics)
    prep_sums_kernel<<<dim3(FDIN / 256, 8), 256>>>(w1, ln1g, ln1b, b1);
    // 3: GEMM1 (128x128 tile, BK=64)   << ncu window
    hgemm128_kernel<1><<<dim3(FDIN / 128, MROWS / 128), 256, H128_DSMEM>>>(
        p_inh, p_w1h, FDIN, FDIN, p_h1h);
    // 4: w2 -> [N][K] fp16
    trans_h_kernel<<<dim3(DD / 32, FDIN / 32), tb>>>(w2, p_w2h, FDIN, DD, nullptr);
    // 5: GEMM2 fused row-LN: feats = LN(h1 @ w2 + b2) -> fp16
    hgemm2ln_kernel<<<dim3(1, MROWS / 128), 512, H256_DSMEM>>>(
        p_h1h, p_w2h, FDIN, p_featsh, b2, ln2g, ln2b);
    // 6: wk|wv -> fp16
    wkv_h_kernel<<<DD * DD / 256, 256>>>(wk, wv);
    // 7: KV GEMM -> fp16
    hgemm128_kernel<3><<<dim3(2 * DD / 128, MROWS / 128), 256, H128_DSMEM>>>(
        p_featsh, p_wkvh, 2 * DD, DD, p_kvh);

    // slot-path weight prep
    trans_f_kernel<<<dim3(DD / 32, DD / 32), tb>>>(wq, p_wqT, DD, DD);
    conv_f2h_kernel<<<3 * DD * DD / 1024, 256>>>(gwih, p_wihh);
    conv_f2h_kernel<<<3 * DD * DD / 1024, 256>>>(gwhh, p_whhh);
    trans_h_kernel<<<dim3(4 * DD / 32, DD / 32), tb>>>(mw1, p_mw1h, DD, 4 * DD, nullptr);
    trans_h_kernel<<<dim3(DD / 32, 4 * DD / 32), tb>>>(mw2, p_mw2h, 4 * DD, DD, nullptr);
    slots_init_kernel<<<SROWS * DD / 256, 256>>>(slots_in);

    for (int t = 0; t < ITERS; t++) {
        qproj_kernel<<<SROWS, 256>>>(normg, normb);
        attn_kernel<<<dim3(BNUM, 16), 256>>>();
        updfin_kernel<<<SROWS, 256>>>();
        hgemm64_kernel<10><<<dim3(3 * DD / 64, SROWS / 128), 256, H64_DSMEM>>>(
            p_updh, p_wihh, 3 * DD, DD, p_gi, nullptr, gbih, nullptr);
        hgemm64_kernel<10><<<dim3(3 * DD / 64, SROWS / 128), 256, H64_DSMEM>>>(
            p_slotsh, p_whhh, 3 * DD, DD, p_gh, nullptr, gbhh, nullptr);
        gru_pw_kernel<<<SROWS, 256>>>(mlng, mlnb);
        hgemm64_kernel<11><<<dim3(4 * DD / 64, SROWS / 128), 256, H64_DSMEM>>>(
            p_mlpinh, p_mw1h, 4 * DD, DD, nullptr, p_hhh, mb1, nullptr);
        float* dst = (t == ITERS - 1) ? out : p_slots;
        hgemm64_kernel<12><<<dim3(DD / 64, SROWS / 128), 256, H64_DSMEM>>>(
            p_hhh, p_mw2h, DD, 4 * DD, dst, p_slotsh, mb2, p_hbuf);
    }
}